// round 7
// baseline (speedup 1.0000x reference)
#include <cuda_runtime.h>
#include <cuda_bf16.h>
#include <cstdint>
#include <math.h>

#define BB 32
#define LL 512
#define DD 1024
#define HH 16
#define HDIM 64
#define EE 8

// ---------------- scratch (device globals; no allocation allowed) ----------------
__device__ float g_cos[LL * 32];
__device__ float g_sin[LL * 32];
__device__ int   g_routes[BB];

// int8 operand tiles: 128 rows x 128 k-bytes (16KB), SW128-swizzled
// X/AO: [rt(128)][kc(8)]
__device__ char g_xi8h[(size_t)128 * 8 * 16384];
__device__ char g_xi8l[(size_t)128 * 8 * 16384];
// W^T: [mode(4)][e(8)][nt(8)][kc(8)]
__device__ char g_wi8h[(size_t)4 * 8 * 8 * 8 * 16384];
__device__ char g_wi8l[(size_t)4 * 8 * 8 * 8 * 16384];
// quantization scales (raw max-abs)
__device__ float g_sa_x[16384];
__device__ float g_sa_ao[16384];
__device__ float g_sb[4 * 8 * 1024];
__device__ unsigned int g_aomax[16384];
// attention output fp32 [B,L,D]
__device__ float g_ao[(size_t)BB * LL * DD];
// q/k/v bf16 hi/lo: [B*H][512][64], SW128-swizzled 128B rows
__device__ __nv_bfloat16 g_qh[(size_t)BB * HH * LL * HDIM];
__device__ __nv_bfloat16 g_ql[(size_t)BB * HH * LL * HDIM];
__device__ __nv_bfloat16 g_kh[(size_t)BB * HH * LL * HDIM];
__device__ __nv_bfloat16 g_kl[(size_t)BB * HH * LL * HDIM];
__device__ __nv_bfloat16 g_vh[(size_t)BB * HH * LL * HDIM];
__device__ __nv_bfloat16 g_vl[(size_t)BB * HH * LL * HDIM];

// ---------------- PTX helpers ----------------
__device__ __forceinline__ uint32_t smem_u32(const void* p) {
    uint32_t a;
    asm("{ .reg .u64 t; cvta.to.shared.u64 t, %1; cvt.u32.u64 %0, t; }" : "=r"(a) : "l"(p));
    return a;
}

#define MBAR_INIT(a, n) \
    asm volatile("mbarrier.init.shared.b64 [%0], %1;" :: "r"(a), "r"((uint32_t)(n)) : "memory")
#define MBAR_EXPECT_TX(a, b) \
    asm volatile("mbarrier.arrive.expect_tx.shared.b64 _, [%0], %1;" :: "r"(a), "r"((uint32_t)(b)) : "memory")

__device__ __forceinline__ void mbar_wait(uint32_t mbar, uint32_t parity) {
    asm volatile(
        "{\n\t.reg .pred P;\n\t"
        "WL_%=:\n\t"
        "mbarrier.try_wait.parity.acquire.cta.shared::cta.b64 P, [%0], %1, 0x989680;\n\t"
        "@P bra.uni WD_%=;\n\t"
        "bra.uni WL_%=;\n\t"
        "WD_%=:\n\t}"
        :: "r"(mbar), "r"(parity) : "memory");
}

__device__ __forceinline__ void bulk_g2s(uint32_t dst, const void* src, uint32_t bytes, uint32_t mbar) {
    asm volatile(
        "cp.async.bulk.shared::cluster.global.mbarrier::complete_tx::bytes [%0], [%1], %2, [%3];"
        :: "r"(dst), "l"(src), "r"(bytes), "r"(mbar) : "memory");
}

__device__ __forceinline__ void ldsm_x4(uint32_t* r, uint32_t a) {
    asm volatile("ldmatrix.sync.aligned.m8n8.x4.shared.b16 {%0,%1,%2,%3}, [%4];"
                 : "=r"(r[0]), "=r"(r[1]), "=r"(r[2]), "=r"(r[3]) : "r"(a));
}
__device__ __forceinline__ void ldsm_x4t(uint32_t* r, uint32_t a) {
    asm volatile("ldmatrix.sync.aligned.m8n8.x4.trans.shared.b16 {%0,%1,%2,%3}, [%4];"
                 : "=r"(r[0]), "=r"(r[1]), "=r"(r[2]), "=r"(r[3]) : "r"(a));
}
__device__ __forceinline__ void mma_bf16(float* d, const uint32_t* a, const uint32_t* b) {
    asm volatile(
        "mma.sync.aligned.m16n8k16.row.col.f32.bf16.bf16.f32 "
        "{%0,%1,%2,%3}, {%4,%5,%6,%7}, {%8,%9}, {%0,%1,%2,%3};"
        : "+f"(d[0]), "+f"(d[1]), "+f"(d[2]), "+f"(d[3])
        : "r"(a[0]), "r"(a[1]), "r"(a[2]), "r"(a[3]), "r"(b[0]), "r"(b[1]));
}
__device__ __forceinline__ void mma_s8(int* d, const uint32_t* a, const uint32_t* b) {
    asm volatile(
        "mma.sync.aligned.m16n8k32.row.col.s32.s8.s8.s32 "
        "{%0,%1,%2,%3}, {%4,%5,%6,%7}, {%8,%9}, {%0,%1,%2,%3};"
        : "+r"(d[0]), "+r"(d[1]), "+r"(d[2]), "+r"(d[3])
        : "r"(a[0]), "r"(a[1]), "r"(a[2]), "r"(a[3]), "r"(b[0]), "r"(b[1]));
}

__device__ __forceinline__ uint32_t pack_bf2(__nv_bfloat16 a, __nv_bfloat16 b) {
    return (uint32_t)__bfloat16_as_ushort(a) | ((uint32_t)__bfloat16_as_ushort(b) << 16);
}
__device__ __forceinline__ uint32_t pack_s8x4(int a, int b, int c, int d) {
    return (uint32_t)(a & 255) | ((uint32_t)(b & 255) << 8) |
           ((uint32_t)(c & 255) << 16) | ((uint32_t)(d & 255) << 24);
}

// quantize 16 floats -> hi uint4, lo uint4
__device__ __forceinline__ void quant16(const float* v, float inv, uint4& hv, uint4& lv) {
    int xh[16], xl[16];
    #pragma unroll
    for (int j = 0; j < 16; j++) {
        int xi = __float2int_rn(v[j] * inv);
        xi = max(-16256, min(16256, xi));
        int h = (xi + 64) >> 7;
        xh[j] = h;
        xl[j] = xi - (h << 7);
    }
    hv = make_uint4(pack_s8x4(xh[0], xh[1], xh[2], xh[3]),  pack_s8x4(xh[4], xh[5], xh[6], xh[7]),
                    pack_s8x4(xh[8], xh[9], xh[10], xh[11]), pack_s8x4(xh[12], xh[13], xh[14], xh[15]));
    lv = make_uint4(pack_s8x4(xl[0], xl[1], xl[2], xl[3]),  pack_s8x4(xl[4], xl[5], xl[6], xl[7]),
                    pack_s8x4(xl[8], xl[9], xl[10], xl[11]), pack_s8x4(xl[12], xl[13], xl[14], xl[15]));
}

// ---------------- RoPE tables + aomax init ----------------
__global__ void rope_init_kernel() {
    int idx = blockIdx.x * blockDim.x + threadIdx.x;
    if (idx >= LL * 32) return;
    g_aomax[idx] = 0u;
    int l = idx >> 5;
    int jp = idx & 31;
    float inv = 1.0f / powf(10000.0f, (float)(2 * jp) / 64.0f);
    float ang = (float)l * inv;
    g_cos[idx] = cosf(ang);
    g_sin[idx] = sinf(ang);
}

// ---------------- router ----------------
__global__ void router_kernel(const float* __restrict__ x,
                              const float* __restrict__ rw,
                              const float* __restrict__ rb,
                              float* __restrict__ probs_out,
                              int write_probs) {
    int b = blockIdx.x;
    __shared__ float mean[DD];
    __shared__ float logits[EE];

    for (int d = threadIdx.x; d < DD; d += blockDim.x) {
        const float* xp = x + (size_t)b * LL * DD + d;
        float s = 0.f;
        #pragma unroll 8
        for (int l = 0; l < LL; l++) s += xp[(size_t)l * DD];
        mean[d] = s * (1.0f / (float)LL);
    }
    __syncthreads();

    int w = threadIdx.x >> 5;
    int lane = threadIdx.x & 31;
    if (w < EE) {
        float s = 0.f;
        for (int d = lane; d < DD; d += 32) s += mean[d] * rw[d * EE + w];
        #pragma unroll
        for (int o = 16; o > 0; o >>= 1) s += __shfl_down_sync(0xffffffffu, s, o);
        if (lane == 0) logits[w] = s + rb[w];
    }
    __syncthreads();

    if (threadIdx.x == 0) {
        float m = logits[0]; int arg = 0;
        #pragma unroll
        for (int e = 1; e < EE; e++) if (logits[e] > m) { m = logits[e]; arg = e; }
        float p[EE], sum = 0.f;
        #pragma unroll
        for (int e = 0; e < EE; e++) { p[e] = expf(logits[e] - m); sum += p[e]; }
        if (write_probs) {
            float inv = 1.0f / sum;
            #pragma unroll
            for (int e = 0; e < EE; e++) probs_out[b * EE + e] = p[e] * inv;
        }
        g_routes[b] = arg;
    }
}

// ---------------- maxes: X row-max + W col-max (merged) ----------------
__global__ void maxes_kernel(const float* __restrict__ x,
                             const float* __restrict__ qw, const float* __restrict__ kw,
                             const float* __restrict__ vw, const float* __restrict__ ow) {
    const int bid = blockIdx.x;
    const int tid = threadIdx.x, lane = tid & 31, wid = tid >> 5;
    if (bid < 2048) {
        // X row max: 8 warps, one row each
        int row = bid * 8 + wid;
        const float* p = x + (size_t)row * DD;
        float m = 0.f;
        #pragma unroll 4
        for (int i = lane; i < DD; i += 32) m = fmaxf(m, fabsf(p[i]));
        #pragma unroll
        for (int o = 16; o > 0; o >>= 1) m = fmaxf(m, __shfl_xor_sync(0xffffffffu, m, o));
        if (lane == 0) g_sa_x[row] = fmaxf(m, 1e-20f);
    } else {
        // W col max: 128 blocks: idx -> (mode, e, 256-col block)
        int idx = bid - 2048;
        int mode = idx >> 5, e = (idx >> 2) & 7, blk = idx & 3;
        const float* W = (mode == 0) ? qw : (mode == 1) ? kw : (mode == 2) ? vw : ow;
        int n = blk * 256 + tid;
        const float* p = W + (size_t)e * DD * DD + n;
        float m = 0.f;
        #pragma unroll 4
        for (int k = 0; k < DD; k++) m = fmaxf(m, fabsf(p[(size_t)k * DD]));
        g_sb[(mode * 8 + e) * 1024 + n] = fmaxf(m, 1e-20f);
    }
}

// ---------------- convert: X tiles + W^T tiles -> int8 hi/lo (merged) ----------------
__global__ void convert_kernel(const float* __restrict__ x,
                               const float* __restrict__ qw, const float* __restrict__ kw,
                               const float* __restrict__ vw, const float* __restrict__ ow) {
    __shared__ float sm[64][129];
    const int bid = blockIdx.x;
    const int tid = threadIdx.x;

    if (bid < 1024) {
        // X tile: rt = bid>>3, kc = bid&7; 128 rows x 128 k
        const int rt = bid >> 3, kc = bid & 7;
        const size_t tb = ((size_t)rt * 8 + kc) * 16384;
        #pragma unroll
        for (int i = 0; i < 4; i++) {
            int u = tid + i * 256;               // 0..1023 16B units
            int r = u >> 3, k16 = u & 7;
            int row = rt * 128 + r;
            float inv = 16256.f / g_sa_x[row];
            const float* p = x + (size_t)row * DD + kc * 128 + k16 * 16;
            float v[16];
            #pragma unroll
            for (int q = 0; q < 4; q++) {
                float4 f = *(const float4*)(p + 4 * q);
                v[4 * q] = f.x; v[4 * q + 1] = f.y; v[4 * q + 2] = f.z; v[4 * q + 3] = f.w;
            }
            uint4 hv, lv;
            quant16(v, inv, hv, lv);
            uint32_t off = (uint32_t)(u * 16);
            off ^= (off >> 3) & 0x70;
            *(uint4*)(g_xi8h + tb + off) = hv;
            *(uint4*)(g_xi8l + tb + off) = lv;
        }
    } else {
        // W tile: idx -> kc, nt, e, mode. Output 128 n-rows x 128 k-bytes.
        const int idx = bid - 1024;
        const int kc = idx & 7, nt = (idx >> 3) & 7;
        const int em = idx >> 6;
        const int e = em & 7, mode = em >> 3;
        const float* W = (mode == 0) ? qw : (mode == 1) ? kw : (mode == 2) ? vw : ow;
        const size_t tb = ((((size_t)(mode * 8 + e) * 8 + nt) * 8) + kc) * 16384;
        const float* sbp = g_sb + (mode * 8 + e) * 1024 + nt * 128;

        for (int ph = 0; ph < 2; ph++) {
            // load 64 k-rows x 128 n-cols
            #pragma unroll
            for (int i = 0; i < 8; i++) {
                int idx2 = tid + i * 256;        // 0..2047 float4s
                int kr = idx2 >> 5, nc = (idx2 & 31) << 2;
                float4 v = *(const float4*)(W + ((size_t)e * DD + kc * 128 + ph * 64 + kr) * DD
                                            + nt * 128 + nc);
                sm[kr][nc] = v.x; sm[kr][nc + 1] = v.y; sm[kr][nc + 2] = v.z; sm[kr][nc + 3] = v.w;
            }
            __syncthreads();
            // write transposed int8 hi/lo (64 bytes of each of 128 n-rows)
            #pragma unroll
            for (int i = 0; i < 2; i++) {
                int u = tid + i * 256;           // 0..511
                int n = u >> 2, k16 = u & 3;
                float inv = 16256.f / sbp[n];
                float v[16];
                #pragma unroll
                for (int j = 0; j < 16; j++) v[j] = sm[k16 * 16 + j][n];
                uint4 hv, lv;
                quant16(v, inv, hv, lv);
                uint32_t off = (uint32_t)(n * 128 + ph * 64 + k16 * 16);
                off ^= (off >> 3) & 0x70;
                *(uint4*)(g_wi8h + tb + off) = hv;
                *(uint4*)(g_wi8l + tb + off) = lv;
            }
            __syncthreads();
        }
    }
}

// ---------------- convert AO -> int8 tiles (reuses g_xi8h/l) ----------------
__global__ void convert_ao_kernel() {
    const int kc = blockIdx.x, rt = blockIdx.y;
    const int tid = threadIdx.x;
    const size_t tb = ((size_t)rt * 8 + kc) * 16384;
    #pragma unroll
    for (int i = 0; i < 4; i++) {
        int u = tid + i * 256;
        int r = u >> 3, k16 = u & 7;
        int row = rt * 128 + r;
        float mx = fmaxf(__uint_as_float(g_aomax[row]), 1e-20f);
        if (k16 == 0) g_sa_ao[row] = mx;
        float inv = 16256.f / mx;
        const float* p = g_ao + (size_t)row * DD + kc * 128 + k16 * 16;
        float v[16];
        #pragma unroll
        for (int q = 0; q < 4; q++) {
            float4 f = *(const float4*)(p + 4 * q);
            v[4 * q] = f.x; v[4 * q + 1] = f.y; v[4 * q + 2] = f.z; v[4 * q + 3] = f.w;
        }
        uint4 hv, lv;
        quant16(v, inv, hv, lv);
        uint32_t off = (uint32_t)(u * 16);
        off ^= (off >> 3) & 0x70;
        *(uint4*)(g_xi8h + tb + off) = hv;
        *(uint4*)(g_xi8l + tb + off) = lv;
    }
}

// ---------------- IMMA GEMM: CTA 128x128, warp 64x32, K=1024 in 8 chunks of 128 ------
// 3-term 15-bit split: y = sa*sb/(16256^2) * (16384*hh + 128*(hl+lh))
__global__ void __launch_bounds__(256, 1) imma_gemm_kernel(float* __restrict__ out,
                                                           int sa_sel, int mode0) {
    extern __shared__ __align__(1024) char smem[];
    const uint32_t sb_ = smem_u32(smem);
    const int tid = threadIdx.x;
    const int lane = tid & 31, wid = tid >> 5;
    const int wm = wid >> 2, wn = wid & 3;            // 2(m) x 4(n)
    const int nt = blockIdx.x & 7;
    const int mode = mode0 + (blockIdx.x >> 3);
    const int mt = blockIdx.y, b = blockIdx.z;
    const int e = g_routes[b];

    const uint32_t FULLB = sb_;
    const uint32_t TILES = sb_ + 1024;                // 2 stages x 64KB: Ah|Al|Bh|Bl (16KB ea)

    if (tid == 0) { MBAR_INIT(FULLB, 1); MBAR_INIT(FULLB + 8, 1); }
    __syncthreads();

    const char* Ah = g_xi8h + (size_t)(b * 4 + mt) * 8 * 16384;
    const char* Al = g_xi8l + (size_t)(b * 4 + mt) * 8 * 16384;
    const size_t wt = (((size_t)(mode * 8 + e) * 8 + nt) * 8) * 16384;
    const char* Bh = g_wi8h + wt;
    const char* Bl = g_wi8l + wt;

    auto issue = [&](int c) {
        int s = c & 1;
        uint32_t fb = FULLB + s * 8;
        uint32_t st = TILES + s * 65536;
        MBAR_EXPECT_TX(fb, 65536);
        bulk_g2s(st,         Ah + (size_t)c * 16384, 16384, fb);
        bulk_g2s(st + 16384, Al + (size_t)c * 16384, 16384, fb);
        bulk_g2s(st + 32768, Bh + (size_t)c * 16384, 16384, fb);
        bulk_g2s(st + 49152, Bl + (size_t)c * 16384, 16384, fb);
    };
    if (tid == 0) { issue(0); issue(1); }

    int hh[4][4][4], cx[4][4][4];
    #pragma unroll
    for (int mf = 0; mf < 4; mf++)
        #pragma unroll
        for (int nf = 0; nf < 4; nf++)
            #pragma unroll
            for (int r = 0; r < 4; r++) { hh[mf][nf][r] = 0; cx[mf][nf][r] = 0; }

    const uint32_t a_row  = (uint32_t)(wm * 64 + (lane & 15)) * 128;
    const uint32_t a_koff = (uint32_t)(lane >> 4) * 16;
    const uint32_t b_row  = (uint32_t)(wn * 32 + (lane & 7) + ((lane >> 4) << 3)) * 128;
    const uint32_t b_koff = (uint32_t)((lane >> 3) & 1) * 16;

    for (int c = 0; c < 8; c++) {
        const int s = c & 1;
        mbar_wait(FULLB + s * 8, (uint32_t)((c >> 1) & 1));
        const uint32_t base = TILES + s * 65536;

        #pragma unroll
        for (int ks = 0; ks < 4; ks++) {
            const uint32_t k0b = (uint32_t)ks * 32;
            uint32_t ah[4][4], al[4][4];
            #pragma unroll
            for (int mf = 0; mf < 4; mf++) {
                uint32_t byt = a_row + (uint32_t)mf * 2048 + a_koff + k0b;
                uint32_t sw = byt ^ ((byt >> 3) & 0x70);
                ldsm_x4(ah[mf], base + sw);
                ldsm_x4(al[mf], base + 16384 + sw);
            }
            uint32_t bh[2][4], bl[2][4];
            #pragma unroll
            for (int p = 0; p < 2; p++) {
                uint32_t byt = b_row + (uint32_t)p * 2048 + b_koff + k0b;
                uint32_t sw = byt ^ ((byt >> 3) & 0x70);
                ldsm_x4(bh[p], base + 32768 + sw);
                ldsm_x4(bl[p], base + 49152 + sw);
            }
            // hh terms (16 independent accumulators)
            #pragma unroll
            for (int p = 0; p < 2; p++)
                #pragma unroll
                for (int mf = 0; mf < 4; mf++) {
                    mma_s8(hh[mf][2 * p],     ah[mf], &bh[p][0]);
                    mma_s8(hh[mf][2 * p + 1], ah[mf], &bh[p][2]);
                }
            // cross: hi*lo
            #pragma unroll
            for (int p = 0; p < 2; p++)
                #pragma unroll
                for (int mf = 0; mf < 4; mf++) {
                    mma_s8(cx[mf][2 * p],     ah[mf], &bl[p][0]);
                    mma_s8(cx[mf][2 * p + 1], ah[mf], &bl[p][2]);
                }
            // cross: lo*hi
            #pragma unroll
            for (int p = 0; p < 2; p++)
                #pragma unroll
                for (int mf = 0; mf < 4; mf++) {
                    mma_s8(cx[mf][2 * p],     al[mf], &bh[p][0]);
                    mma_s8(cx[mf][2 * p + 1], al[mf], &bh[p][2]);
                }
        }
        __syncthreads();
        if (tid == 0 && c + 2 < 8) issue(c + 2);
    }

    // ---------------- epilogue ----------------
    const int lr = lane >> 2, tig = lane & 3;
    const int colbase = nt * 128 + wn * 32;
    const float inv2 = 1.0f / (16256.0f * 16256.0f);
    float2 sbv[4];
    #pragma unroll
    for (int nf = 0; nf < 4; nf++)
        sbv[nf] = *(const float2*)&g_sb[(mode * 8 + e) * 1024 + colbase + 8 * nf + 2 * tig];
    const int h2 = colbase >> 6;
    const int d0 = colbase & 63;

    #pragma unroll
    for (int mf = 0; mf < 4; mf++) {
        #pragma unroll
        for (int rh = 0; rh < 2; rh++) {
            const int l = mt * 128 + wm * 64 + mf * 16 + 8 * rh + lr;
            const int grow = b * 512 + l;
            const float sa = sa_sel ? g_sa_ao[grow] : g_sa_x[grow];
            const float fs = sa * inv2;
            #pragma unroll
            for (int nf = 0; nf < 4; nf++) {
                float x0 = fs * sbv[nf].x * (16384.f * (float)hh[mf][nf][2 * rh]
                                             + 128.f * (float)cx[mf][nf][2 * rh]);
                float x1 = fs * sbv[nf].y * (16384.f * (float)hh[mf][nf][2 * rh + 1]
                                             + 128.f * (float)cx[mf][nf][2 * rh + 1]);
                if (mode == 3) {
                    *(float2*)(out + ((size_t)b * LL + l) * DD + colbase + 8 * nf + 2 * tig)
                        = make_float2(x0, x1);
                } else {
                    const int d = d0 + 8 * nf + 2 * tig;
                    float y0, y1;
                    if (mode == 2) { y0 = x0; y1 = x1; }
                    else {
                        const int p = d >> 1;
                        float cs = g_cos[l * 32 + p];
                        float sn = g_sin[l * 32 + p];
                        y0 = x0 * cs - x1 * sn;
                        y1 = x1 * cs + x0 * sn;
                    }
                    __nv_bfloat16 hb0 = __float2bfloat16(y0);
                    __nv_bfloat16 hb1 = __float2bfloat16(y1);
                    __nv_bfloat16 lb0 = __float2bfloat16(y0 - __bfloat162float(hb0));
                    __nv_bfloat16 lb1 = __float2bfloat16(y1 - __bfloat162float(hb1));
                    uint32_t off = (uint32_t)((((b * HH + h2) * LL) + l) * 128 + d * 2);
                    uint32_t sw = off ^ ((off >> 3) & 0x70);
                    char* bhp = (char*)((mode == 0) ? g_qh : (mode == 1) ? g_kh : g_vh);
                    char* blp = (char*)((mode == 0) ? g_ql : (mode == 1) ? g_kl : g_vl);
                    *(uint32_t*)(bhp + sw) = pack_bf2(hb0, hb1);
                    *(uint32_t*)(blp + sw) = pack_bf2(lb0, lb1);
                }
            }
        }
    }
}

// ---------------- flash attention on HMMA: 128 q-rows/CTA, 8 warps x 16 rows ---------
__global__ void __launch_bounds__(256, 2) attn_kernel() {
    extern __shared__ __align__(1024) char smem[];
    const uint32_t sb = smem_u32(smem);
    const int tid = threadIdx.x, lane = tid & 31, w = tid >> 5;
    const int qt = 3 - blockIdx.x;       // long CTAs first
    const int bh = blockIdx.y;
    const int b = bh >> 4, h = bh & 15;
    const int g = lane >> 2, tig = lane & 3;

    const uint32_t QB = sb;
    const uint32_t FB = sb + 8;
    const uint32_t QT = sb + 1024;
    const uint32_t KV = sb + 1024 + 32768;

    if (tid == 0) { MBAR_INIT(QB, 1); MBAR_INIT(FB, 1); MBAR_INIT(FB + 8, 1); }
    __syncthreads();

    const size_t bh_off = (size_t)bh * LL * HDIM;
    const __nv_bfloat16* kh = g_kh + bh_off;
    const __nv_bfloat16* kl = g_kl + bh_off;
    const __nv_bfloat16* vh = g_vh + bh_off;
    const __nv_bfloat16* vl = g_vl + bh_off;

    const int jmax = 2 * qt + 2;

    auto issue = [&](int jt) {
        int s = jt & 1;
        uint32_t fb = FB + s * 8;
        uint32_t st = KV + s * 32768;
        MBAR_EXPECT_TX(fb, 32768);
        bulk_g2s(st,         kh + (size_t)jt * 4096, 8192, fb);
        bulk_g2s(st + 8192,  kl + (size_t)jt * 4096, 8192, fb);
        bulk_g2s(st + 16384, vh + (size_t)jt * 4096, 8192, fb);
        bulk_g2s(st + 24576, vl + (size_t)jt * 4096, 8192, fb);
    };
    if (tid == 0) {
        MBAR_EXPECT_TX(QB, 32768);
        bulk_g2s(QT,         g_qh + bh_off + (size_t)qt * 128 * 64, 16384, QB);
        bulk_g2s(QT + 16384, g_ql + bh_off + (size_t)qt * 128 * 64, 16384, QB);
        issue(0);
        issue(1);
    }

    float o[8][4];
    #pragma unroll
    for (int nf = 0; nf < 8; nf++)
        #pragma unroll
        for (int r = 0; r < 4; r++) o[nf][r] = 0.f;
    float m0 = -1e30f, m1 = -1e30f, l0 = 0.f, l1 = 0.f;

    const int rowmin = qt * 128 + w * 16;

    mbar_wait(QB, 0);

    for (int jt = 0; jt < jmax; jt++) {
        const int s = jt & 1;
        mbar_wait(FB + s * 8, (uint32_t)((jt >> 1) & 1));
        const uint32_t kb = KV + s * 32768;

        if (jt * 64 <= rowmin + 15) {
            float p[8][4];
            #pragma unroll
            for (int nf = 0; nf < 8; nf++)
                #pragma unroll
                for (int r = 0; r < 4; r++) p[nf][r] = 0.f;

            #pragma unroll
            for (int ks = 0; ks < 4; ks++) {
                uint32_t qoff = (uint32_t)(w * 16 + (lane & 15)) * 128
                                + (uint32_t)(lane >> 4) * 16 + (uint32_t)ks * 32;
                uint32_t swq = qoff ^ ((qoff >> 3) & 0x70);
                uint32_t ah[4], al[4];
                ldsm_x4(ah, QT + swq);
                ldsm_x4(al, QT + 16384 + swq);
                #pragma unroll
                for (int nfp = 0; nfp < 4; nfp++) {
                    uint32_t koff = (uint32_t)(nfp * 16 + (lane & 7) + ((lane & 16) >> 1)) * 128
                                    + (uint32_t)ks * 32 + ((lane & 8) << 1);
                    uint32_t swk = koff ^ ((koff >> 3) & 0x70);
                    uint32_t kbh[4], kbl[4];
                    ldsm_x4(kbh, kb + swk);
                    ldsm_x4(kbl, kb + 8192 + swk);
                    mma_bf16(p[2 * nfp],     ah, &kbh[0]);
                    mma_bf16(p[2 * nfp],     ah, &kbl[0]);
                    mma_bf16(p[2 * nfp],     al, &kbh[0]);
                    mma_bf16(p[2 * nfp + 1], ah, &kbh[2]);
                    mma_bf16(p[2 * nfp + 1], ah, &kbl[2]);
                    mma_bf16(p[2 * nfp + 1], al, &kbh[2]);
                }
            }

            const bool need_mask = (jt * 64 + 63) > rowmin;
            #pragma unroll
            for (int nf = 0; nf < 8; nf++)
                #pragma unroll
                for (int r = 0; r < 4; r++) {
                    float v = p[nf][r] * 0.125f;
                    if (need_mask) {
                        int qr = rowmin + g + ((r & 2) << 2);
                        int kc = jt * 64 + 8 * nf + 2 * tig + (r & 1);
                        if (kc > qr) v = -1e30f;
                    }
                    p[nf][r] = v;
                }

            float mx0 = m0, mx1 = m1;
            #pragma unroll
            for (int nf = 0; nf < 8; nf++) {
                mx0 = fmaxf(mx0, fmaxf(p[nf][0], p[nf][1]));
                mx1 = fmaxf(mx1, fmaxf(p[nf][2], p[nf][3]));
            }
            mx0 = fmaxf(mx0, __shfl_xor_sync(0xffffffffu, mx0, 1));
            mx0 = fmaxf(mx0, __shfl_xor_sync(0xffffffffu, mx0, 2));
            mx1 = fmaxf(mx1, __shfl_xor_sync(0xffffffffu, mx1, 1));
            mx1 = fmaxf(mx1, __shfl_xor_sync(0xffffffffu, mx1, 2));
            float c0 = __expf(m0 - mx0), c1 = __expf(m1 - mx1);
            m0 = mx0; m1 = mx1;
            float s0 = 0.f, s1 = 0.f;
            #pragma unroll
            for (int nf = 0; nf < 8; nf++) {
                p[nf][0] = __expf(p[nf][0] - mx0); s0 += p[nf][0];
                p[nf][1] = __expf(p[nf][1] - mx0); s0 += p[nf][1];
                p[nf][2] = __expf(p[nf][2] - mx1); s1 += p[nf][2];
                p[nf][3] = __expf(p[nf][3] - mx1); s1 += p[nf][3];
            }
            s0 += __shfl_xor_sync(0xffffffffu, s0, 1);
            s0 += __shfl_xor_sync(0xffffffffu, s0, 2);
            s1 += __shfl_xor_sync(0xffffffffu, s1, 1);
            s1 += __shfl_xor_sync(0xffffffffu, s1, 2);
            l0 = l0 * c0 + s0;
            l1 = l1 * c1 + s1;
            #pragma unroll
            for (int nf = 0; nf < 8; nf++) {
                o[nf][0] *= c0; o[nf][1] *= c0;
                o[nf][2] *= c1; o[nf][3] *= c1;
            }

            #pragma unroll
            for (int j = 0; j < 4; j++) {
                uint32_t pah[4], pal[4];
                #pragma unroll
                for (int half = 0; half < 2; half++) {
                    const float* pf = p[2 * j + half];
                    __nv_bfloat16 h0 = __float2bfloat16(pf[0]);
                    __nv_bfloat16 h1 = __float2bfloat16(pf[1]);
                    __nv_bfloat16 h2 = __float2bfloat16(pf[2]);
                    __nv_bfloat16 h3 = __float2bfloat16(pf[3]);
                    pah[2 * half]     = pack_bf2(h0, h1);
                    pah[2 * half + 1] = pack_bf2(h2, h3);
                    pal[2 * half]     = pack_bf2(__float2bfloat16(pf[0] - __bfloat162float(h0)),
                                                 __float2bfloat16(pf[1] - __bfloat162float(h1)));
                    pal[2 * half + 1] = pack_bf2(__float2bfloat16(pf[2] - __bfloat162float(h2)),
                                                 __float2bfloat16(pf[3] - __bfloat162float(h3)));
                }
                #pragma unroll
                for (int nfp = 0; nfp < 4; nfp++) {
                    uint32_t voff = (uint32_t)(16 * j + (lane & 7) + (lane & 8)) * 128
                                    + (uint32_t)nfp * 32 + (lane & 16);
                    uint32_t swv = voff ^ ((voff >> 3) & 0x70);
                    uint32_t vbh[4], vbl[4];
                    ldsm_x4t(vbh, kb + 16384 + swv);
                    ldsm_x4t(vbl, kb + 24576 + swv);
                    mma_bf16(o[2 * nfp],     pah, &vbh[0]);
                    mma_bf16(o[2 * nfp],     pah, &vbl[0]);
                    mma_bf16(o[2 * nfp],     pal, &vbh[0]);
                    mma_bf16(o[2 * nfp + 1], pah, &vbh[2]);
                    mma_bf16(o[2 * nfp + 1], pah, &vbl[2]);
                    mma_bf16(o[2 * nfp + 1], pal, &vbh[2]);
                }
            }
        }
        __syncthreads();
        if (tid == 0 && jt + 2 < jmax) issue(jt + 2);
    }

    // epilogue: O /= l; write fp32 AO + row max (for int8 requant)
    const float i0 = 1.f / l0, i1 = 1.f / l1;
    #pragma unroll
    for (int rh = 0; rh < 2; rh++) {
        const float inv = rh ? i1 : i0;
        const int row = b * 512 + qt * 128 + w * 16 + g + 8 * rh;
        float2* dst = (float2*)(g_ao + (size_t)row * DD + h * 64 + 2 * tig);
        float mloc = 0.f;
        #pragma unroll
        for (int nf = 0; nf < 8; nf++) {
            float y0 = o[nf][2 * rh] * inv;
            float y1 = o[nf][2 * rh + 1] * inv;
            mloc = fmaxf(mloc, fmaxf(fabsf(y0), fabsf(y1)));
            dst[nf * 4] = make_float2(y0, y1);
        }
        mloc = fmaxf(mloc, __shfl_xor_sync(0xffffffffu, mloc, 1));
        mloc = fmaxf(mloc, __shfl_xor_sync(0xffffffffu, mloc, 2));
        if (tig == 0) atomicMax(&g_aomax[row], __float_as_uint(mloc));
    }
}

// ---------------- launch ----------------
extern "C" void kernel_launch(void* const* d_in, const int* in_sizes, int n_in,
                              void* d_out, int out_size) {
    const float* x  = (const float*)d_in[0];
    const float* qw = (const float*)d_in[1];
    const float* kw = (const float*)d_in[2];
    const float* vw = (const float*)d_in[3];
    const float* ow = (const float*)d_in[4];
    const float* rw = (const float*)d_in[5];
    const float* rb = (const float*)d_in[6];
    float* out = (float*)d_out;

    const int GEMM_SMEM = 1024 + 2 * 65536;           // 132096
    cudaFuncSetAttribute(imma_gemm_kernel, cudaFuncAttributeMaxDynamicSharedMemorySize, GEMM_SMEM);
    const int ATTN_SMEM = 1024 + 32768 + 2 * 32768;   // 99328
    cudaFuncSetAttribute(attn_kernel, cudaFuncAttributeMaxDynamicSharedMemorySize, ATTN_SMEM);

    rope_init_kernel<<<64, 256>>>();                                          // 0

    int write_probs = (out_size >= BB * LL * DD + BB * EE) ? 1 : 0;
    router_kernel<<<BB, 256>>>(x, rw, rb, out + (size_t)BB * LL * DD, write_probs); // 1

    maxes_kernel<<<2176, 256>>>(x, qw, kw, vw, ow);                           // 2
    convert_kernel<<<3072, 256>>>(x, qw, kw, vw, ow);                         // 3

    // fused Q/K/V projection (ncu capture target: launch index 4)
    imma_gemm_kernel<<<dim3(24, 4, BB), 256, GEMM_SMEM>>>(nullptr, 0, 0);     // 4

    attn_kernel<<<dim3(4, BB * HH), 256, ATTN_SMEM>>>();                      // 5

    convert_ao_kernel<<<dim3(8, 128), 256>>>();                               // 6

    imma_gemm_kernel<<<dim3(8, 4, BB), 256, GEMM_SMEM>>>(out, 1, 3);          // 7
}

// round 8
// speedup vs baseline: 3.2319x; 3.2319x over previous
#include <cuda_runtime.h>
#include <cuda_bf16.h>
#include <cuda_fp16.h>
#include <cstdint>
#include <math.h>

#define BB 32
#define LL 512
#define DD 1024
#define HH 16
#define HDIM 64
#define EE 8

// ---------------- scratch (device globals; no allocation allowed) ----------------
__device__ float g_cos[LL * 32];
__device__ float g_sin[LL * 32];
__device__ int   g_routes[BB];

// X/AO tiles: [rt(128)][kc(16)] each 128 rows x 64 cols fp16 (16KB), SW128-swizzled
__device__ __half g_xh[(size_t)16384 * 1024];
__device__ __half g_xl[(size_t)16384 * 1024];
// W^T tiles (single fp16): [mode(4)][e(8)][nt(8)][kc(16)] each 128(n) x 64(k), SW128
__device__ __half g_wt[(size_t)4 * 8 * 1024 * 1024];
// q/k/v bf16 hi/lo: [B*H][512][64], SW128-swizzled 128B rows
__device__ __nv_bfloat16 g_qh[(size_t)BB * HH * LL * HDIM];
__device__ __nv_bfloat16 g_ql[(size_t)BB * HH * LL * HDIM];
__device__ __nv_bfloat16 g_kh[(size_t)BB * HH * LL * HDIM];
__device__ __nv_bfloat16 g_kl[(size_t)BB * HH * LL * HDIM];
__device__ __nv_bfloat16 g_vh[(size_t)BB * HH * LL * HDIM];
__device__ __nv_bfloat16 g_vl[(size_t)BB * HH * LL * HDIM];

// ---------------- PTX helpers ----------------
__device__ __forceinline__ uint32_t smem_u32(const void* p) {
    uint32_t a;
    asm("{ .reg .u64 t; cvta.to.shared.u64 t, %1; cvt.u32.u64 %0, t; }" : "=r"(a) : "l"(p));
    return a;
}

#define MBAR_INIT(a, n) \
    asm volatile("mbarrier.init.shared.b64 [%0], %1;" :: "r"(a), "r"((uint32_t)(n)) : "memory")
#define MBAR_EXPECT_TX(a, b) \
    asm volatile("mbarrier.arrive.expect_tx.shared.b64 _, [%0], %1;" :: "r"(a), "r"((uint32_t)(b)) : "memory")

__device__ __forceinline__ void mbar_wait(uint32_t mbar, uint32_t parity) {
    asm volatile(
        "{\n\t.reg .pred P;\n\t"
        "WL_%=:\n\t"
        "mbarrier.try_wait.parity.acquire.cta.shared::cta.b64 P, [%0], %1, 0x989680;\n\t"
        "@P bra.uni WD_%=;\n\t"
        "bra.uni WL_%=;\n\t"
        "WD_%=:\n\t}"
        :: "r"(mbar), "r"(parity) : "memory");
}

__device__ __forceinline__ void bulk_g2s(uint32_t dst, const void* src, uint32_t bytes, uint32_t mbar) {
    asm volatile(
        "cp.async.bulk.shared::cluster.global.mbarrier::complete_tx::bytes [%0], [%1], %2, [%3];"
        :: "r"(dst), "l"(src), "r"(bytes), "r"(mbar) : "memory");
}

__device__ __forceinline__ void ldsm_x4(uint32_t* r, uint32_t a) {
    asm volatile("ldmatrix.sync.aligned.m8n8.x4.shared.b16 {%0,%1,%2,%3}, [%4];"
                 : "=r"(r[0]), "=r"(r[1]), "=r"(r[2]), "=r"(r[3]) : "r"(a));
}
__device__ __forceinline__ void ldsm_x4t(uint32_t* r, uint32_t a) {
    asm volatile("ldmatrix.sync.aligned.m8n8.x4.trans.shared.b16 {%0,%1,%2,%3}, [%4];"
                 : "=r"(r[0]), "=r"(r[1]), "=r"(r[2]), "=r"(r[3]) : "r"(a));
}
__device__ __forceinline__ void mma_bf16(float* d, const uint32_t* a, const uint32_t* b) {
    asm volatile(
        "mma.sync.aligned.m16n8k16.row.col.f32.bf16.bf16.f32 "
        "{%0,%1,%2,%3}, {%4,%5,%6,%7}, {%8,%9}, {%0,%1,%2,%3};"
        : "+f"(d[0]), "+f"(d[1]), "+f"(d[2]), "+f"(d[3])
        : "r"(a[0]), "r"(a[1]), "r"(a[2]), "r"(a[3]), "r"(b[0]), "r"(b[1]));
}
__device__ __forceinline__ void mma_f16(float* d, const uint32_t* a, const uint32_t* b) {
    asm volatile(
        "mma.sync.aligned.m16n8k16.row.col.f32.f16.f16.f32 "
        "{%0,%1,%2,%3}, {%4,%5,%6,%7}, {%8,%9}, {%0,%1,%2,%3};"
        : "+f"(d[0]), "+f"(d[1]), "+f"(d[2]), "+f"(d[3])
        : "r"(a[0]), "r"(a[1]), "r"(a[2]), "r"(a[3]), "r"(b[0]), "r"(b[1]));
}

__device__ __forceinline__ uint32_t pack_bf2(__nv_bfloat16 a, __nv_bfloat16 b) {
    return (uint32_t)__bfloat16_as_ushort(a) | ((uint32_t)__bfloat16_as_ushort(b) << 16);
}
__device__ __forceinline__ uint32_t pack_h2(__half a, __half b) {
    return (uint32_t)__half_as_ushort(a) | ((uint32_t)__half_as_ushort(b) << 16);
}

// ---------------- RoPE tables ----------------
__global__ void rope_init_kernel() {
    int idx = blockIdx.x * blockDim.x + threadIdx.x;
    if (idx >= LL * 32) return;
    int l = idx >> 5;
    int jp = idx & 31;
    float inv = 1.0f / powf(10000.0f, (float)(2 * jp) / 64.0f);
    float ang = (float)l * inv;
    g_cos[idx] = cosf(ang);
    g_sin[idx] = sinf(ang);
}

// ---------------- router ----------------
__global__ void router_kernel(const float* __restrict__ x,
                              const float* __restrict__ rw,
                              const float* __restrict__ rb,
                              float* __restrict__ probs_out,
                              int write_probs) {
    int b = blockIdx.x;
    __shared__ float mean[DD];
    __shared__ float logits[EE];

    for (int d = threadIdx.x; d < DD; d += blockDim.x) {
        const float* xp = x + (size_t)b * LL * DD + d;
        float s = 0.f;
        #pragma unroll 8
        for (int l = 0; l < LL; l++) s += xp[(size_t)l * DD];
        mean[d] = s * (1.0f / (float)LL);
    }
    __syncthreads();

    int w = threadIdx.x >> 5;
    int lane = threadIdx.x & 31;
    if (w < EE) {
        float s = 0.f;
        for (int d = lane; d < DD; d += 32) s += mean[d] * rw[d * EE + w];
        #pragma unroll
        for (int o = 16; o > 0; o >>= 1) s += __shfl_down_sync(0xffffffffu, s, o);
        if (lane == 0) logits[w] = s + rb[w];
    }
    __syncthreads();

    if (threadIdx.x == 0) {
        float m = logits[0]; int arg = 0;
        #pragma unroll
        for (int e = 1; e < EE; e++) if (logits[e] > m) { m = logits[e]; arg = e; }
        float p[EE], sum = 0.f;
        #pragma unroll
        for (int e = 0; e < EE; e++) { p[e] = expf(logits[e] - m); sum += p[e]; }
        if (write_probs) {
            float inv = 1.0f / sum;
            #pragma unroll
            for (int e = 0; e < EE; e++) probs_out[b * EE + e] = p[e] * inv;
        }
        g_routes[b] = arg;
    }
}

// ---------------- merged convert: X tiles (hi/lo) + W^T tiles (single fp16) ----------
__global__ void convert_kernel(const float* __restrict__ x,
                               const float* __restrict__ qw, const float* __restrict__ kw,
                               const float* __restrict__ vw, const float* __restrict__ ow) {
    __shared__ float sm[64][129];
    const int bid = blockIdx.x;
    const int tid = threadIdx.x;

    if (bid < 2048) {
        // X tile: rt = bid>>4, kc = bid&15; 128 rows x 64 cols
        const int rt = bid >> 4, kc = bid & 15;
        const size_t tb = ((size_t)rt * 16 + kc) * 8192;   // elements
        char* dh = (char*)(g_xh + tb);
        char* dl = (char*)(g_xl + tb);
        #pragma unroll
        for (int i = 0; i < 4; i++) {
            int u = tid + i * 256;               // 0..1023 16B units
            int r = u >> 3, k8 = u & 7;
            const float* p = x + ((size_t)(rt * 128 + r)) * DD + kc * 64 + k8 * 8;
            float4 a = *(const float4*)p;
            float4 b4 = *(const float4*)(p + 4);
            float xs[8] = {a.x, a.y, a.z, a.w, b4.x, b4.y, b4.z, b4.w};
            __half hi[8], lo[8];
            #pragma unroll
            for (int j = 0; j < 8; j++) {
                hi[j] = __float2half_rn(xs[j]);
                lo[j] = __float2half_rn(xs[j] - __half2float(hi[j]));
            }
            uint32_t off = (uint32_t)(u * 16);
            off ^= (off >> 3) & 0x70;            // SW128
            *(uint4*)(dh + off) = make_uint4(pack_h2(hi[0], hi[1]), pack_h2(hi[2], hi[3]),
                                             pack_h2(hi[4], hi[5]), pack_h2(hi[6], hi[7]));
            *(uint4*)(dl + off) = make_uint4(pack_h2(lo[0], lo[1]), pack_h2(lo[2], lo[3]),
                                             pack_h2(lo[4], lo[5]), pack_h2(lo[6], lo[7]));
        }
    } else {
        // W tile: idx -> kc(16), nt(8), e(8), mode(4). Output 128 n-rows x 64 k fp16.
        const int idx = bid - 2048;
        const int kc = idx & 15, nt = (idx >> 4) & 7;
        const int e = (idx >> 7) & 7, mode = idx >> 10;
        const float* W = (mode == 0) ? qw : (mode == 1) ? kw : (mode == 2) ? vw : ow;
        const float* src = W + ((size_t)e * DD + kc * 64) * DD + nt * 128;

        #pragma unroll
        for (int i = 0; i < 8; i++) {
            int idx2 = tid + i * 256;            // 0..2047 float4s (64 k-rows x 128 n)
            int kr = idx2 >> 5, nc = (idx2 & 31) << 2;
            float4 v = *(const float4*)(src + (size_t)kr * DD + nc);
            sm[kr][nc] = v.x; sm[kr][nc + 1] = v.y; sm[kr][nc + 2] = v.z; sm[kr][nc + 3] = v.w;
        }
        __syncthreads();

        const size_t tb = (((size_t)(mode * 8 + e) * 8 + nt) * 16 + kc) * 8192;
        char* dw = (char*)(g_wt + tb);
        #pragma unroll
        for (int i = 0; i < 4; i++) {
            int u = tid + i * 256;               // 0..1023 16B units
            int n = u >> 3, k8 = u & 7;
            __half h[8];
            #pragma unroll
            for (int j = 0; j < 8; j++) h[j] = __float2half_rn(sm[k8 * 8 + j][n]);
            uint32_t off = (uint32_t)(u * 16);
            off ^= (off >> 3) & 0x70;
            *(uint4*)(dw + off) = make_uint4(pack_h2(h[0], h[1]), pack_h2(h[2], h[3]),
                                             pack_h2(h[4], h[5]), pack_h2(h[6], h[7]));
        }
    }
}

// ---------------- HMMA GEMM: CTA 128x256, warp 64x64, 2-term fp16 split --------------
// y = (a_hi + a_lo) * w   (exact in A; error only from W fp16 quantization ~2^-12)
// K=1024 in 16 chunks of 64; 2-stage bulk-copy pipeline (64KB/stage).
__global__ void __launch_bounds__(256, 1) hmma_gemm_kernel(float* __restrict__ out, int mode0) {
    extern __shared__ __align__(1024) char smem[];
    const uint32_t sb = smem_u32(smem);
    const int tid = threadIdx.x;
    const int lane = tid & 31, wid = tid >> 5;
    const int wm = wid >> 2, wn = wid & 3;            // 2(m) x 4(n)
    const int nt = blockIdx.x & 3;
    const int mode = mode0 + (blockIdx.x >> 2);
    const int mt = blockIdx.y, b = blockIdx.z;
    const int e = g_routes[b];

    const uint32_t FULLB = sb;
    const uint32_t TILES = sb + 1024;                 // 2 stages x 64KB: Ah|Al|B0|B1

    if (tid == 0) { MBAR_INIT(FULLB, 1); MBAR_INIT(FULLB + 8, 1); }
    __syncthreads();

    const __half* Ah = g_xh + ((size_t)(b * 4 + mt) * 16) * 8192;
    const __half* Al = g_xl + ((size_t)(b * 4 + mt) * 16) * 8192;
    const __half* B0 = g_wt + (((size_t)(mode * 8 + e) * 8 + 2 * nt) * 16) * 8192;
    const __half* B1 = B0 + (size_t)16 * 8192;

    auto issue = [&](int c) {
        int s = c & 1;
        uint32_t fb = FULLB + s * 8;
        uint32_t st = TILES + s * 65536;
        MBAR_EXPECT_TX(fb, 65536);
        bulk_g2s(st,         Ah + (size_t)c * 8192, 16384, fb);
        bulk_g2s(st + 16384, Al + (size_t)c * 8192, 16384, fb);
        bulk_g2s(st + 32768, B0 + (size_t)c * 8192, 16384, fb);
        bulk_g2s(st + 49152, B1 + (size_t)c * 8192, 16384, fb);
    };
    if (tid == 0) { issue(0); issue(1); }

    float acc[4][8][4];
    #pragma unroll
    for (int mf = 0; mf < 4; mf++)
        #pragma unroll
        for (int nf = 0; nf < 8; nf++)
            #pragma unroll
            for (int r = 0; r < 4; r++) acc[mf][nf][r] = 0.f;

    const uint32_t a_row  = (uint32_t)(wm * 64 + (lane & 15)) * 128;
    const uint32_t a_koff = (uint32_t)(lane >> 4) * 16;
    const uint32_t b_tile = 32768 + (uint32_t)(wn >> 1) * 16384;
    const uint32_t b_row  = (uint32_t)((wn & 1) * 64 + (lane & 7) + ((lane >> 4) << 3)) * 128;
    const uint32_t b_koff = (uint32_t)((lane >> 3) & 1) * 16;

    for (int c = 0; c < 16; c++) {
        const int s = c & 1;
        mbar_wait(FULLB + s * 8, (uint32_t)((c >> 1) & 1));
        const uint32_t base = TILES + s * 65536;

        #pragma unroll
        for (int ks = 0; ks < 4; ks++) {
            const uint32_t k0b = (uint32_t)ks * 32;
            uint32_t ah[4][4], al[4][4];
            #pragma unroll
            for (int mf = 0; mf < 4; mf++) {
                uint32_t byt = a_row + (uint32_t)mf * 2048 + a_koff + k0b;
                uint32_t sw = byt ^ ((byt >> 3) & 0x70);
                ldsm_x4(ah[mf], base + sw);
                ldsm_x4(al[mf], base + 16384 + sw);
            }
            uint32_t bf[4][4];
            #pragma unroll
            for (int p = 0; p < 4; p++) {
                uint32_t byt = b_row + (uint32_t)p * 2048 + b_koff + k0b;
                uint32_t sw = byt ^ ((byt >> 3) & 0x70);
                ldsm_x4(bf[p], base + b_tile + sw);
            }
            // term 1: a_hi * w  (32 independent accumulators)
            #pragma unroll
            for (int p = 0; p < 4; p++)
                #pragma unroll
                for (int mf = 0; mf < 4; mf++) {
                    mma_f16(acc[mf][2 * p],     ah[mf], &bf[p][0]);
                    mma_f16(acc[mf][2 * p + 1], ah[mf], &bf[p][2]);
                }
            // term 2: a_lo * w
            #pragma unroll
            for (int p = 0; p < 4; p++)
                #pragma unroll
                for (int mf = 0; mf < 4; mf++) {
                    mma_f16(acc[mf][2 * p],     al[mf], &bf[p][0]);
                    mma_f16(acc[mf][2 * p + 1], al[mf], &bf[p][2]);
                }
        }
        __syncthreads();
        if (tid == 0 && c + 2 < 16) issue(c + 2);
    }

    // ---------------- epilogue ----------------
    const int l_base = mt * 128 + wm * 64 + (lane >> 2);
    const int tig = lane & 3;
    const int hglob = nt * 4 + wn;               // whole warp same 64-col group

    #pragma unroll
    for (int mf = 0; mf < 4; mf++) {
        #pragma unroll
        for (int rh = 0; rh < 2; rh++) {
            const int l = l_base + mf * 16 + 8 * rh;
            #pragma unroll
            for (int nf = 0; nf < 8; nf++) {
                const int d = 8 * nf + 2 * tig;
                float x0 = acc[mf][nf][2 * rh];
                float x1 = acc[mf][nf][2 * rh + 1];
                if (mode == 3) {
                    float2* dst = (float2*)(out + ((size_t)b * LL + l) * DD + hglob * 64 + d);
                    *dst = make_float2(x0, x1);
                } else {
                    float y0, y1;
                    if (mode == 2) { y0 = x0; y1 = x1; }
                    else {
                        const int p = d >> 1;
                        float cs = g_cos[l * 32 + p];
                        float sn = g_sin[l * 32 + p];
                        y0 = x0 * cs - x1 * sn;
                        y1 = x1 * cs + x0 * sn;
                    }
                    __nv_bfloat16 hb0 = __float2bfloat16(y0);
                    __nv_bfloat16 hb1 = __float2bfloat16(y1);
                    __nv_bfloat16 lb0 = __float2bfloat16(y0 - __bfloat162float(hb0));
                    __nv_bfloat16 lb1 = __float2bfloat16(y1 - __bfloat162float(hb1));
                    uint32_t off = (uint32_t)((((b * HH + hglob) * LL) + l) * 128 + d * 2);
                    uint32_t sw = off ^ ((off >> 3) & 0x70);
                    char* bhp = (char*)((mode == 0) ? g_qh : (mode == 1) ? g_kh : g_vh);
                    char* blp = (char*)((mode == 0) ? g_ql : (mode == 1) ? g_kl : g_vl);
                    *(uint32_t*)(bhp + sw) = pack_bf2(hb0, hb1);
                    *(uint32_t*)(blp + sw) = pack_bf2(lb0, lb1);
                }
            }
        }
    }
}

// ---------------- flash attention on HMMA: 128 q-rows/CTA, 8 warps x 16 rows ---------
__global__ void __launch_bounds__(256, 2) attn_kernel() {
    extern __shared__ __align__(1024) char smem[];
    const uint32_t sb = smem_u32(smem);
    const int tid = threadIdx.x, lane = tid & 31, w = tid >> 5;
    const int qt = 3 - blockIdx.x;       // long CTAs first
    const int bh = blockIdx.y;
    const int b = bh >> 4, h = bh & 15;
    const int g = lane >> 2, tig = lane & 3;

    const uint32_t QB = sb;
    const uint32_t FB = sb + 8;
    const uint32_t QT = sb + 1024;
    const uint32_t KV = sb + 1024 + 32768;

    if (tid == 0) { MBAR_INIT(QB, 1); MBAR_INIT(FB, 1); MBAR_INIT(FB + 8, 1); }
    __syncthreads();

    const size_t bh_off = (size_t)bh * LL * HDIM;
    const __nv_bfloat16* kh = g_kh + bh_off;
    const __nv_bfloat16* kl = g_kl + bh_off;
    const __nv_bfloat16* vh = g_vh + bh_off;
    const __nv_bfloat16* vl = g_vl + bh_off;

    const int jmax = 2 * qt + 2;

    auto issue = [&](int jt) {
        int s = jt & 1;
        uint32_t fb = FB + s * 8;
        uint32_t st = KV + s * 32768;
        MBAR_EXPECT_TX(fb, 32768);
        bulk_g2s(st,         kh + (size_t)jt * 4096, 8192, fb);
        bulk_g2s(st + 8192,  kl + (size_t)jt * 4096, 8192, fb);
        bulk_g2s(st + 16384, vh + (size_t)jt * 4096, 8192, fb);
        bulk_g2s(st + 24576, vl + (size_t)jt * 4096, 8192, fb);
    };
    if (tid == 0) {
        MBAR_EXPECT_TX(QB, 32768);
        bulk_g2s(QT,         g_qh + bh_off + (size_t)qt * 128 * 64, 16384, QB);
        bulk_g2s(QT + 16384, g_ql + bh_off + (size_t)qt * 128 * 64, 16384, QB);
        issue(0);
        issue(1);
    }

    float o[8][4];
    #pragma unroll
    for (int nf = 0; nf < 8; nf++)
        #pragma unroll
        for (int r = 0; r < 4; r++) o[nf][r] = 0.f;
    float m0 = -1e30f, m1 = -1e30f, l0 = 0.f, l1 = 0.f;

    const int rowmin = qt * 128 + w * 16;

    mbar_wait(QB, 0);

    for (int jt = 0; jt < jmax; jt++) {
        const int s = jt & 1;
        mbar_wait(FB + s * 8, (uint32_t)((jt >> 1) & 1));
        const uint32_t kb = KV + s * 32768;

        if (jt * 64 <= rowmin + 15) {
            float p[8][4];
            #pragma unroll
            for (int nf = 0; nf < 8; nf++)
                #pragma unroll
                for (int r = 0; r < 4; r++) p[nf][r] = 0.f;

            #pragma unroll
            for (int ks = 0; ks < 4; ks++) {
                uint32_t qoff = (uint32_t)(w * 16 + (lane & 15)) * 128
                                + (uint32_t)(lane >> 4) * 16 + (uint32_t)ks * 32;
                uint32_t swq = qoff ^ ((qoff >> 3) & 0x70);
                uint32_t ah[4], al[4];
                ldsm_x4(ah, QT + swq);
                ldsm_x4(al, QT + 16384 + swq);
                #pragma unroll
                for (int nfp = 0; nfp < 4; nfp++) {
                    uint32_t koff = (uint32_t)(nfp * 16 + (lane & 7) + ((lane & 16) >> 1)) * 128
                                    + (uint32_t)ks * 32 + ((lane & 8) << 1);
                    uint32_t swk = koff ^ ((koff >> 3) & 0x70);
                    uint32_t kbh[4], kbl[4];
                    ldsm_x4(kbh, kb + swk);
                    ldsm_x4(kbl, kb + 8192 + swk);
                    mma_bf16(p[2 * nfp],     ah, &kbh[0]);
                    mma_bf16(p[2 * nfp],     ah, &kbl[0]);
                    mma_bf16(p[2 * nfp],     al, &kbh[0]);
                    mma_bf16(p[2 * nfp + 1], ah, &kbh[2]);
                    mma_bf16(p[2 * nfp + 1], ah, &kbl[2]);
                    mma_bf16(p[2 * nfp + 1], al, &kbh[2]);
                }
            }

            const bool need_mask = (jt * 64 + 63) > rowmin;
            #pragma unroll
            for (int nf = 0; nf < 8; nf++)
                #pragma unroll
                for (int r = 0; r < 4; r++) {
                    float v = p[nf][r] * 0.125f;
                    if (need_mask) {
                        int qr = rowmin + g + ((r & 2) << 2);
                        int kc = jt * 64 + 8 * nf + 2 * tig + (r & 1);
                        if (kc > qr) v = -1e30f;
                    }
                    p[nf][r] = v;
                }

            float mx0 = m0, mx1 = m1;
            #pragma unroll
            for (int nf = 0; nf < 8; nf++) {
                mx0 = fmaxf(mx0, fmaxf(p[nf][0], p[nf][1]));
                mx1 = fmaxf(mx1, fmaxf(p[nf][2], p[nf][3]));
            }
            mx0 = fmaxf(mx0, __shfl_xor_sync(0xffffffffu, mx0, 1));
            mx0 = fmaxf(mx0, __shfl_xor_sync(0xffffffffu, mx0, 2));
            mx1 = fmaxf(mx1, __shfl_xor_sync(0xffffffffu, mx1, 1));
            mx1 = fmaxf(mx1, __shfl_xor_sync(0xffffffffu, mx1, 2));
            float c0 = __expf(m0 - mx0), c1 = __expf(m1 - mx1);
            m0 = mx0; m1 = mx1;
            float s0 = 0.f, s1 = 0.f;
            #pragma unroll
            for (int nf = 0; nf < 8; nf++) {
                p[nf][0] = __expf(p[nf][0] - mx0); s0 += p[nf][0];
                p[nf][1] = __expf(p[nf][1] - mx0); s0 += p[nf][1];
                p[nf][2] = __expf(p[nf][2] - mx1); s1 += p[nf][2];
                p[nf][3] = __expf(p[nf][3] - mx1); s1 += p[nf][3];
            }
            s0 += __shfl_xor_sync(0xffffffffu, s0, 1);
            s0 += __shfl_xor_sync(0xffffffffu, s0, 2);
            s1 += __shfl_xor_sync(0xffffffffu, s1, 1);
            s1 += __shfl_xor_sync(0xffffffffu, s1, 2);
            l0 = l0 * c0 + s0;
            l1 = l1 * c1 + s1;
            #pragma unroll
            for (int nf = 0; nf < 8; nf++) {
                o[nf][0] *= c0; o[nf][1] *= c0;
                o[nf][2] *= c1; o[nf][3] *= c1;
            }

            #pragma unroll
            for (int j = 0; j < 4; j++) {
                uint32_t pah[4], pal[4];
                #pragma unroll
                for (int half = 0; half < 2; half++) {
                    const float* pf = p[2 * j + half];
                    __nv_bfloat16 h0 = __float2bfloat16(pf[0]);
                    __nv_bfloat16 h1 = __float2bfloat16(pf[1]);
                    __nv_bfloat16 h2 = __float2bfloat16(pf[2]);
                    __nv_bfloat16 h3 = __float2bfloat16(pf[3]);
                    pah[2 * half]     = pack_bf2(h0, h1);
                    pah[2 * half + 1] = pack_bf2(h2, h3);
                    pal[2 * half]     = pack_bf2(__float2bfloat16(pf[0] - __bfloat162float(h0)),
                                                 __float2bfloat16(pf[1] - __bfloat162float(h1)));
                    pal[2 * half + 1] = pack_bf2(__float2bfloat16(pf[2] - __bfloat162float(h2)),
                                                 __float2bfloat16(pf[3] - __bfloat162float(h3)));
                }
                #pragma unroll
                for (int nfp = 0; nfp < 4; nfp++) {
                    uint32_t voff = (uint32_t)(16 * j + (lane & 7) + (lane & 8)) * 128
                                    + (uint32_t)nfp * 32 + (lane & 16);
                    uint32_t swv = voff ^ ((voff >> 3) & 0x70);
                    uint32_t vbh[4], vbl[4];
                    ldsm_x4t(vbh, kb + 16384 + swv);
                    ldsm_x4t(vbl, kb + 24576 + swv);
                    mma_bf16(o[2 * nfp],     pah, &vbh[0]);
                    mma_bf16(o[2 * nfp],     pah, &vbl[0]);
                    mma_bf16(o[2 * nfp],     pal, &vbh[0]);
                    mma_bf16(o[2 * nfp + 1], pah, &vbh[2]);
                    mma_bf16(o[2 * nfp + 1], pah, &vbl[2]);
                    mma_bf16(o[2 * nfp + 1], pal, &vbh[2]);
                }
            }
        }
        __syncthreads();
        if (tid == 0 && jt + 2 < jmax) issue(jt + 2);
    }

    // epilogue: O /= l; write AO as fp16 hi/lo swizzled tile (rt = b*4+qt, kc = h)
    const float i0 = 1.f / l0, i1 = 1.f / l1;
    const size_t tb = (((size_t)(b * 4 + qt) * 16) + h) * 16384;   // bytes
    char* dh = (char*)g_xh + tb;
    char* dl = (char*)g_xl + tb;
    #pragma unroll
    for (int nf = 0; nf < 8; nf++) {
        #pragma unroll
        for (int rh = 0; rh < 2; rh++) {
            float y0 = o[nf][2 * rh]     * (rh ? i1 : i0);
            float y1 = o[nf][2 * rh + 1] * (rh ? i1 : i0);
            __half hb0 = __float2half_rn(y0);
            __half hb1 = __float2half_rn(y1);
            __half lb0 = __float2half_rn(y0 - __half2float(hb0));
            __half lb1 = __float2half_rn(y1 - __half2float(hb1));
            uint32_t off = (uint32_t)((w * 16 + g + 8 * rh) * 128 + (8 * nf + 2 * tig) * 2);
            uint32_t sw = off ^ ((off >> 3) & 0x70);
            *(uint32_t*)(dh + sw) = pack_h2(hb0, hb1);
            *(uint32_t*)(dl + sw) = pack_h2(lb0, lb1);
        }
    }
}

// ---------------- launch ----------------
extern "C" void kernel_launch(void* const* d_in, const int* in_sizes, int n_in,
                              void* d_out, int out_size) {
    const float* x  = (const float*)d_in[0];
    const float* qw = (const float*)d_in[1];
    const float* kw = (const float*)d_in[2];
    const float* vw = (const float*)d_in[3];
    const float* ow = (const float*)d_in[4];
    const float* rw = (const float*)d_in[5];
    const float* rb = (const float*)d_in[6];
    float* out = (float*)d_out;

    const int GEMM_SMEM = 1024 + 2 * 65536;           // 132096
    cudaFuncSetAttribute(hmma_gemm_kernel, cudaFuncAttributeMaxDynamicSharedMemorySize, GEMM_SMEM);
    const int ATTN_SMEM = 1024 + 32768 + 2 * 32768;   // 99328
    cudaFuncSetAttribute(attn_kernel, cudaFuncAttributeMaxDynamicSharedMemorySize, ATTN_SMEM);

    rope_init_kernel<<<64, 256>>>();                                          // 0

    int write_probs = (out_size >= BB * LL * DD + BB * EE) ? 1 : 0;
    router_kernel<<<BB, 256>>>(x, rw, rb, out + (size_t)BB * LL * DD, write_probs); // 1

    convert_kernel<<<6144, 256>>>(x, qw, kw, vw, ow);                         // 2

    // fused Q/K/V projection (profiled: launch index 3)
    hmma_gemm_kernel<<<dim3(12, 4, BB), 256, GEMM_SMEM>>>(nullptr, 0);        // 3

    attn_kernel<<<dim3(4, BB * HH), 256, ATTN_SMEM>>>();                      // 4

    // out projection (AO tiles written directly by attention epilogue)
    hmma_gemm_kernel<<<dim3(4, 4, BB), 256, GEMM_SMEM>>>(out, 3);             // 5
}

// round 9
// speedup vs baseline: 3.8017x; 1.1763x over previous
#include <cuda_runtime.h>
#include <cuda_bf16.h>
#include <cuda_fp16.h>
#include <cstdint>
#include <math.h>

#define BB 32
#define LL 512
#define DD 1024
#define HH 16
#define HDIM 64
#define EE 8

// ---------------- scratch (device globals; no allocation allowed) ----------------
__device__ float g_cos[LL * 32];
__device__ float g_sin[LL * 32];
__device__ int   g_routes[BB];

// X/AO tiles: [rt(128)][kc(16)] each 128 rows x 64 cols fp16 (16KB), SW128-swizzled
__device__ __half g_xh[(size_t)16384 * 1024];
__device__ __half g_xl[(size_t)16384 * 1024];
// W^T tiles (single fp16): [mode(4)][e(8)][nt(8)][kc(16)] each 128(n) x 64(k), SW128
__device__ __half g_wt[(size_t)4 * 8 * 1024 * 1024];
// q fp16 hi/lo (A-side of S, exact split); k/v single fp16 (B-side)
__device__ __half g_qh[(size_t)BB * HH * LL * HDIM];
__device__ __half g_ql[(size_t)BB * HH * LL * HDIM];
__device__ __half g_kh[(size_t)BB * HH * LL * HDIM];
__device__ __half g_vh[(size_t)BB * HH * LL * HDIM];

// ---------------- PTX helpers ----------------
__device__ __forceinline__ uint32_t smem_u32(const void* p) {
    uint32_t a;
    asm("{ .reg .u64 t; cvta.to.shared.u64 t, %1; cvt.u32.u64 %0, t; }" : "=r"(a) : "l"(p));
    return a;
}

#define MBAR_INIT(a, n) \
    asm volatile("mbarrier.init.shared.b64 [%0], %1;" :: "r"(a), "r"((uint32_t)(n)) : "memory")
#define MBAR_EXPECT_TX(a, b) \
    asm volatile("mbarrier.arrive.expect_tx.shared.b64 _, [%0], %1;" :: "r"(a), "r"((uint32_t)(b)) : "memory")
#define MBAR_ARRIVE(a) \
    asm volatile("mbarrier.arrive.shared.b64 _, [%0];" :: "r"(a) : "memory")

__device__ __forceinline__ void mbar_wait(uint32_t mbar, uint32_t parity) {
    asm volatile(
        "{\n\t.reg .pred P;\n\t"
        "WL_%=:\n\t"
        "mbarrier.try_wait.parity.acquire.cta.shared::cta.b64 P, [%0], %1, 0x989680;\n\t"
        "@P bra.uni WD_%=;\n\t"
        "bra.uni WL_%=;\n\t"
        "WD_%=:\n\t}"
        :: "r"(mbar), "r"(parity) : "memory");
}

__device__ __forceinline__ void bulk_g2s(uint32_t dst, const void* src, uint32_t bytes, uint32_t mbar) {
    asm volatile(
        "cp.async.bulk.shared::cluster.global.mbarrier::complete_tx::bytes [%0], [%1], %2, [%3];"
        :: "r"(dst), "l"(src), "r"(bytes), "r"(mbar) : "memory");
}

__device__ __forceinline__ void ldsm_x4(uint32_t* r, uint32_t a) {
    asm volatile("ldmatrix.sync.aligned.m8n8.x4.shared.b16 {%0,%1,%2,%3}, [%4];"
                 : "=r"(r[0]), "=r"(r[1]), "=r"(r[2]), "=r"(r[3]) : "r"(a));
}
__device__ __forceinline__ void ldsm_x4t(uint32_t* r, uint32_t a) {
    asm volatile("ldmatrix.sync.aligned.m8n8.x4.trans.shared.b16 {%0,%1,%2,%3}, [%4];"
                 : "=r"(r[0]), "=r"(r[1]), "=r"(r[2]), "=r"(r[3]) : "r"(a));
}
__device__ __forceinline__ void mma_f16(float* d, const uint32_t* a, const uint32_t* b) {
    asm volatile(
        "mma.sync.aligned.m16n8k16.row.col.f32.f16.f16.f32 "
        "{%0,%1,%2,%3}, {%4,%5,%6,%7}, {%8,%9}, {%0,%1,%2,%3};"
        : "+f"(d[0]), "+f"(d[1]), "+f"(d[2]), "+f"(d[3])
        : "r"(a[0]), "r"(a[1]), "r"(a[2]), "r"(a[3]), "r"(b[0]), "r"(b[1]));
}

__device__ __forceinline__ uint32_t pack_h2(__half a, __half b) {
    return (uint32_t)__half_as_ushort(a) | ((uint32_t)__half_as_ushort(b) << 16);
}

// ---------------- RoPE tables ----------------
__global__ void rope_init_kernel() {
    int idx = blockIdx.x * blockDim.x + threadIdx.x;
    if (idx >= LL * 32) return;
    int l = idx >> 5;
    int jp = idx & 31;
    float inv = 1.0f / powf(10000.0f, (float)(2 * jp) / 64.0f);
    float ang = (float)l * inv;
    g_cos[idx] = cosf(ang);
    g_sin[idx] = sinf(ang);
}

// ---------------- router ----------------
__global__ void router_kernel(const float* __restrict__ x,
                              const float* __restrict__ rw,
                              const float* __restrict__ rb,
                              float* __restrict__ probs_out,
                              int write_probs) {
    int b = blockIdx.x;
    __shared__ float mean[DD];
    __shared__ float logits[EE];

    for (int d = threadIdx.x; d < DD; d += blockDim.x) {
        const float* xp = x + (size_t)b * LL * DD + d;
        float s = 0.f;
        #pragma unroll 8
        for (int l = 0; l < LL; l++) s += xp[(size_t)l * DD];
        mean[d] = s * (1.0f / (float)LL);
    }
    __syncthreads();

    int w = threadIdx.x >> 5;
    int lane = threadIdx.x & 31;
    if (w < EE) {
        float s = 0.f;
        for (int d = lane; d < DD; d += 32) s += mean[d] * rw[d * EE + w];
        #pragma unroll
        for (int o = 16; o > 0; o >>= 1) s += __shfl_down_sync(0xffffffffu, s, o);
        if (lane == 0) logits[w] = s + rb[w];
    }
    __syncthreads();

    if (threadIdx.x == 0) {
        float m = logits[0]; int arg = 0;
        #pragma unroll
        for (int e = 1; e < EE; e++) if (logits[e] > m) { m = logits[e]; arg = e; }
        float p[EE], sum = 0.f;
        #pragma unroll
        for (int e = 0; e < EE; e++) { p[e] = expf(logits[e] - m); sum += p[e]; }
        if (write_probs) {
            float inv = 1.0f / sum;
            #pragma unroll
            for (int e = 0; e < EE; e++) probs_out[b * EE + e] = p[e] * inv;
        }
        g_routes[b] = arg;
    }
}

// ---------------- merged convert: X tiles (hi/lo) + W^T tiles (single fp16) ----------
__global__ void convert_kernel(const float* __restrict__ x,
                               const float* __restrict__ qw, const float* __restrict__ kw,
                               const float* __restrict__ vw, const float* __restrict__ ow) {
    __shared__ float sm[64][129];
    const int bid = blockIdx.x;
    const int tid = threadIdx.x;

    if (bid < 2048) {
        const int rt = bid >> 4, kc = bid & 15;
        const size_t tb = ((size_t)rt * 16 + kc) * 8192;
        char* dh = (char*)(g_xh + tb);
        char* dl = (char*)(g_xl + tb);
        #pragma unroll
        for (int i = 0; i < 4; i++) {
            int u = tid + i * 256;
            int r = u >> 3, k8 = u & 7;
            const float* p = x + ((size_t)(rt * 128 + r)) * DD + kc * 64 + k8 * 8;
            float4 a = *(const float4*)p;
            float4 b4 = *(const float4*)(p + 4);
            float xs[8] = {a.x, a.y, a.z, a.w, b4.x, b4.y, b4.z, b4.w};
            __half hi[8], lo[8];
            #pragma unroll
            for (int j = 0; j < 8; j++) {
                hi[j] = __float2half_rn(xs[j]);
                lo[j] = __float2half_rn(xs[j] - __half2float(hi[j]));
            }
            uint32_t off = (uint32_t)(u * 16);
            off ^= (off >> 3) & 0x70;
            *(uint4*)(dh + off) = make_uint4(pack_h2(hi[0], hi[1]), pack_h2(hi[2], hi[3]),
                                             pack_h2(hi[4], hi[5]), pack_h2(hi[6], hi[7]));
            *(uint4*)(dl + off) = make_uint4(pack_h2(lo[0], lo[1]), pack_h2(lo[2], lo[3]),
                                             pack_h2(lo[4], lo[5]), pack_h2(lo[6], lo[7]));
        }
    } else {
        const int idx = bid - 2048;
        const int kc = idx & 15, nt = (idx >> 4) & 7;
        const int e = (idx >> 7) & 7, mode = idx >> 10;
        const float* W = (mode == 0) ? qw : (mode == 1) ? kw : (mode == 2) ? vw : ow;
        const float* src = W + ((size_t)e * DD + kc * 64) * DD + nt * 128;

        #pragma unroll
        for (int i = 0; i < 8; i++) {
            int idx2 = tid + i * 256;
            int kr = idx2 >> 5, nc = (idx2 & 31) << 2;
            float4 v = *(const float4*)(src + (size_t)kr * DD + nc);
            sm[kr][nc] = v.x; sm[kr][nc + 1] = v.y; sm[kr][nc + 2] = v.z; sm[kr][nc + 3] = v.w;
        }
        __syncthreads();

        const size_t tb = (((size_t)(mode * 8 + e) * 8 + nt) * 16 + kc) * 8192;
        char* dw = (char*)(g_wt + tb);
        #pragma unroll
        for (int i = 0; i < 4; i++) {
            int u = tid + i * 256;
            int n = u >> 3, k8 = u & 7;
            __half h[8];
            #pragma unroll
            for (int j = 0; j < 8; j++) h[j] = __float2half_rn(sm[k8 * 8 + j][n]);
            uint32_t off = (uint32_t)(u * 16);
            off ^= (off >> 3) & 0x70;
            *(uint4*)(dw + off) = make_uint4(pack_h2(h[0], h[1]), pack_h2(h[2], h[3]),
                                             pack_h2(h[4], h[5]), pack_h2(h[6], h[7]));
        }
    }
}

// ---------------- HMMA GEMM: CTA 128x256, warp 64x64, bar-free 3-stage pipeline ------
// modes 0 (q), 1 (k): 2-term exact A-split; modes 2 (v), 3 (out): 1-term.
__global__ void __launch_bounds__(256, 1) hmma_gemm_kernel(float* __restrict__ out, int mode0) {
    extern __shared__ __align__(1024) char smem[];
    const uint32_t sb = smem_u32(smem);
    const int tid = threadIdx.x;
    const int lane = tid & 31, wid = tid >> 5;
    const int wm = wid >> 2, wn = wid & 3;            // 2(m) x 4(n)
    const int nt = blockIdx.x & 3;
    const int mode = mode0 + (blockIdx.x >> 2);
    const int mt = blockIdx.y, b = blockIdx.z;
    const int e = g_routes[b];
    const int nterm = (mode <= 1) ? 2 : 1;

    const uint32_t FULLB = sb;                        // 3 full mbarriers
    const uint32_t EMPTB = sb + 24;                   // 3 empty mbarriers (count 8)
    const uint32_t TILES = sb + 1024;                 // 3 stages x 64KB: Ah|Al|B0|B1

    if (tid == 0) {
        #pragma unroll
        for (int s = 0; s < 3; s++) { MBAR_INIT(FULLB + s * 8, 1); MBAR_INIT(EMPTB + s * 8, 8); }
    }
    __syncthreads();

    const __half* Ah = g_xh + ((size_t)(b * 4 + mt) * 16) * 8192;
    const __half* Al = g_xl + ((size_t)(b * 4 + mt) * 16) * 8192;
    const __half* B0 = g_wt + (((size_t)(mode * 8 + e) * 8 + 2 * nt) * 16) * 8192;
    const __half* B1 = B0 + (size_t)16 * 8192;

    auto issue = [&](int c) {
        int s = c % 3;
        uint32_t fb = FULLB + s * 8;
        uint32_t st = TILES + s * 65536;
        MBAR_EXPECT_TX(fb, nterm == 2 ? 65536 : 49152);
        bulk_g2s(st,         Ah + (size_t)c * 8192, 16384, fb);
        if (nterm == 2)
            bulk_g2s(st + 16384, Al + (size_t)c * 8192, 16384, fb);
        bulk_g2s(st + 32768, B0 + (size_t)c * 8192, 16384, fb);
        bulk_g2s(st + 49152, B1 + (size_t)c * 8192, 16384, fb);
    };
    if (tid == 0) { issue(0); issue(1); issue(2); }

    float acc[4][8][4];
    #pragma unroll
    for (int mf = 0; mf < 4; mf++)
        #pragma unroll
        for (int nf = 0; nf < 8; nf++)
            #pragma unroll
            for (int r = 0; r < 4; r++) acc[mf][nf][r] = 0.f;

    const uint32_t a_row  = (uint32_t)(wm * 64 + (lane & 15)) * 128;
    const uint32_t a_koff = (uint32_t)(lane >> 4) * 16;
    const uint32_t b_tile = 32768 + (uint32_t)(wn >> 1) * 16384;
    const uint32_t b_row  = (uint32_t)((wn & 1) * 64 + (lane & 7) + ((lane >> 4) << 3)) * 128;
    const uint32_t b_koff = (uint32_t)((lane >> 3) & 1) * 16;

    for (int c = 0; c < 16; c++) {
        const int s = c % 3;
        const uint32_t phase = (uint32_t)((c / 3) & 1);
        mbar_wait(FULLB + s * 8, phase);
        const uint32_t base = TILES + s * 65536;

        #pragma unroll
        for (int ks = 0; ks < 4; ks++) {
            const uint32_t k0b = (uint32_t)ks * 32;
            uint32_t ah[4][4], al[4][4];
            #pragma unroll
            for (int mf = 0; mf < 4; mf++) {
                uint32_t byt = a_row + (uint32_t)mf * 2048 + a_koff + k0b;
                uint32_t sw = byt ^ ((byt >> 3) & 0x70);
                ldsm_x4(ah[mf], base + sw);
                if (nterm == 2) ldsm_x4(al[mf], base + 16384 + sw);
            }
            uint32_t bf[4][4];
            #pragma unroll
            for (int p = 0; p < 4; p++) {
                uint32_t byt = b_row + (uint32_t)p * 2048 + b_koff + k0b;
                uint32_t sw = byt ^ ((byt >> 3) & 0x70);
                ldsm_x4(bf[p], base + b_tile + sw);
            }
            // all stage reads for this chunk done on last ks step -> release stage
            if (ks == 3 && lane == 0) MBAR_ARRIVE(EMPTB + s * 8);

            #pragma unroll
            for (int p = 0; p < 4; p++)
                #pragma unroll
                for (int mf = 0; mf < 4; mf++) {
                    mma_f16(acc[mf][2 * p],     ah[mf], &bf[p][0]);
                    mma_f16(acc[mf][2 * p + 1], ah[mf], &bf[p][2]);
                }
            if (nterm == 2) {
                #pragma unroll
                for (int p = 0; p < 4; p++)
                    #pragma unroll
                    for (int mf = 0; mf < 4; mf++) {
                        mma_f16(acc[mf][2 * p],     al[mf], &bf[p][0]);
                        mma_f16(acc[mf][2 * p + 1], al[mf], &bf[p][2]);
                    }
            }
        }
        // producer: refill this stage for chunk c+3 once all 8 warps released it
        if (tid == 0 && c + 3 < 16) {
            mbar_wait(EMPTB + s * 8, phase);
            issue(c + 3);
        }
    }

    // ---------------- epilogue ----------------
    const int l_base = mt * 128 + wm * 64 + (lane >> 2);
    const int tig = lane & 3;
    const int hglob = nt * 4 + wn;

    #pragma unroll
    for (int mf = 0; mf < 4; mf++) {
        #pragma unroll
        for (int rh = 0; rh < 2; rh++) {
            const int l = l_base + mf * 16 + 8 * rh;
            #pragma unroll
            for (int nf = 0; nf < 8; nf++) {
                const int d = 8 * nf + 2 * tig;
                float x0 = acc[mf][nf][2 * rh];
                float x1 = acc[mf][nf][2 * rh + 1];
                if (mode == 3) {
                    float2* dst = (float2*)(out + ((size_t)b * LL + l) * DD + hglob * 64 + d);
                    *dst = make_float2(x0, x1);
                } else {
                    float y0, y1;
                    if (mode == 2) { y0 = x0; y1 = x1; }
                    else {
                        const int p = d >> 1;
                        float cs = g_cos[l * 32 + p];
                        float sn = g_sin[l * 32 + p];
                        y0 = x0 * cs - x1 * sn;
                        y1 = x1 * cs + x0 * sn;
                    }
                    __half hb0 = __float2half_rn(y0);
                    __half hb1 = __float2half_rn(y1);
                    uint32_t off = (uint32_t)((((b * HH + hglob) * LL) + l) * 128 + d * 2);
                    uint32_t sw = off ^ ((off >> 3) & 0x70);
                    if (mode == 0) {
                        *(uint32_t*)((char*)g_qh + sw + 0) = pack_h2(hb0, hb1);
                        __half lb0 = __float2half_rn(y0 - __half2float(hb0));
                        __half lb1 = __float2half_rn(y1 - __half2float(hb1));
                        *(uint32_t*)((char*)g_ql + sw) = pack_h2(lb0, lb1);
                    } else {
                        char* dst = (mode == 1) ? (char*)g_kh : (char*)g_vh;
                        *(uint32_t*)(dst + sw) = pack_h2(hb0, hb1);
                    }
                }
            }
        }
    }
}

// ---------------- flash attention (fp16 2-term): 128 q-rows/CTA, 8 warps x 16 rows ---
__global__ void __launch_bounds__(256, 2) attn_kernel() {
    extern __shared__ __align__(1024) char smem[];
    const uint32_t sb = smem_u32(smem);
    const int tid = threadIdx.x, lane = tid & 31, w = tid >> 5;
    const int qt = 3 - blockIdx.x;       // long CTAs first
    const int bh = blockIdx.y;
    const int b = bh >> 4, h = bh & 15;
    const int g = lane >> 2, tig = lane & 3;

    const uint32_t QB = sb;
    const uint32_t FB = sb + 8;
    const uint32_t QT = sb + 1024;                 // Q hi 16KB | Q lo 16KB
    const uint32_t KV = sb + 1024 + 32768;         // 2 stages x (Kh 8KB | Vh 8KB)

    if (tid == 0) { MBAR_INIT(QB, 1); MBAR_INIT(FB, 1); MBAR_INIT(FB + 8, 1); }
    __syncthreads();

    const size_t bh_off = (size_t)bh * LL * HDIM;
    const __half* kh = g_kh + bh_off;
    const __half* vh = g_vh + bh_off;

    const int jmax = 2 * qt + 2;

    auto issue = [&](int jt) {
        int s = jt & 1;
        uint32_t fb = FB + s * 8;
        uint32_t st = KV + s * 16384;
        MBAR_EXPECT_TX(fb, 16384);
        bulk_g2s(st,        kh + (size_t)jt * 4096, 8192, fb);
        bulk_g2s(st + 8192, vh + (size_t)jt * 4096, 8192, fb);
    };
    if (tid == 0) {
        MBAR_EXPECT_TX(QB, 32768);
        bulk_g2s(QT,         g_qh + bh_off + (size_t)qt * 128 * 64, 16384, QB);
        bulk_g2s(QT + 16384, g_ql + bh_off + (size_t)qt * 128 * 64, 16384, QB);
        issue(0);
        issue(1);
    }

    float o[8][4];
    #pragma unroll
    for (int nf = 0; nf < 8; nf++)
        #pragma unroll
        for (int r = 0; r < 4; r++) o[nf][r] = 0.f;
    float m0 = -1e30f, m1 = -1e30f, l0 = 0.f, l1 = 0.f;

    const int rowmin = qt * 128 + w * 16;

    mbar_wait(QB, 0);

    for (int jt = 0; jt < jmax; jt++) {
        const int s = jt & 1;
        mbar_wait(FB + s * 8, (uint32_t)((jt >> 1) & 1));
        const uint32_t kb = KV + s * 16384;

        if (jt * 64 <= rowmin + 15) {
            float p[8][4];
            #pragma unroll
            for (int nf = 0; nf < 8; nf++)
                #pragma unroll
                for (int r = 0; r < 4; r++) p[nf][r] = 0.f;

            // S = Q K^T : Q exact 2-term (hi/lo), K single fp16
            #pragma unroll
            for (int ks = 0; ks < 4; ks++) {
                uint32_t qoff = (uint32_t)(w * 16 + (lane & 15)) * 128
                                + (uint32_t)(lane >> 4) * 16 + (uint32_t)ks * 32;
                uint32_t swq = qoff ^ ((qoff >> 3) & 0x70);
                uint32_t ah[4], al[4];
                ldsm_x4(ah, QT + swq);
                ldsm_x4(al, QT + 16384 + swq);
                #pragma unroll
                for (int nfp = 0; nfp < 4; nfp++) {
                    uint32_t koff = (uint32_t)(nfp * 16 + (lane & 7) + ((lane & 16) >> 1)) * 128
                                    + (uint32_t)ks * 32 + ((lane & 8) << 1);
                    uint32_t swk = koff ^ ((koff >> 3) & 0x70);
                    uint32_t kf[4];
                    ldsm_x4(kf, kb + swk);
                    mma_f16(p[2 * nfp],     ah, &kf[0]);
                    mma_f16(p[2 * nfp],     al, &kf[0]);
                    mma_f16(p[2 * nfp + 1], ah, &kf[2]);
                    mma_f16(p[2 * nfp + 1], al, &kf[2]);
                }
            }

            const bool need_mask = (jt * 64 + 63) > rowmin;
            #pragma unroll
            for (int nf = 0; nf < 8; nf++)
                #pragma unroll
                for (int r = 0; r < 4; r++) {
                    float v = p[nf][r] * 0.125f;
                    if (need_mask) {
                        int qr = rowmin + g + ((r & 2) << 2);
                        int kc = jt * 64 + 8 * nf + 2 * tig + (r & 1);
                        if (kc > qr) v = -1e30f;
                    }
                    p[nf][r] = v;
                }

            float mx0 = m0, mx1 = m1;
            #pragma unroll
            for (int nf = 0; nf < 8; nf++) {
                mx0 = fmaxf(mx0, fmaxf(p[nf][0], p[nf][1]));
                mx1 = fmaxf(mx1, fmaxf(p[nf][2], p[nf][3]));
            }
            mx0 = fmaxf(mx0, __shfl_xor_sync(0xffffffffu, mx0, 1));
            mx0 = fmaxf(mx0, __shfl_xor_sync(0xffffffffu, mx0, 2));
            mx1 = fmaxf(mx1, __shfl_xor_sync(0xffffffffu, mx1, 1));
            mx1 = fmaxf(mx1, __shfl_xor_sync(0xffffffffu, mx1, 2));
            float c0 = __expf(m0 - mx0), c1 = __expf(m1 - mx1);
            m0 = mx0; m1 = mx1;
            float s0 = 0.f, s1 = 0.f;
            #pragma unroll
            for (int nf = 0; nf < 8; nf++) {
                p[nf][0] = __expf(p[nf][0] - mx0); s0 += p[nf][0];
                p[nf][1] = __expf(p[nf][1] - mx0); s0 += p[nf][1];
                p[nf][2] = __expf(p[nf][2] - mx1); s1 += p[nf][2];
                p[nf][3] = __expf(p[nf][3] - mx1); s1 += p[nf][3];
            }
            s0 += __shfl_xor_sync(0xffffffffu, s0, 1);
            s0 += __shfl_xor_sync(0xffffffffu, s0, 2);
            s1 += __shfl_xor_sync(0xffffffffu, s1, 1);
            s1 += __shfl_xor_sync(0xffffffffu, s1, 2);
            l0 = l0 * c0 + s0;
            l1 = l1 * c1 + s1;
            #pragma unroll
            for (int nf = 0; nf < 8; nf++) {
                o[nf][0] *= c0; o[nf][1] *= c0;
                o[nf][2] *= c1; o[nf][3] *= c1;
            }

            // O += P V : P exact 2-term (hi/lo in regs), V single fp16
            #pragma unroll
            for (int j = 0; j < 4; j++) {
                uint32_t pah[4], pal[4];
                #pragma unroll
                for (int half = 0; half < 2; half++) {
                    const float* pf = p[2 * j + half];
                    __half h0 = __float2half_rn(pf[0]);
                    __half h1 = __float2half_rn(pf[1]);
                    __half h2 = __float2half_rn(pf[2]);
                    __half h3 = __float2half_rn(pf[3]);
                    pah[2 * half]     = pack_h2(h0, h1);
                    pah[2 * half + 1] = pack_h2(h2, h3);
                    pal[2 * half]     = pack_h2(__float2half_rn(pf[0] - __half2float(h0)),
                                                __float2half_rn(pf[1] - __half2float(h1)));
                    pal[2 * half + 1] = pack_h2(__float2half_rn(pf[2] - __half2float(h2)),
                                                __float2half_rn(pf[3] - __half2float(h3)));
                }
                #pragma unroll
                for (int nfp = 0; nfp < 4; nfp++) {
                    uint32_t voff = (uint32_t)(16 * j + (lane & 7) + (lane & 8)) * 128
                                    + (uint32_t)nfp * 32 + (lane & 16);
                    uint32_t swv = voff ^ ((voff >> 3) & 0x70);
                    uint32_t vf[4];
                    ldsm_x4t(vf, kb + 8192 + swv);
                    mma_f16(o[2 * nfp],     pah, &vf[0]);
                    mma_f16(o[2 * nfp],     pal, &vf[0]);
                    mma_f16(o[2 * nfp + 1], pah, &vf[2]);
                    mma_f16(o[2 * nfp + 1], pal, &vf[2]);
                }
            }
        }
        __syncthreads();
        if (tid == 0 && jt + 2 < jmax) issue(jt + 2);
    }

    // epilogue: O /= l; write AO as fp16 hi/lo swizzled tile (rt = b*4+qt, kc = h)
    const float i0 = 1.f / l0, i1 = 1.f / l1;
    const size_t tb = (((size_t)(b * 4 + qt) * 16) + h) * 16384;   // bytes
    char* dh = (char*)g_xh + tb;
    char* dl = (char*)g_xl + tb;
    #pragma unroll
    for (int nf = 0; nf < 8; nf++) {
        #pragma unroll
        for (int rh = 0; rh < 2; rh++) {
            float y0 = o[nf][2 * rh]     * (rh ? i1 : i0);
            float y1 = o[nf][2 * rh + 1] * (rh ? i1 : i0);
            __half hb0 = __float2half_rn(y0);
            __half hb1 = __float2half_rn(y1);
            __half lb0 = __float2half_rn(y0 - __half2float(hb0));
            __half lb1 = __float2half_rn(y1 - __half2float(hb1));
            uint32_t off = (uint32_t)((w * 16 + g + 8 * rh) * 128 + (8 * nf + 2 * tig) * 2);
            uint32_t sw = off ^ ((off >> 3) & 0x70);
            *(uint32_t*)(dh + sw) = pack_h2(hb0, hb1);
            *(uint32_t*)(dl + sw) = pack_h2(lb0, lb1);
        }
    }
}

// ---------------- launch ----------------
extern "C" void kernel_launch(void* const* d_in, const int* in_sizes, int n_in,
                              void* d_out, int out_size) {
    const float* x  = (const float*)d_in[0];
    const float* qw = (const float*)d_in[1];
    const float* kw = (const float*)d_in[2];
    const float* vw = (const float*)d_in[3];
    const float* ow = (const float*)d_in[4];
    const float* rw = (const float*)d_in[5];
    const float* rb = (const float*)d_in[6];
    float* out = (float*)d_out;

    const int GEMM_SMEM = 1024 + 3 * 65536;           // 197632
    cudaFuncSetAttribute(hmma_gemm_kernel, cudaFuncAttributeMaxDynamicSharedMemorySize, GEMM_SMEM);
    const int ATTN_SMEM = 1024 + 32768 + 2 * 16384;   // 66560
    cudaFuncSetAttribute(attn_kernel, cudaFuncAttributeMaxDynamicSharedMemorySize, ATTN_SMEM);

    rope_init_kernel<<<64, 256>>>();                                          // 0

    int write_probs = (out_size >= BB * LL * DD + BB * EE) ? 1 : 0;
    router_kernel<<<BB, 256>>>(x, rw, rb, out + (size_t)BB * LL * DD, write_probs); // 1

    convert_kernel<<<6144, 256>>>(x, qw, kw, vw, ow);                         // 2

    // fused Q/K/V projection (profiled: launch index 3)
    hmma_gemm_kernel<<<dim3(12, 4, BB), 256, GEMM_SMEM>>>(nullptr, 0);        // 3

    attn_kernel<<<dim3(4, BB * HH), 256, ATTN_SMEM>>>();                      // 4

    // out projection (AO tiles written directly by attention epilogue)
    hmma_gemm_kernel<<<dim3(4, 4, BB), 256, GEMM_SMEM>>>(out, 3);             // 5
}

// round 10
// speedup vs baseline: 4.1504x; 1.0917x over previous
#include <cuda_runtime.h>
#include <cuda_bf16.h>
#include <cuda_fp16.h>
#include <cstdint>
#include <math.h>

#define BB 32
#define LL 512
#define DD 1024
#define HH 16
#define HDIM 64
#define EE 8

// ---------------- scratch (device globals; no allocation allowed) ----------------
__device__ float g_cos[LL * 32];
__device__ float g_sin[LL * 32];
__device__ int   g_routes[BB];

// X/AO tiles: [rt(128)][kc(16)] each 128 rows x 64 cols fp16 (16KB), SW128-swizzled
__device__ __half g_xh[(size_t)16384 * 1024];
__device__ __half g_xl[(size_t)16384 * 1024];
// W^T tiles (single fp16): [mode(4)][e(8)][nt(8)][kc(16)] each 128(n) x 64(k), SW128
__device__ __half g_wt[(size_t)4 * 8 * 1024 * 1024];
// q fp16 hi/lo (A-side of S, exact split); k/v single fp16 (B-side)
__device__ __half g_qh[(size_t)BB * HH * LL * HDIM];
__device__ __half g_ql[(size_t)BB * HH * LL * HDIM];
__device__ __half g_kh[(size_t)BB * HH * LL * HDIM];
__device__ __half g_vh[(size_t)BB * HH * LL * HDIM];

// ---------------- PTX helpers ----------------
__device__ __forceinline__ uint32_t smem_u32(const void* p) {
    uint32_t a;
    asm("{ .reg .u64 t; cvta.to.shared.u64 t, %1; cvt.u32.u64 %0, t; }" : "=r"(a) : "l"(p));
    return a;
}

#define MBAR_INIT(a, n) \
    asm volatile("mbarrier.init.shared.b64 [%0], %1;" :: "r"(a), "r"((uint32_t)(n)) : "memory")
#define MBAR_EXPECT_TX(a, b) \
    asm volatile("mbarrier.arrive.expect_tx.shared.b64 _, [%0], %1;" :: "r"(a), "r"((uint32_t)(b)) : "memory")
#define MBAR_ARRIVE(a) \
    asm volatile("mbarrier.arrive.shared.b64 _, [%0];" :: "r"(a) : "memory")

__device__ __forceinline__ void mbar_wait(uint32_t mbar, uint32_t parity) {
    asm volatile(
        "{\n\t.reg .pred P;\n\t"
        "WL_%=:\n\t"
        "mbarrier.try_wait.parity.acquire.cta.shared::cta.b64 P, [%0], %1, 0x989680;\n\t"
        "@P bra.uni WD_%=;\n\t"
        "bra.uni WL_%=;\n\t"
        "WD_%=:\n\t}"
        :: "r"(mbar), "r"(parity) : "memory");
}

__device__ __forceinline__ void bulk_g2s(uint32_t dst, const void* src, uint32_t bytes, uint32_t mbar) {
    asm volatile(
        "cp.async.bulk.shared::cluster.global.mbarrier::complete_tx::bytes [%0], [%1], %2, [%3];"
        :: "r"(dst), "l"(src), "r"(bytes), "r"(mbar) : "memory");
}

__device__ __forceinline__ void ldsm_x4(uint32_t* r, uint32_t a) {
    asm volatile("ldmatrix.sync.aligned.m8n8.x4.shared.b16 {%0,%1,%2,%3}, [%4];"
                 : "=r"(r[0]), "=r"(r[1]), "=r"(r[2]), "=r"(r[3]) : "r"(a));
}
__device__ __forceinline__ void ldsm_x4t(uint32_t* r, uint32_t a) {
    asm volatile("ldmatrix.sync.aligned.m8n8.x4.trans.shared.b16 {%0,%1,%2,%3}, [%4];"
                 : "=r"(r[0]), "=r"(r[1]), "=r"(r[2]), "=r"(r[3]) : "r"(a));
}
__device__ __forceinline__ void mma_f16(float* d, const uint32_t* a, const uint32_t* b) {
    asm volatile(
        "mma.sync.aligned.m16n8k16.row.col.f32.f16.f16.f32 "
        "{%0,%1,%2,%3}, {%4,%5,%6,%7}, {%8,%9}, {%0,%1,%2,%3};"
        : "+f"(d[0]), "+f"(d[1]), "+f"(d[2]), "+f"(d[3])
        : "r"(a[0]), "r"(a[1]), "r"(a[2]), "r"(a[3]), "r"(b[0]), "r"(b[1]));
}

__device__ __forceinline__ uint32_t pack_h2(__half a, __half b) {
    return (uint32_t)__half_as_ushort(a) | ((uint32_t)__half_as_ushort(b) << 16);
}

// ---------------- RoPE tables ----------------
__global__ void rope_init_kernel() {
    int idx = blockIdx.x * blockDim.x + threadIdx.x;
    if (idx >= LL * 32) return;
    int l = idx >> 5;
    int jp = idx & 31;
    float inv = 1.0f / powf(10000.0f, (float)(2 * jp) / 64.0f);
    float ang = (float)l * inv;
    g_cos[idx] = cosf(ang);
    g_sin[idx] = sinf(ang);
}

// ---------------- router ----------------
__global__ void router_kernel(const float* __restrict__ x,
                              const float* __restrict__ rw,
                              const float* __restrict__ rb,
                              float* __restrict__ probs_out,
                              int write_probs) {
    int b = blockIdx.x;
    __shared__ float mean[DD];
    __shared__ float logits[EE];

    for (int d = threadIdx.x; d < DD; d += blockDim.x) {
        const float* xp = x + (size_t)b * LL * DD + d;
        float s = 0.f;
        #pragma unroll 8
        for (int l = 0; l < LL; l++) s += xp[(size_t)l * DD];
        mean[d] = s * (1.0f / (float)LL);
    }
    __syncthreads();

    int w = threadIdx.x >> 5;
    int lane = threadIdx.x & 31;
    if (w < EE) {
        float s = 0.f;
        for (int d = lane; d < DD; d += 32) s += mean[d] * rw[d * EE + w];
        #pragma unroll
        for (int o = 16; o > 0; o >>= 1) s += __shfl_down_sync(0xffffffffu, s, o);
        if (lane == 0) logits[w] = s + rb[w];
    }
    __syncthreads();

    if (threadIdx.x == 0) {
        float m = logits[0]; int arg = 0;
        #pragma unroll
        for (int e = 1; e < EE; e++) if (logits[e] > m) { m = logits[e]; arg = e; }
        float p[EE], sum = 0.f;
        #pragma unroll
        for (int e = 0; e < EE; e++) { p[e] = expf(logits[e] - m); sum += p[e]; }
        if (write_probs) {
            float inv = 1.0f / sum;
            #pragma unroll
            for (int e = 0; e < EE; e++) probs_out[b * EE + e] = p[e] * inv;
        }
        g_routes[b] = arg;
    }
}

// ---------------- merged convert: X tiles (hi/lo) + W^T tiles (single fp16) ----------
__global__ void convert_kernel(const float* __restrict__ x,
                               const float* __restrict__ qw, const float* __restrict__ kw,
                               const float* __restrict__ vw, const float* __restrict__ ow) {
    __shared__ float sm[64][129];
    const int bid = blockIdx.x;
    const int tid = threadIdx.x;

    if (bid < 2048) {
        const int rt = bid >> 4, kc = bid & 15;
        const size_t tb = ((size_t)rt * 16 + kc) * 8192;
        char* dh = (char*)(g_xh + tb);
        char* dl = (char*)(g_xl + tb);
        #pragma unroll
        for (int i = 0; i < 4; i++) {
            int u = tid + i * 256;
            int r = u >> 3, k8 = u & 7;
            const float* p = x + ((size_t)(rt * 128 + r)) * DD + kc * 64 + k8 * 8;
            float4 a = *(const float4*)p;
            float4 b4 = *(const float4*)(p + 4);
            float xs[8] = {a.x, a.y, a.z, a.w, b4.x, b4.y, b4.z, b4.w};
            __half hi[8], lo[8];
            #pragma unroll
            for (int j = 0; j < 8; j++) {
                hi[j] = __float2half_rn(xs[j]);
                lo[j] = __float2half_rn(xs[j] - __half2float(hi[j]));
            }
            uint32_t off = (uint32_t)(u * 16);
            off ^= (off >> 3) & 0x70;
            *(uint4*)(dh + off) = make_uint4(pack_h2(hi[0], hi[1]), pack_h2(hi[2], hi[3]),
                                             pack_h2(hi[4], hi[5]), pack_h2(hi[6], hi[7]));
            *(uint4*)(dl + off) = make_uint4(pack_h2(lo[0], lo[1]), pack_h2(lo[2], lo[3]),
                                             pack_h2(lo[4], lo[5]), pack_h2(lo[6], lo[7]));
        }
    } else {
        const int idx = bid - 2048;
        const int kc = idx & 15, nt = (idx >> 4) & 7;
        const int e = (idx >> 7) & 7, mode = idx >> 10;
        const float* W = (mode == 0) ? qw : (mode == 1) ? kw : (mode == 2) ? vw : ow;
        const float* src = W + ((size_t)e * DD + kc * 64) * DD + nt * 128;

        #pragma unroll
        for (int i = 0; i < 8; i++) {
            int idx2 = tid + i * 256;
            int kr = idx2 >> 5, nc = (idx2 & 31) << 2;
            float4 v = *(const float4*)(src + (size_t)kr * DD + nc);
            sm[kr][nc] = v.x; sm[kr][nc + 1] = v.y; sm[kr][nc + 2] = v.z; sm[kr][nc + 3] = v.w;
        }
        __syncthreads();

        const size_t tb = (((size_t)(mode * 8 + e) * 8 + nt) * 16 + kc) * 8192;
        char* dw = (char*)(g_wt + tb);
        #pragma unroll
        for (int i = 0; i < 4; i++) {
            int u = tid + i * 256;
            int n = u >> 3, k8 = u & 7;
            __half h[8];
            #pragma unroll
            for (int j = 0; j < 8; j++) h[j] = __float2half_rn(sm[k8 * 8 + j][n]);
            uint32_t off = (uint32_t)(u * 16);
            off ^= (off >> 3) & 0x70;
            *(uint4*)(dw + off) = make_uint4(pack_h2(h[0], h[1]), pack_h2(h[2], h[3]),
                                             pack_h2(h[4], h[5]), pack_h2(h[6], h[7]));
        }
    }
}

// ---------------- HMMA GEMM: CTA 128x256, warp 64x64, bar-free 3-stage pipeline ------
// mode 0 (q): 2-term exact A-split; modes 1 (k), 2 (v), 3 (out): 1-term.
__global__ void __launch_bounds__(256, 1) hmma_gemm_kernel(float* __restrict__ out, int mode0) {
    extern __shared__ __align__(1024) char smem[];
    const uint32_t sb = smem_u32(smem);
    const int tid = threadIdx.x;
    const int lane = tid & 31, wid = tid >> 5;
    const int wm = wid >> 2, wn = wid & 3;            // 2(m) x 4(n)
    const int nt = blockIdx.x & 3;
    const int mode = mode0 + (blockIdx.x >> 2);
    const int mt = blockIdx.y, b = blockIdx.z;
    const int e = g_routes[b];
    const int nterm = (mode == 0) ? 2 : 1;

    const uint32_t FULLB = sb;                        // 3 full mbarriers
    const uint32_t EMPTB = sb + 24;                   // 3 empty mbarriers (count 8)
    const uint32_t TILES = sb + 1024;                 // 3 stages x 64KB: Ah|Al|B0|B1

    if (tid == 0) {
        #pragma unroll
        for (int s = 0; s < 3; s++) { MBAR_INIT(FULLB + s * 8, 1); MBAR_INIT(EMPTB + s * 8, 8); }
    }
    __syncthreads();

    const __half* Ah = g_xh + ((size_t)(b * 4 + mt) * 16) * 8192;
    const __half* Al = g_xl + ((size_t)(b * 4 + mt) * 16) * 8192;
    const __half* B0 = g_wt + (((size_t)(mode * 8 + e) * 8 + 2 * nt) * 16) * 8192;
    const __half* B1 = B0 + (size_t)16 * 8192;

    auto issue = [&](int c) {
        int s = c % 3;
        uint32_t fb = FULLB + s * 8;
        uint32_t st = TILES + s * 65536;
        MBAR_EXPECT_TX(fb, nterm == 2 ? 65536 : 49152);
        bulk_g2s(st,         Ah + (size_t)c * 8192, 16384, fb);
        if (nterm == 2)
            bulk_g2s(st + 16384, Al + (size_t)c * 8192, 16384, fb);
        bulk_g2s(st + 32768, B0 + (size_t)c * 8192, 16384, fb);
        bulk_g2s(st + 49152, B1 + (size_t)c * 8192, 16384, fb);
    };
    if (tid == 0) { issue(0); issue(1); issue(2); }

    float acc[4][8][4];
    #pragma unroll
    for (int mf = 0; mf < 4; mf++)
        #pragma unroll
        for (int nf = 0; nf < 8; nf++)
            #pragma unroll
            for (int r = 0; r < 4; r++) acc[mf][nf][r] = 0.f;

    const uint32_t a_row  = (uint32_t)(wm * 64 + (lane & 15)) * 128;
    const uint32_t a_koff = (uint32_t)(lane >> 4) * 16;
    const uint32_t b_tile = 32768 + (uint32_t)(wn >> 1) * 16384;
    const uint32_t b_row  = (uint32_t)((wn & 1) * 64 + (lane & 7) + ((lane >> 4) << 3)) * 128;
    const uint32_t b_koff = (uint32_t)((lane >> 3) & 1) * 16;

    for (int c = 0; c < 16; c++) {
        const int s = c % 3;
        const uint32_t phase = (uint32_t)((c / 3) & 1);
        mbar_wait(FULLB + s * 8, phase);
        const uint32_t base = TILES + s * 65536;

        #pragma unroll
        for (int ks = 0; ks < 4; ks++) {
            const uint32_t k0b = (uint32_t)ks * 32;
            uint32_t ah[4][4], al[4][4];
            #pragma unroll
            for (int mf = 0; mf < 4; mf++) {
                uint32_t byt = a_row + (uint32_t)mf * 2048 + a_koff + k0b;
                uint32_t sw = byt ^ ((byt >> 3) & 0x70);
                ldsm_x4(ah[mf], base + sw);
                if (nterm == 2) ldsm_x4(al[mf], base + 16384 + sw);
            }
            uint32_t bf[4][4];
            #pragma unroll
            for (int p = 0; p < 4; p++) {
                uint32_t byt = b_row + (uint32_t)p * 2048 + b_koff + k0b;
                uint32_t sw = byt ^ ((byt >> 3) & 0x70);
                ldsm_x4(bf[p], base + b_tile + sw);
            }
            if (ks == 3 && lane == 0) MBAR_ARRIVE(EMPTB + s * 8);

            #pragma unroll
            for (int p = 0; p < 4; p++)
                #pragma unroll
                for (int mf = 0; mf < 4; mf++) {
                    mma_f16(acc[mf][2 * p],     ah[mf], &bf[p][0]);
                    mma_f16(acc[mf][2 * p + 1], ah[mf], &bf[p][2]);
                }
            if (nterm == 2) {
                #pragma unroll
                for (int p = 0; p < 4; p++)
                    #pragma unroll
                    for (int mf = 0; mf < 4; mf++) {
                        mma_f16(acc[mf][2 * p],     al[mf], &bf[p][0]);
                        mma_f16(acc[mf][2 * p + 1], al[mf], &bf[p][2]);
                    }
            }
        }
        if (tid == 0 && c + 3 < 16) {
            mbar_wait(EMPTB + s * 8, phase);
            issue(c + 3);
        }
    }

    // ---------------- epilogue ----------------
    const int l_base = mt * 128 + wm * 64 + (lane >> 2);
    const int tig = lane & 3;
    const int hglob = nt * 4 + wn;

    #pragma unroll
    for (int mf = 0; mf < 4; mf++) {
        #pragma unroll
        for (int rh = 0; rh < 2; rh++) {
            const int l = l_base + mf * 16 + 8 * rh;
            #pragma unroll
            for (int nf = 0; nf < 8; nf++) {
                const int d = 8 * nf + 2 * tig;
                float x0 = acc[mf][nf][2 * rh];
                float x1 = acc[mf][nf][2 * rh + 1];
                if (mode == 3) {
                    float2* dst = (float2*)(out + ((size_t)b * LL + l) * DD + hglob * 64 + d);
                    *dst = make_float2(x0, x1);
                } else {
                    float y0, y1;
                    if (mode == 2) { y0 = x0; y1 = x1; }
                    else {
                        const int p = d >> 1;
                        float cs = g_cos[l * 32 + p];
                        float sn = g_sin[l * 32 + p];
                        y0 = x0 * cs - x1 * sn;
                        y1 = x1 * cs + x0 * sn;
                    }
                    __half hb0 = __float2half_rn(y0);
                    __half hb1 = __float2half_rn(y1);
                    uint32_t off = (uint32_t)((((b * HH + hglob) * LL) + l) * 128 + d * 2);
                    uint32_t sw = off ^ ((off >> 3) & 0x70);
                    if (mode == 0) {
                        *(uint32_t*)((char*)g_qh + sw) = pack_h2(hb0, hb1);
                        __half lb0 = __float2half_rn(y0 - __half2float(hb0));
                        __half lb1 = __float2half_rn(y1 - __half2float(hb1));
                        *(uint32_t*)((char*)g_ql + sw) = pack_h2(lb0, lb1);
                    } else {
                        char* dst = (mode == 1) ? (char*)g_kh : (char*)g_vh;
                        *(uint32_t*)(dst + sw) = pack_h2(hb0, hb1);
                    }
                }
            }
        }
    }
}

// ---------------- flash attention (fp16): 128 q-rows/CTA, 8 warps x 16 rows ----------
// S: Q 2-term (exact) x K 1-term; PV: P 1-term x V 1-term.
__global__ void __launch_bounds__(256, 2) attn_kernel() {
    extern __shared__ __align__(1024) char smem[];
    const uint32_t sb = smem_u32(smem);
    const int tid = threadIdx.x, lane = tid & 31, w = tid >> 5;
    const int qt = 3 - blockIdx.x;       // long CTAs first
    const int bh = blockIdx.y;
    const int b = bh >> 4, h = bh & 15;
    const int g = lane >> 2, tig = lane & 3;

    const uint32_t QB = sb;
    const uint32_t FB = sb + 8;
    const uint32_t QT = sb + 1024;                 // Q hi 16KB | Q lo 16KB
    const uint32_t KV = sb + 1024 + 32768;         // 2 stages x (Kh 8KB | Vh 8KB)

    if (tid == 0) { MBAR_INIT(QB, 1); MBAR_INIT(FB, 1); MBAR_INIT(FB + 8, 1); }
    __syncthreads();

    const size_t bh_off = (size_t)bh * LL * HDIM;
    const __half* kh = g_kh + bh_off;
    const __half* vh = g_vh + bh_off;

    const int jmax = 2 * qt + 2;

    auto issue = [&](int jt) {
        int s = jt & 1;
        uint32_t fb = FB + s * 8;
        uint32_t st = KV + s * 16384;
        MBAR_EXPECT_TX(fb, 16384);
        bulk_g2s(st,        kh + (size_t)jt * 4096, 8192, fb);
        bulk_g2s(st + 8192, vh + (size_t)jt * 4096, 8192, fb);
    };
    if (tid == 0) {
        MBAR_EXPECT_TX(QB, 32768);
        bulk_g2s(QT,         g_qh + bh_off + (size_t)qt * 128 * 64, 16384, QB);
        bulk_g2s(QT + 16384, g_ql + bh_off + (size_t)qt * 128 * 64, 16384, QB);
        issue(0);
        issue(1);
    }

    float o[8][4];
    #pragma unroll
    for (int nf = 0; nf < 8; nf++)
        #pragma unroll
        for (int r = 0; r < 4; r++) o[nf][r] = 0.f;
    float m0 = -1e30f, m1 = -1e30f, l0 = 0.f, l1 = 0.f;

    const int rowmin = qt * 128 + w * 16;

    mbar_wait(QB, 0);

    for (int jt = 0; jt < jmax; jt++) {
        const int s = jt & 1;
        mbar_wait(FB + s * 8, (uint32_t)((jt >> 1) & 1));
        const uint32_t kb = KV + s * 16384;

        if (jt * 64 <= rowmin + 15) {
            float p[8][4];
            #pragma unroll
            for (int nf = 0; nf < 8; nf++)
                #pragma unroll
                for (int r = 0; r < 4; r++) p[nf][r] = 0.f;

            // S = Q K^T : Q exact 2-term (hi/lo), K single fp16
            #pragma unroll
            for (int ks = 0; ks < 4; ks++) {
                uint32_t qoff = (uint32_t)(w * 16 + (lane & 15)) * 128
                                + (uint32_t)(lane >> 4) * 16 + (uint32_t)ks * 32;
                uint32_t swq = qoff ^ ((qoff >> 3) & 0x70);
                uint32_t ah[4], al[4];
                ldsm_x4(ah, QT + swq);
                ldsm_x4(al, QT + 16384 + swq);
                #pragma unroll
                for (int nfp = 0; nfp < 4; nfp++) {
                    uint32_t koff = (uint32_t)(nfp * 16 + (lane & 7) + ((lane & 16) >> 1)) * 128
                                    + (uint32_t)ks * 32 + ((lane & 8) << 1);
                    uint32_t swk = koff ^ ((koff >> 3) & 0x70);
                    uint32_t kf[4];
                    ldsm_x4(kf, kb + swk);
                    mma_f16(p[2 * nfp],     ah, &kf[0]);
                    mma_f16(p[2 * nfp],     al, &kf[0]);
                    mma_f16(p[2 * nfp + 1], ah, &kf[2]);
                    mma_f16(p[2 * nfp + 1], al, &kf[2]);
                }
            }

            const bool need_mask = (jt * 64 + 63) > rowmin;
            #pragma unroll
            for (int nf = 0; nf < 8; nf++)
                #pragma unroll
                for (int r = 0; r < 4; r++) {
                    float v = p[nf][r] * 0.125f;
                    if (need_mask) {
                        int qr = rowmin + g + ((r & 2) << 2);
                        int kc = jt * 64 + 8 * nf + 2 * tig + (r & 1);
                        if (kc > qr) v = -1e30f;
                    }
                    p[nf][r] = v;
                }

            float mx0 = m0, mx1 = m1;
            #pragma unroll
            for (int nf = 0; nf < 8; nf++) {
                mx0 = fmaxf(mx0, fmaxf(p[nf][0], p[nf][1]));
                mx1 = fmaxf(mx1, fmaxf(p[nf][2], p[nf][3]));
            }
            mx0 = fmaxf(mx0, __shfl_xor_sync(0xffffffffu, mx0, 1));
            mx0 = fmaxf(mx0, __shfl_xor_sync(0xffffffffu, mx0, 2));
            mx1 = fmaxf(mx1, __shfl_xor_sync(0xffffffffu, mx1, 1));
            mx1 = fmaxf(mx1, __shfl_xor_sync(0xffffffffu, mx1, 2));
            float c0 = __expf(m0 - mx0), c1 = __expf(m1 - mx1);
            m0 = mx0; m1 = mx1;
            float s0 = 0.f, s1 = 0.f;
            #pragma unroll
            for (int nf = 0; nf < 8; nf++) {
                p[nf][0] = __expf(p[nf][0] - mx0); s0 += p[nf][0];
                p[nf][1] = __expf(p[nf][1] - mx0); s0 += p[nf][1];
                p[nf][2] = __expf(p[nf][2] - mx1); s1 += p[nf][2];
                p[nf][3] = __expf(p[nf][3] - mx1); s1 += p[nf][3];
            }
            s0 += __shfl_xor_sync(0xffffffffu, s0, 1);
            s0 += __shfl_xor_sync(0xffffffffu, s0, 2);
            s1 += __shfl_xor_sync(0xffffffffu, s1, 1);
            s1 += __shfl_xor_sync(0xffffffffu, s1, 2);
            l0 = l0 * c0 + s0;
            l1 = l1 * c1 + s1;
            #pragma unroll
            for (int nf = 0; nf < 8; nf++) {
                o[nf][0] *= c0; o[nf][1] *= c0;
                o[nf][2] *= c1; o[nf][3] *= c1;
            }

            // O += P V : P single fp16 (positive weights; normalization cancels bias)
            #pragma unroll
            for (int j = 0; j < 4; j++) {
                uint32_t pah[4];
                #pragma unroll
                for (int half = 0; half < 2; half++) {
                    const float* pf = p[2 * j + half];
                    pah[2 * half]     = pack_h2(__float2half_rn(pf[0]), __float2half_rn(pf[1]));
                    pah[2 * half + 1] = pack_h2(__float2half_rn(pf[2]), __float2half_rn(pf[3]));
                }
                #pragma unroll
                for (int nfp = 0; nfp < 4; nfp++) {
                    uint32_t voff = (uint32_t)(16 * j + (lane & 7) + (lane & 8)) * 128
                                    + (uint32_t)nfp * 32 + (lane & 16);
                    uint32_t swv = voff ^ ((voff >> 3) & 0x70);
                    uint32_t vf[4];
                    ldsm_x4t(vf, kb + 8192 + swv);
                    mma_f16(o[2 * nfp],     pah, &vf[0]);
                    mma_f16(o[2 * nfp + 1], pah, &vf[2]);
                }
            }
        }
        __syncthreads();
        if (tid == 0 && jt + 2 < jmax) issue(jt + 2);
    }

    // epilogue: O /= l; write AO as fp16 hi/lo swizzled tile (rt = b*4+qt, kc = h)
    const float i0 = 1.f / l0, i1 = 1.f / l1;
    const size_t tb = (((size_t)(b * 4 + qt) * 16) + h) * 16384;   // bytes
    char* dh = (char*)g_xh + tb;
    char* dl = (char*)g_xl + tb;
    #pragma unroll
    for (int nf = 0; nf < 8; nf++) {
        #pragma unroll
        for (int rh = 0; rh < 2; rh++) {
            float y0 = o[nf][2 * rh]     * (rh ? i1 : i0);
            float y1 = o[nf][2 * rh + 1] * (rh ? i1 : i0);
            __half hb0 = __float2half_rn(y0);
            __half hb1 = __float2half_rn(y1);
            __half lb0 = __float2half_rn(y0 - __half2float(hb0));
            __half lb1 = __float2half_rn(y1 - __half2float(hb1));
            uint32_t off = (uint32_t)((w * 16 + g + 8 * rh) * 128 + (8 * nf + 2 * tig) * 2);
            uint32_t sw = off ^ ((off >> 3) & 0x70);
            *(uint32_t*)(dh + sw) = pack_h2(hb0, hb1);
            *(uint32_t*)(dl + sw) = pack_h2(lb0, lb1);
        }
    }
}

// ---------------- launch ----------------
extern "C" void kernel_launch(void* const* d_in, const int* in_sizes, int n_in,
                              void* d_out, int out_size) {
    const float* x  = (const float*)d_in[0];
    const float* qw = (const float*)d_in[1];
    const float* kw = (const float*)d_in[2];
    const float* vw = (const float*)d_in[3];
    const float* ow = (const float*)d_in[4];
    const float* rw = (const float*)d_in[5];
    const float* rb = (const float*)d_in[6];
    float* out = (float*)d_out;

    const int GEMM_SMEM = 1024 + 3 * 65536;           // 197632
    cudaFuncSetAttribute(hmma_gemm_kernel, cudaFuncAttributeMaxDynamicSharedMemorySize, GEMM_SMEM);
    const int ATTN_SMEM = 1024 + 32768 + 2 * 16384;   // 66560
    cudaFuncSetAttribute(attn_kernel, cudaFuncAttributeMaxDynamicSharedMemorySize, ATTN_SMEM);

    rope_init_kernel<<<64, 256>>>();                                          // 0

    int write_probs = (out_size >= BB * LL * DD + BB * EE) ? 1 : 0;
    router_kernel<<<BB, 256>>>(x, rw, rb, out + (size_t)BB * LL * DD, write_probs); // 1

    convert_kernel<<<6144, 256>>>(x, qw, kw, vw, ow);                         // 2

    // fused Q/K/V projection (profiled: launch index 3)
    hmma_gemm_kernel<<<dim3(12, 4, BB), 256, GEMM_SMEM>>>(nullptr, 0);        // 3

    attn_kernel<<<dim3(4, BB * HH), 256, ATTN_SMEM>>>();                      // 4

    // out projection (AO tiles written directly by attention epilogue)
    hmma_gemm_kernel<<<dim3(4, 4, BB), 256, GEMM_SMEM>>>(out, 3);             // 5
}

// round 11
// speedup vs baseline: 5.0332x; 1.2127x over previous
#include <cuda_runtime.h>
#include <cuda_bf16.h>
#include <cuda_fp16.h>
#include <cstdint>
#include <math.h>

#define BB 32
#define LL 512
#define DD 1024
#define HH 16
#define HDIM 64
#define EE 8

// ---------------- scratch (device globals; no allocation allowed) ----------------
__device__ float g_cos[LL * 32];
__device__ float g_sin[LL * 32];
__device__ int   g_routes[BB];

// X/AO tiles (single fp16): [rt(128)][kc(16)] each 128 rows x 64 cols (16KB), SW128
__device__ __half g_xh[(size_t)16384 * 1024];
// W^T tiles (single fp16): [mode(4)][e(8)][nt(8)][kc(16)] each 128(n) x 64(k), SW128
__device__ __half g_wt[(size_t)4 * 8 * 1024 * 1024];
// q/k/v single fp16: [B*H][512][64], SW128-swizzled 128B rows
__device__ __half g_qh[(size_t)BB * HH * LL * HDIM];
__device__ __half g_kh[(size_t)BB * HH * LL * HDIM];
__device__ __half g_vh[(size_t)BB * HH * LL * HDIM];

// ---------------- PTX helpers ----------------
__device__ __forceinline__ uint32_t smem_u32(const void* p) {
    uint32_t a;
    asm("{ .reg .u64 t; cvta.to.shared.u64 t, %1; cvt.u32.u64 %0, t; }" : "=r"(a) : "l"(p));
    return a;
}

#define MBAR_INIT(a, n) \
    asm volatile("mbarrier.init.shared.b64 [%0], %1;" :: "r"(a), "r"((uint32_t)(n)) : "memory")
#define MBAR_EXPECT_TX(a, b) \
    asm volatile("mbarrier.arrive.expect_tx.shared.b64 _, [%0], %1;" :: "r"(a), "r"((uint32_t)(b)) : "memory")
#define MBAR_ARRIVE(a) \
    asm volatile("mbarrier.arrive.shared.b64 _, [%0];" :: "r"(a) : "memory")

__device__ __forceinline__ void mbar_wait(uint32_t mbar, uint32_t parity) {
    asm volatile(
        "{\n\t.reg .pred P;\n\t"
        "WL_%=:\n\t"
        "mbarrier.try_wait.parity.acquire.cta.shared::cta.b64 P, [%0], %1, 0x989680;\n\t"
        "@P bra.uni WD_%=;\n\t"
        "bra.uni WL_%=;\n\t"
        "WD_%=:\n\t}"
        :: "r"(mbar), "r"(parity) : "memory");
}

__device__ __forceinline__ void bulk_g2s(uint32_t dst, const void* src, uint32_t bytes, uint32_t mbar) {
    asm volatile(
        "cp.async.bulk.shared::cluster.global.mbarrier::complete_tx::bytes [%0], [%1], %2, [%3];"
        :: "r"(dst), "l"(src), "r"(bytes), "r"(mbar) : "memory");
}

__device__ __forceinline__ void ldsm_x4(uint32_t* r, uint32_t a) {
    asm volatile("ldmatrix.sync.aligned.m8n8.x4.shared.b16 {%0,%1,%2,%3}, [%4];"
                 : "=r"(r[0]), "=r"(r[1]), "=r"(r[2]), "=r"(r[3]) : "r"(a));
}
__device__ __forceinline__ void ldsm_x4t(uint32_t* r, uint32_t a) {
    asm volatile("ldmatrix.sync.aligned.m8n8.x4.trans.shared.b16 {%0,%1,%2,%3}, [%4];"
                 : "=r"(r[0]), "=r"(r[1]), "=r"(r[2]), "=r"(r[3]) : "r"(a));
}
__device__ __forceinline__ void mma_f16(float* d, const uint32_t* a, const uint32_t* b) {
    asm volatile(
        "mma.sync.aligned.m16n8k16.row.col.f32.f16.f16.f32 "
        "{%0,%1,%2,%3}, {%4,%5,%6,%7}, {%8,%9}, {%0,%1,%2,%3};"
        : "+f"(d[0]), "+f"(d[1]), "+f"(d[2]), "+f"(d[3])
        : "r"(a[0]), "r"(a[1]), "r"(a[2]), "r"(a[3]), "r"(b[0]), "r"(b[1]));
}

__device__ __forceinline__ uint32_t pack_h2(__half a, __half b) {
    return (uint32_t)__half_as_ushort(a) | ((uint32_t)__half_as_ushort(b) << 16);
}

// ---------------- RoPE tables ----------------
__global__ void rope_init_kernel() {
    int idx = blockIdx.x * blockDim.x + threadIdx.x;
    if (idx >= LL * 32) return;
    int l = idx >> 5;
    int jp = idx & 31;
    float inv = 1.0f / powf(10000.0f, (float)(2 * jp) / 64.0f);
    float ang = (float)l * inv;
    g_cos[idx] = cosf(ang);
    g_sin[idx] = sinf(ang);
}

// ---------------- router ----------------
__global__ void router_kernel(const float* __restrict__ x,
                              const float* __restrict__ rw,
                              const float* __restrict__ rb,
                              float* __restrict__ probs_out,
                              int write_probs) {
    int b = blockIdx.x;
    __shared__ float mean[DD];
    __shared__ float logits[EE];

    for (int d = threadIdx.x; d < DD; d += blockDim.x) {
        const float* xp = x + (size_t)b * LL * DD + d;
        float s = 0.f;
        #pragma unroll 8
        for (int l = 0; l < LL; l++) s += xp[(size_t)l * DD];
        mean[d] = s * (1.0f / (float)LL);
    }
    __syncthreads();

    int w = threadIdx.x >> 5;
    int lane = threadIdx.x & 31;
    if (w < EE) {
        float s = 0.f;
        for (int d = lane; d < DD; d += 32) s += mean[d] * rw[d * EE + w];
        #pragma unroll
        for (int o = 16; o > 0; o >>= 1) s += __shfl_down_sync(0xffffffffu, s, o);
        if (lane == 0) logits[w] = s + rb[w];
    }
    __syncthreads();

    if (threadIdx.x == 0) {
        float m = logits[0]; int arg = 0;
        #pragma unroll
        for (int e = 1; e < EE; e++) if (logits[e] > m) { m = logits[e]; arg = e; }
        float p[EE], sum = 0.f;
        #pragma unroll
        for (int e = 0; e < EE; e++) { p[e] = expf(logits[e] - m); sum += p[e]; }
        if (write_probs) {
            float inv = 1.0f / sum;
            #pragma unroll
            for (int e = 0; e < EE; e++) probs_out[b * EE + e] = p[e] * inv;
        }
        g_routes[b] = arg;
    }
}

// ---------------- merged convert: X tiles + W^T tiles (single fp16) ------------------
__global__ void convert_kernel(const float* __restrict__ x,
                               const float* __restrict__ qw, const float* __restrict__ kw,
                               const float* __restrict__ vw, const float* __restrict__ ow) {
    __shared__ float sm[64][129];
    const int bid = blockIdx.x;
    const int tid = threadIdx.x;

    if (bid < 2048) {
        const int rt = bid >> 4, kc = bid & 15;
        const size_t tb = ((size_t)rt * 16 + kc) * 8192;
        char* dh = (char*)(g_xh + tb);
        #pragma unroll
        for (int i = 0; i < 4; i++) {
            int u = tid + i * 256;
            int r = u >> 3, k8 = u & 7;
            const float* p = x + ((size_t)(rt * 128 + r)) * DD + kc * 64 + k8 * 8;
            float4 a = *(const float4*)p;
            float4 b4 = *(const float4*)(p + 4);
            uint32_t off = (uint32_t)(u * 16);
            off ^= (off >> 3) & 0x70;
            *(uint4*)(dh + off) = make_uint4(
                pack_h2(__float2half_rn(a.x),  __float2half_rn(a.y)),
                pack_h2(__float2half_rn(a.z),  __float2half_rn(a.w)),
                pack_h2(__float2half_rn(b4.x), __float2half_rn(b4.y)),
                pack_h2(__float2half_rn(b4.z), __float2half_rn(b4.w)));
        }
    } else {
        const int idx = bid - 2048;
        const int kc = idx & 15, nt = (idx >> 4) & 7;
        const int e = (idx >> 7) & 7, mode = idx >> 10;
        const float* W = (mode == 0) ? qw : (mode == 1) ? kw : (mode == 2) ? vw : ow;
        const float* src = W + ((size_t)e * DD + kc * 64) * DD + nt * 128;

        #pragma unroll
        for (int i = 0; i < 8; i++) {
            int idx2 = tid + i * 256;
            int kr = idx2 >> 5, nc = (idx2 & 31) << 2;
            float4 v = *(const float4*)(src + (size_t)kr * DD + nc);
            sm[kr][nc] = v.x; sm[kr][nc + 1] = v.y; sm[kr][nc + 2] = v.z; sm[kr][nc + 3] = v.w;
        }
        __syncthreads();

        const size_t tb = (((size_t)(mode * 8 + e) * 8 + nt) * 16 + kc) * 8192;
        char* dw = (char*)(g_wt + tb);
        #pragma unroll
        for (int i = 0; i < 4; i++) {
            int u = tid + i * 256;
            int n = u >> 3, k8 = u & 7;
            __half h[8];
            #pragma unroll
            for (int j = 0; j < 8; j++) h[j] = __float2half_rn(sm[k8 * 8 + j][n]);
            uint32_t off = (uint32_t)(u * 16);
            off ^= (off >> 3) & 0x70;
            *(uint4*)(dw + off) = make_uint4(pack_h2(h[0], h[1]), pack_h2(h[2], h[3]),
                                             pack_h2(h[4], h[5]), pack_h2(h[6], h[7]));
        }
    }
}

// ---------------- HMMA GEMM: CTA 128x256, warp 64x64, 1-term, 4-stage pipeline -------
__global__ void __launch_bounds__(256, 1) hmma_gemm_kernel(float* __restrict__ out, int mode0) {
    extern __shared__ __align__(1024) char smem[];
    const uint32_t sb = smem_u32(smem);
    const int tid = threadIdx.x;
    const int lane = tid & 31, wid = tid >> 5;
    const int wm = wid >> 2, wn = wid & 3;            // 2(m) x 4(n)
    const int nt = blockIdx.x & 3;
    const int mode = mode0 + (blockIdx.x >> 2);
    const int mt = blockIdx.y, b = blockIdx.z;
    const int e = g_routes[b];

    const uint32_t FULLB = sb;                        // 4 full mbarriers
    const uint32_t EMPTB = sb + 32;                   // 4 empty mbarriers (count 8)
    const uint32_t TILES = sb + 1024;                 // 4 stages x 48KB: A|B0|B1

    if (tid == 0) {
        #pragma unroll
        for (int s = 0; s < 4; s++) { MBAR_INIT(FULLB + s * 8, 1); MBAR_INIT(EMPTB + s * 8, 8); }
    }
    __syncthreads();

    const __half* Ah = g_xh + ((size_t)(b * 4 + mt) * 16) * 8192;
    const __half* B0 = g_wt + (((size_t)(mode * 8 + e) * 8 + 2 * nt) * 16) * 8192;
    const __half* B1 = B0 + (size_t)16 * 8192;

    auto issue = [&](int c) {
        int s = c & 3;
        uint32_t fb = FULLB + s * 8;
        uint32_t st = TILES + s * 49152;
        MBAR_EXPECT_TX(fb, 49152);
        bulk_g2s(st,         Ah + (size_t)c * 8192, 16384, fb);
        bulk_g2s(st + 16384, B0 + (size_t)c * 8192, 16384, fb);
        bulk_g2s(st + 32768, B1 + (size_t)c * 8192, 16384, fb);
    };
    if (tid == 0) { issue(0); issue(1); issue(2); issue(3); }

    float acc[4][8][4];
    #pragma unroll
    for (int mf = 0; mf < 4; mf++)
        #pragma unroll
        for (int nf = 0; nf < 8; nf++)
            #pragma unroll
            for (int r = 0; r < 4; r++) acc[mf][nf][r] = 0.f;

    const uint32_t a_row  = (uint32_t)(wm * 64 + (lane & 15)) * 128;
    const uint32_t a_koff = (uint32_t)(lane >> 4) * 16;
    const uint32_t b_tile = 16384 + (uint32_t)(wn >> 1) * 16384;
    const uint32_t b_row  = (uint32_t)((wn & 1) * 64 + (lane & 7) + ((lane >> 4) << 3)) * 128;
    const uint32_t b_koff = (uint32_t)((lane >> 3) & 1) * 16;

    for (int c = 0; c < 16; c++) {
        const int s = c & 3;
        const uint32_t phase = (uint32_t)((c >> 2) & 1);
        mbar_wait(FULLB + s * 8, phase);
        const uint32_t base = TILES + s * 49152;

        #pragma unroll
        for (int ks = 0; ks < 4; ks++) {
            const uint32_t k0b = (uint32_t)ks * 32;
            uint32_t ah[4][4];
            #pragma unroll
            for (int mf = 0; mf < 4; mf++) {
                uint32_t byt = a_row + (uint32_t)mf * 2048 + a_koff + k0b;
                uint32_t sw = byt ^ ((byt >> 3) & 0x70);
                ldsm_x4(ah[mf], base + sw);
            }
            uint32_t bf[4][4];
            #pragma unroll
            for (int p = 0; p < 4; p++) {
                uint32_t byt = b_row + (uint32_t)p * 2048 + b_koff + k0b;
                uint32_t sw = byt ^ ((byt >> 3) & 0x70);
                ldsm_x4(bf[p], base + b_tile + sw);
            }
            if (ks == 3 && lane == 0) MBAR_ARRIVE(EMPTB + s * 8);

            #pragma unroll
            for (int p = 0; p < 4; p++)
                #pragma unroll
                for (int mf = 0; mf < 4; mf++) {
                    mma_f16(acc[mf][2 * p],     ah[mf], &bf[p][0]);
                    mma_f16(acc[mf][2 * p + 1], ah[mf], &bf[p][2]);
                }
        }
        if (tid == 0 && c + 4 < 16) {
            mbar_wait(EMPTB + s * 8, phase);
            issue(c + 4);
        }
    }

    // ---------------- epilogue ----------------
    const int l_base = mt * 128 + wm * 64 + (lane >> 2);
    const int tig = lane & 3;
    const int hglob = nt * 4 + wn;

    #pragma unroll
    for (int mf = 0; mf < 4; mf++) {
        #pragma unroll
        for (int rh = 0; rh < 2; rh++) {
            const int l = l_base + mf * 16 + 8 * rh;
            #pragma unroll
            for (int nf = 0; nf < 8; nf++) {
                const int d = 8 * nf + 2 * tig;
                float x0 = acc[mf][nf][2 * rh];
                float x1 = acc[mf][nf][2 * rh + 1];
                if (mode == 3) {
                    float2* dst = (float2*)(out + ((size_t)b * LL + l) * DD + hglob * 64 + d);
                    *dst = make_float2(x0, x1);
                } else {
                    float y0, y1;
                    if (mode == 2) { y0 = x0; y1 = x1; }
                    else {
                        const int p = d >> 1;
                        float cs = g_cos[l * 32 + p];
                        float sn = g_sin[l * 32 + p];
                        y0 = x0 * cs - x1 * sn;
                        y1 = x1 * cs + x0 * sn;
                    }
                    uint32_t off = (uint32_t)((((b * HH + hglob) * LL) + l) * 128 + d * 2);
                    uint32_t sw = off ^ ((off >> 3) & 0x70);
                    char* dst = (mode == 0) ? (char*)g_qh : (mode == 1) ? (char*)g_kh : (char*)g_vh;
                    *(uint32_t*)(dst + sw) = pack_h2(__float2half_rn(y0), __float2half_rn(y1));
                }
            }
        }
    }
}

// ---------------- flash attention (fp16 1-term): 128 q-rows/CTA, 8 warps x 16 rows ---
__global__ void __launch_bounds__(256, 2) attn_kernel() {
    extern __shared__ __align__(1024) char smem[];
    const uint32_t sb = smem_u32(smem);
    const int tid = threadIdx.x, lane = tid & 31, w = tid >> 5;
    const int qt = 3 - blockIdx.x;       // long CTAs first
    const int bh = blockIdx.y;
    const int b = bh >> 4, h = bh & 15;
    const int g = lane >> 2, tig = lane & 3;

    const uint32_t QB = sb;
    const uint32_t FB = sb + 8;
    const uint32_t QT = sb + 1024;                 // Q 16KB
    const uint32_t KV = sb + 1024 + 16384;         // 2 stages x (Kh 8KB | Vh 8KB)

    if (tid == 0) { MBAR_INIT(QB, 1); MBAR_INIT(FB, 1); MBAR_INIT(FB + 8, 1); }
    __syncthreads();

    const size_t bh_off = (size_t)bh * LL * HDIM;
    const __half* kh = g_kh + bh_off;
    const __half* vh = g_vh + bh_off;

    const int jmax = 2 * qt + 2;

    auto issue = [&](int jt) {
        int s = jt & 1;
        uint32_t fb = FB + s * 8;
        uint32_t st = KV + s * 16384;
        MBAR_EXPECT_TX(fb, 16384);
        bulk_g2s(st,        kh + (size_t)jt * 4096, 8192, fb);
        bulk_g2s(st + 8192, vh + (size_t)jt * 4096, 8192, fb);
    };
    if (tid == 0) {
        MBAR_EXPECT_TX(QB, 16384);
        bulk_g2s(QT, g_qh + bh_off + (size_t)qt * 128 * 64, 16384, QB);
        issue(0);
        issue(1);
    }

    float o[8][4];
    #pragma unroll
    for (int nf = 0; nf < 8; nf++)
        #pragma unroll
        for (int r = 0; r < 4; r++) o[nf][r] = 0.f;
    float m0 = -1e30f, m1 = -1e30f, l0 = 0.f, l1 = 0.f;

    const int rowmin = qt * 128 + w * 16;

    mbar_wait(QB, 0);

    for (int jt = 0; jt < jmax; jt++) {
        const int s = jt & 1;
        mbar_wait(FB + s * 8, (uint32_t)((jt >> 1) & 1));
        const uint32_t kb = KV + s * 16384;

        if (jt * 64 <= rowmin + 15) {
            float p[8][4];
            #pragma unroll
            for (int nf = 0; nf < 8; nf++)
                #pragma unroll
                for (int r = 0; r < 4; r++) p[nf][r] = 0.f;

            // S = Q K^T : both single fp16
            #pragma unroll
            for (int ks = 0; ks < 4; ks++) {
                uint32_t qoff = (uint32_t)(w * 16 + (lane & 15)) * 128
                                + (uint32_t)(lane >> 4) * 16 + (uint32_t)ks * 32;
                uint32_t swq = qoff ^ ((qoff >> 3) & 0x70);
                uint32_t ah[4];
                ldsm_x4(ah, QT + swq);
                #pragma unroll
                for (int nfp = 0; nfp < 4; nfp++) {
                    uint32_t koff = (uint32_t)(nfp * 16 + (lane & 7) + ((lane & 16) >> 1)) * 128
                                    + (uint32_t)ks * 32 + ((lane & 8) << 1);
                    uint32_t swk = koff ^ ((koff >> 3) & 0x70);
                    uint32_t kf[4];
                    ldsm_x4(kf, kb + swk);
                    mma_f16(p[2 * nfp],     ah, &kf[0]);
                    mma_f16(p[2 * nfp + 1], ah, &kf[2]);
                }
            }

            const bool need_mask = (jt * 64 + 63) > rowmin;
            #pragma unroll
            for (int nf = 0; nf < 8; nf++)
                #pragma unroll
                for (int r = 0; r < 4; r++) {
                    float v = p[nf][r] * 0.125f;
                    if (need_mask) {
                        int qr = rowmin + g + ((r & 2) << 2);
                        int kc = jt * 64 + 8 * nf + 2 * tig + (r & 1);
                        if (kc > qr) v = -1e30f;
                    }
                    p[nf][r] = v;
                }

            float mx0 = m0, mx1 = m1;
            #pragma unroll
            for (int nf = 0; nf < 8; nf++) {
                mx0 = fmaxf(mx0, fmaxf(p[nf][0], p[nf][1]));
                mx1 = fmaxf(mx1, fmaxf(p[nf][2], p[nf][3]));
            }
            mx0 = fmaxf(mx0, __shfl_xor_sync(0xffffffffu, mx0, 1));
            mx0 = fmaxf(mx0, __shfl_xor_sync(0xffffffffu, mx0, 2));
            mx1 = fmaxf(mx1, __shfl_xor_sync(0xffffffffu, mx1, 1));
            mx1 = fmaxf(mx1, __shfl_xor_sync(0xffffffffu, mx1, 2));
            float c0 = __expf(m0 - mx0), c1 = __expf(m1 - mx1);
            m0 = mx0; m1 = mx1;
            float s0 = 0.f, s1 = 0.f;
            #pragma unroll
            for (int nf = 0; nf < 8; nf++) {
                p[nf][0] = __expf(p[nf][0] - mx0); s0 += p[nf][0];
                p[nf][1] = __expf(p[nf][1] - mx0); s0 += p[nf][1];
                p[nf][2] = __expf(p[nf][2] - mx1); s1 += p[nf][2];
                p[nf][3] = __expf(p[nf][3] - mx1); s1 += p[nf][3];
            }
            s0 += __shfl_xor_sync(0xffffffffu, s0, 1);
            s0 += __shfl_xor_sync(0xffffffffu, s0, 2);
            s1 += __shfl_xor_sync(0xffffffffu, s1, 1);
            s1 += __shfl_xor_sync(0xffffffffu, s1, 2);
            l0 = l0 * c0 + s0;
            l1 = l1 * c1 + s1;
            #pragma unroll
            for (int nf = 0; nf < 8; nf++) {
                o[nf][0] *= c0; o[nf][1] *= c0;
                o[nf][2] *= c1; o[nf][3] *= c1;
            }

            // O += P V : P single fp16, V single fp16
            #pragma unroll
            for (int j = 0; j < 4; j++) {
                uint32_t pah[4];
                #pragma unroll
                for (int half = 0; half < 2; half++) {
                    const float* pf = p[2 * j + half];
                    pah[2 * half]     = pack_h2(__float2half_rn(pf[0]), __float2half_rn(pf[1]));
                    pah[2 * half + 1] = pack_h2(__float2half_rn(pf[2]), __float2half_rn(pf[3]));
                }
                #pragma unroll
                for (int nfp = 0; nfp < 4; nfp++) {
                    uint32_t voff = (uint32_t)(16 * j + (lane & 7) + (lane & 8)) * 128
                                    + (uint32_t)nfp * 32 + (lane & 16);
                    uint32_t swv = voff ^ ((voff >> 3) & 0x70);
                    uint32_t vf[4];
                    ldsm_x4t(vf, kb + 8192 + swv);
                    mma_f16(o[2 * nfp],     pah, &vf[0]);
                    mma_f16(o[2 * nfp + 1], pah, &vf[2]);
                }
            }
        }
        __syncthreads();
        if (tid == 0 && jt + 2 < jmax) issue(jt + 2);
    }

    // epilogue: O /= l; write AO as single-fp16 swizzled tile (rt = b*4+qt, kc = h)
    const float i0 = 1.f / l0, i1 = 1.f / l1;
    const size_t tb = (((size_t)(b * 4 + qt) * 16) + h) * 16384;   // bytes
    char* dh = (char*)g_xh + tb;
    #pragma unroll
    for (int nf = 0; nf < 8; nf++) {
        #pragma unroll
        for (int rh = 0; rh < 2; rh++) {
            float y0 = o[nf][2 * rh]     * (rh ? i1 : i0);
            float y1 = o[nf][2 * rh + 1] * (rh ? i1 : i0);
            uint32_t off = (uint32_t)((w * 16 + g + 8 * rh) * 128 + (8 * nf + 2 * tig) * 2);
            uint32_t sw = off ^ ((off >> 3) & 0x70);
            *(uint32_t*)(dh + sw) = pack_h2(__float2half_rn(y0), __float2half_rn(y1));
        }
    }
}

// ---------------- launch ----------------
extern "C" void kernel_launch(void* const* d_in, const int* in_sizes, int n_in,
                              void* d_out, int out_size) {
    const float* x  = (const float*)d_in[0];
    const float* qw = (const float*)d_in[1];
    const float* kw = (const float*)d_in[2];
    const float* vw = (const float*)d_in[3];
    const float* ow = (const float*)d_in[4];
    const float* rw = (const float*)d_in[5];
    const float* rb = (const float*)d_in[6];
    float* out = (float*)d_out;

    const int GEMM_SMEM = 1024 + 4 * 49152;           // 197632
    cudaFuncSetAttribute(hmma_gemm_kernel, cudaFuncAttributeMaxDynamicSharedMemorySize, GEMM_SMEM);
    const int ATTN_SMEM = 1024 + 16384 + 2 * 16384;   // 50176
    cudaFuncSetAttribute(attn_kernel, cudaFuncAttributeMaxDynamicSharedMemorySize, ATTN_SMEM);

    rope_init_kernel<<<64, 256>>>();                                          // 0

    int write_probs = (out_size >= BB * LL * DD + BB * EE) ? 1 : 0;
    router_kernel<<<BB, 256>>>(x, rw, rb, out + (size_t)BB * LL * DD, write_probs); // 1

    convert_kernel<<<6144, 256>>>(x, qw, kw, vw, ow);                         // 2

    // fused Q/K/V projection (profiled: launch index 3)
    hmma_gemm_kernel<<<dim3(12, 4, BB), 256, GEMM_SMEM>>>(nullptr, 0);        // 3

    attn_kernel<<<dim3(4, BB * HH), 256, ATTN_SMEM>>>();                      // 4

    // out projection (AO tiles written directly by attention epilogue)
    hmma_gemm_kernel<<<dim3(4, 4, BB), 256, GEMM_SMEM>>>(out, 3);             // 5
}

// round 12
// speedup vs baseline: 5.5187x; 1.0965x over previous
#include <cuda_runtime.h>
#include <cuda_bf16.h>
#include <cuda_fp16.h>
#include <cstdint>
#include <math.h>

#define BB 32
#define LL 512
#define DD 1024
#define HH 16
#define HDIM 64
#define EE 8

// ---------------- scratch (device globals; no allocation allowed) ----------------
__device__ float g_cos[LL * 32];
__device__ float g_sin[LL * 32];
__device__ int   g_routes[BB];

// X/AO tiles (single fp16): [rt(128)][kc(16)] each 128 rows x 64 cols (16KB), SW128
__device__ __half g_xh[(size_t)16384 * 1024];
// W^T tiles (single fp16): [mode(4)][e(8)][nt(8)][kc(16)] each 128(n) x 64(k), SW128
__device__ __half g_wt[(size_t)4 * 8 * 1024 * 1024];
// q/k/v single fp16: [B*H][512][64], SW128-swizzled 128B rows
__device__ __half g_qh[(size_t)BB * HH * LL * HDIM];
__device__ __half g_kh[(size_t)BB * HH * LL * HDIM];
__device__ __half g_vh[(size_t)BB * HH * LL * HDIM];

// ---------------- PTX helpers ----------------
__device__ __forceinline__ uint32_t smem_u32(const void* p) {
    uint32_t a;
    asm("{ .reg .u64 t; cvta.to.shared.u64 t, %1; cvt.u32.u64 %0, t; }" : "=r"(a) : "l"(p));
    return a;
}

#define MBAR_INIT(a, n) \
    asm volatile("mbarrier.init.shared.b64 [%0], %1;" :: "r"(a), "r"((uint32_t)(n)) : "memory")
#define MBAR_EXPECT_TX(a, b) \
    asm volatile("mbarrier.arrive.expect_tx.shared.b64 _, [%0], %1;" :: "r"(a), "r"((uint32_t)(b)) : "memory")
#define MBAR_ARRIVE(a) \
    asm volatile("mbarrier.arrive.shared.b64 _, [%0];" :: "r"(a) : "memory")

__device__ __forceinline__ void mbar_wait(uint32_t mbar, uint32_t parity) {
    asm volatile(
        "{\n\t.reg .pred P;\n\t"
        "WL_%=:\n\t"
        "mbarrier.try_wait.parity.acquire.cta.shared::cta.b64 P, [%0], %1, 0x989680;\n\t"
        "@P bra.uni WD_%=;\n\t"
        "bra.uni WL_%=;\n\t"
        "WD_%=:\n\t}"
        :: "r"(mbar), "r"(parity) : "memory");
}

__device__ __forceinline__ void bulk_g2s(uint32_t dst, const void* src, uint32_t bytes, uint32_t mbar) {
    asm volatile(
        "cp.async.bulk.shared::cluster.global.mbarrier::complete_tx::bytes [%0], [%1], %2, [%3];"
        :: "r"(dst), "l"(src), "r"(bytes), "r"(mbar) : "memory");
}

__device__ __forceinline__ void ldsm_x4(uint32_t* r, uint32_t a) {
    asm volatile("ldmatrix.sync.aligned.m8n8.x4.shared.b16 {%0,%1,%2,%3}, [%4];"
                 : "=r"(r[0]), "=r"(r[1]), "=r"(r[2]), "=r"(r[3]) : "r"(a));
}
__device__ __forceinline__ void ldsm_x4t(uint32_t* r, uint32_t a) {
    asm volatile("ldmatrix.sync.aligned.m8n8.x4.trans.shared.b16 {%0,%1,%2,%3}, [%4];"
                 : "=r"(r[0]), "=r"(r[1]), "=r"(r[2]), "=r"(r[3]) : "r"(a));
}
__device__ __forceinline__ void mma_f16(float* d, const uint32_t* a, const uint32_t* b) {
    asm volatile(
        "mma.sync.aligned.m16n8k16.row.col.f32.f16.f16.f32 "
        "{%0,%1,%2,%3}, {%4,%5,%6,%7}, {%8,%9}, {%0,%1,%2,%3};"
        : "+f"(d[0]), "+f"(d[1]), "+f"(d[2]), "+f"(d[3])
        : "r"(a[0]), "r"(a[1]), "r"(a[2]), "r"(a[3]), "r"(b[0]), "r"(b[1]));
}

__device__ __forceinline__ uint32_t pack_h2(__half a, __half b) {
    return (uint32_t)__half_as_ushort(a) | ((uint32_t)__half_as_ushort(b) << 16);
}

// ---------------- RoPE tables ----------------
__global__ void rope_init_kernel() {
    int idx = blockIdx.x * blockDim.x + threadIdx.x;
    if (idx >= LL * 32) return;
    int l = idx >> 5;
    int jp = idx & 31;
    float inv = 1.0f / powf(10000.0f, (float)(2 * jp) / 64.0f);
    float ang = (float)l * inv;
    g_cos[idx] = cosf(ang);
    g_sin[idx] = sinf(ang);
}

// ---------------- router ----------------
__global__ void router_kernel(const float* __restrict__ x,
                              const float* __restrict__ rw,
                              const float* __restrict__ rb,
                              float* __restrict__ probs_out,
                              int write_probs) {
    int b = blockIdx.x;
    __shared__ float mean[DD];
    __shared__ float logits[EE];

    for (int d = threadIdx.x; d < DD; d += blockDim.x) {
        const float* xp = x + (size_t)b * LL * DD + d;
        float s = 0.f;
        #pragma unroll 8
        for (int l = 0; l < LL; l++) s += xp[(size_t)l * DD];
        mean[d] = s * (1.0f / (float)LL);
    }
    __syncthreads();

    int w = threadIdx.x >> 5;
    int lane = threadIdx.x & 31;
    if (w < EE) {
        float s = 0.f;
        for (int d = lane; d < DD; d += 32) s += mean[d] * rw[d * EE + w];
        #pragma unroll
        for (int o = 16; o > 0; o >>= 1) s += __shfl_down_sync(0xffffffffu, s, o);
        if (lane == 0) logits[w] = s + rb[w];
    }
    __syncthreads();

    if (threadIdx.x == 0) {
        float m = logits[0]; int arg = 0;
        #pragma unroll
        for (int e = 1; e < EE; e++) if (logits[e] > m) { m = logits[e]; arg = e; }
        float p[EE], sum = 0.f;
        #pragma unroll
        for (int e = 0; e < EE; e++) { p[e] = expf(logits[e] - m); sum += p[e]; }
        if (write_probs) {
            float inv = 1.0f / sum;
            #pragma unroll
            for (int e = 0; e < EE; e++) probs_out[b * EE + e] = p[e] * inv;
        }
        g_routes[b] = arg;
    }
}

// ---------------- merged convert: X tiles + W^T tiles (single fp16) ------------------
__global__ void convert_kernel(const float* __restrict__ x,
                               const float* __restrict__ qw, const float* __restrict__ kw,
                               const float* __restrict__ vw, const float* __restrict__ ow) {
    __shared__ float sm[64][129];
    const int bid = blockIdx.x;
    const int tid = threadIdx.x;

    if (bid < 2048) {
        const int rt = bid >> 4, kc = bid & 15;
        const size_t tb = ((size_t)rt * 16 + kc) * 8192;
        char* dh = (char*)(g_xh + tb);
        #pragma unroll
        for (int i = 0; i < 4; i++) {
            int u = tid + i * 256;
            int r = u >> 3, k8 = u & 7;
            const float* p = x + ((size_t)(rt * 128 + r)) * DD + kc * 64 + k8 * 8;
            float4 a = *(const float4*)p;
            float4 b4 = *(const float4*)(p + 4);
            uint32_t off = (uint32_t)(u * 16);
            off ^= (off >> 3) & 0x70;
            *(uint4*)(dh + off) = make_uint4(
                pack_h2(__float2half_rn(a.x),  __float2half_rn(a.y)),
                pack_h2(__float2half_rn(a.z),  __float2half_rn(a.w)),
                pack_h2(__float2half_rn(b4.x), __float2half_rn(b4.y)),
                pack_h2(__float2half_rn(b4.z), __float2half_rn(b4.w)));
        }
    } else {
        const int idx = bid - 2048;
        const int kc = idx & 15, nt = (idx >> 4) & 7;
        const int e = (idx >> 7) & 7, mode = idx >> 10;
        const float* W = (mode == 0) ? qw : (mode == 1) ? kw : (mode == 2) ? vw : ow;
        const float* src = W + ((size_t)e * DD + kc * 64) * DD + nt * 128;

        #pragma unroll
        for (int i = 0; i < 8; i++) {
            int idx2 = tid + i * 256;
            int kr = idx2 >> 5, nc = (idx2 & 31) << 2;
            float4 v = *(const float4*)(src + (size_t)kr * DD + nc);
            sm[kr][nc] = v.x; sm[kr][nc + 1] = v.y; sm[kr][nc + 2] = v.z; sm[kr][nc + 3] = v.w;
        }
        __syncthreads();

        const size_t tb = (((size_t)(mode * 8 + e) * 8 + nt) * 16 + kc) * 8192;
        char* dw = (char*)(g_wt + tb);
        #pragma unroll
        for (int i = 0; i < 4; i++) {
            int u = tid + i * 256;
            int n = u >> 3, k8 = u & 7;
            __half h[8];
            #pragma unroll
            for (int j = 0; j < 8; j++) h[j] = __float2half_rn(sm[k8 * 8 + j][n]);
            uint32_t off = (uint32_t)(u * 16);
            off ^= (off >> 3) & 0x70;
            *(uint4*)(dw + off) = make_uint4(pack_h2(h[0], h[1]), pack_h2(h[2], h[3]),
                                             pack_h2(h[4], h[5]), pack_h2(h[6], h[7]));
        }
    }
}

// ---------------- HMMA GEMM: CTA 128x128, warp 64x32, 2 CTAs/SM, 3-stage -------------
__global__ void __launch_bounds__(256, 2) hmma_gemm_kernel(float* __restrict__ out, int mode0) {
    extern __shared__ __align__(1024) char smem[];
    const uint32_t sb = smem_u32(smem);
    const int tid = threadIdx.x;
    const int lane = tid & 31, wid = tid >> 5;
    const int wm = wid >> 2, wn = wid & 3;            // 2(m) x 4(n)
    const int nt = blockIdx.x & 7;
    const int mode = mode0 + (blockIdx.x >> 3);
    const int mt = blockIdx.y, b = blockIdx.z;
    const int e = g_routes[b];

    const uint32_t FULLB = sb;                        // 3 full mbarriers
    const uint32_t EMPTB = sb + 24;                   // 3 empty mbarriers (count 8)
    const uint32_t TILES = sb + 1024;                 // 3 stages x 32KB: A | B

    if (tid == 0) {
        #pragma unroll
        for (int s = 0; s < 3; s++) { MBAR_INIT(FULLB + s * 8, 1); MBAR_INIT(EMPTB + s * 8, 8); }
    }
    __syncthreads();

    const __half* Ah = g_xh + ((size_t)(b * 4 + mt) * 16) * 8192;
    const __half* B0 = g_wt + (((size_t)(mode * 8 + e) * 8 + nt) * 16) * 8192;

    auto issue = [&](int c) {
        int s = c % 3;
        uint32_t fb = FULLB + s * 8;
        uint32_t st = TILES + s * 32768;
        MBAR_EXPECT_TX(fb, 32768);
        bulk_g2s(st,         Ah + (size_t)c * 8192, 16384, fb);
        bulk_g2s(st + 16384, B0 + (size_t)c * 8192, 16384, fb);
    };
    if (tid == 0) { issue(0); issue(1); issue(2); }

    float acc[4][4][4];
    #pragma unroll
    for (int mf = 0; mf < 4; mf++)
        #pragma unroll
        for (int nf = 0; nf < 4; nf++)
            #pragma unroll
            for (int r = 0; r < 4; r++) acc[mf][nf][r] = 0.f;

    const uint32_t a_row  = (uint32_t)(wm * 64 + (lane & 15)) * 128;
    const uint32_t a_koff = (uint32_t)(lane >> 4) * 16;
    const uint32_t b_row  = (uint32_t)(wn * 32 + (lane & 7) + ((lane >> 4) << 3)) * 128;
    const uint32_t b_koff = (uint32_t)((lane >> 3) & 1) * 16;

    for (int c = 0; c < 16; c++) {
        const int s = c % 3;
        const uint32_t phase = (uint32_t)((c / 3) & 1);
        mbar_wait(FULLB + s * 8, phase);
        const uint32_t base = TILES + s * 32768;

        #pragma unroll
        for (int ks = 0; ks < 4; ks++) {
            const uint32_t k0b = (uint32_t)ks * 32;
            uint32_t ah[4][4];
            #pragma unroll
            for (int mf = 0; mf < 4; mf++) {
                uint32_t byt = a_row + (uint32_t)mf * 2048 + a_koff + k0b;
                uint32_t sw = byt ^ ((byt >> 3) & 0x70);
                ldsm_x4(ah[mf], base + sw);
            }
            uint32_t bf[2][4];
            #pragma unroll
            for (int p = 0; p < 2; p++) {
                uint32_t byt = b_row + (uint32_t)p * 2048 + b_koff + k0b;
                uint32_t sw = byt ^ ((byt >> 3) & 0x70);
                ldsm_x4(bf[p], base + 16384 + sw);
            }
            if (ks == 3 && lane == 0) MBAR_ARRIVE(EMPTB + s * 8);

            #pragma unroll
            for (int p = 0; p < 2; p++)
                #pragma unroll
                for (int mf = 0; mf < 4; mf++) {
                    mma_f16(acc[mf][2 * p],     ah[mf], &bf[p][0]);
                    mma_f16(acc[mf][2 * p + 1], ah[mf], &bf[p][2]);
                }
        }
        if (tid == 0 && c + 3 < 16) {
            mbar_wait(EMPTB + s * 8, phase);
            issue(c + 3);
        }
    }

    // ---------------- epilogue ----------------
    const int l_base = mt * 128 + wm * 64 + (lane >> 2);
    const int tig = lane & 3;
    const int colbase = nt * 128 + wn * 32;
    const int hglob = colbase >> 6;
    const int d0 = colbase & 63;

    #pragma unroll
    for (int mf = 0; mf < 4; mf++) {
        #pragma unroll
        for (int rh = 0; rh < 2; rh++) {
            const int l = l_base + mf * 16 + 8 * rh;
            #pragma unroll
            for (int nf = 0; nf < 4; nf++) {
                const int d = d0 + 8 * nf + 2 * tig;
                float x0 = acc[mf][nf][2 * rh];
                float x1 = acc[mf][nf][2 * rh + 1];
                if (mode == 3) {
                    float2* dst = (float2*)(out + ((size_t)b * LL + l) * DD + hglob * 64 + d);
                    *dst = make_float2(x0, x1);
                } else {
                    float y0, y1;
                    if (mode == 2) { y0 = x0; y1 = x1; }
                    else {
                        const int p = d >> 1;
                        float cs = g_cos[l * 32 + p];
                        float sn = g_sin[l * 32 + p];
                        y0 = x0 * cs - x1 * sn;
                        y1 = x1 * cs + x0 * sn;
                    }
                    uint32_t off = (uint32_t)((((b * HH + hglob) * LL) + l) * 128 + d * 2);
                    uint32_t sw = off ^ ((off >> 3) & 0x70);
                    char* dst = (mode == 0) ? (char*)g_qh : (mode == 1) ? (char*)g_kh : (char*)g_vh;
                    *(uint32_t*)(dst + sw) = pack_h2(__float2half_rn(y0), __float2half_rn(y1));
                }
            }
        }
    }
}

// ---------------- flash attention (fp16 1-term): 128 q-rows/CTA, 8 warps x 16 rows ---
__global__ void __launch_bounds__(256, 2) attn_kernel() {
    extern __shared__ __align__(1024) char smem[];
    const uint32_t sb = smem_u32(smem);
    const int tid = threadIdx.x, lane = tid & 31, w = tid >> 5;
    const int qt = 3 - blockIdx.x;       // long CTAs first
    const int bh = blockIdx.y;
    const int b = bh >> 4, h = bh & 15;
    const int g = lane >> 2, tig = lane & 3;

    const uint32_t QB = sb;
    const uint32_t FB = sb + 8;
    const uint32_t QT = sb + 1024;                 // Q 16KB
    const uint32_t KV = sb + 1024 + 16384;         // 2 stages x (Kh 8KB | Vh 8KB)

    if (tid == 0) { MBAR_INIT(QB, 1); MBAR_INIT(FB, 1); MBAR_INIT(FB + 8, 1); }
    __syncthreads();

    const size_t bh_off = (size_t)bh * LL * HDIM;
    const __half* kh = g_kh + bh_off;
    const __half* vh = g_vh + bh_off;

    const int jmax = 2 * qt + 2;

    auto issue = [&](int jt) {
        int s = jt & 1;
        uint32_t fb = FB + s * 8;
        uint32_t st = KV + s * 16384;
        MBAR_EXPECT_TX(fb, 16384);
        bulk_g2s(st,        kh + (size_t)jt * 4096, 8192, fb);
        bulk_g2s(st + 8192, vh + (size_t)jt * 4096, 8192, fb);
    };
    if (tid == 0) {
        MBAR_EXPECT_TX(QB, 16384);
        bulk_g2s(QT, g_qh + bh_off + (size_t)qt * 128 * 64, 16384, QB);
        issue(0);
        issue(1);
    }

    float o[8][4];
    #pragma unroll
    for (int nf = 0; nf < 8; nf++)
        #pragma unroll
        for (int r = 0; r < 4; r++) o[nf][r] = 0.f;
    float m0 = -1e30f, m1 = -1e30f, l0 = 0.f, l1 = 0.f;

    const int rowmin = qt * 128 + w * 16;

    mbar_wait(QB, 0);

    for (int jt = 0; jt < jmax; jt++) {
        const int s = jt & 1;
        mbar_wait(FB + s * 8, (uint32_t)((jt >> 1) & 1));
        const uint32_t kb = KV + s * 16384;

        if (jt * 64 <= rowmin + 15) {
            float p[8][4];
            #pragma unroll
            for (int nf = 0; nf < 8; nf++)
                #pragma unroll
                for (int r = 0; r < 4; r++) p[nf][r] = 0.f;

            // S = Q K^T : both single fp16
            #pragma unroll
            for (int ks = 0; ks < 4; ks++) {
                uint32_t qoff = (uint32_t)(w * 16 + (lane & 15)) * 128
                                + (uint32_t)(lane >> 4) * 16 + (uint32_t)ks * 32;
                uint32_t swq = qoff ^ ((qoff >> 3) & 0x70);
                uint32_t ah[4];
                ldsm_x4(ah, QT + swq);
                #pragma unroll
                for (int nfp = 0; nfp < 4; nfp++) {
                    uint32_t koff = (uint32_t)(nfp * 16 + (lane & 7) + ((lane & 16) >> 1)) * 128
                                    + (uint32_t)ks * 32 + ((lane & 8) << 1);
                    uint32_t swk = koff ^ ((koff >> 3) & 0x70);
                    uint32_t kf[4];
                    ldsm_x4(kf, kb + swk);
                    mma_f16(p[2 * nfp],     ah, &kf[0]);
                    mma_f16(p[2 * nfp + 1], ah, &kf[2]);
                }
            }

            const bool need_mask = (jt * 64 + 63) > rowmin;
            #pragma unroll
            for (int nf = 0; nf < 8; nf++)
                #pragma unroll
                for (int r = 0; r < 4; r++) {
                    float v = p[nf][r] * 0.125f;
                    if (need_mask) {
                        int qr = rowmin + g + ((r & 2) << 2);
                        int kc = jt * 64 + 8 * nf + 2 * tig + (r & 1);
                        if (kc > qr) v = -1e30f;
                    }
                    p[nf][r] = v;
                }

            float mx0 = m0, mx1 = m1;
            #pragma unroll
            for (int nf = 0; nf < 8; nf++) {
                mx0 = fmaxf(mx0, fmaxf(p[nf][0], p[nf][1]));
                mx1 = fmaxf(mx1, fmaxf(p[nf][2], p[nf][3]));
            }
            mx0 = fmaxf(mx0, __shfl_xor_sync(0xffffffffu, mx0, 1));
            mx0 = fmaxf(mx0, __shfl_xor_sync(0xffffffffu, mx0, 2));
            mx1 = fmaxf(mx1, __shfl_xor_sync(0xffffffffu, mx1, 1));
            mx1 = fmaxf(mx1, __shfl_xor_sync(0xffffffffu, mx1, 2));
            float c0 = __expf(m0 - mx0), c1 = __expf(m1 - mx1);
            m0 = mx0; m1 = mx1;
            float s0 = 0.f, s1 = 0.f;
            #pragma unroll
            for (int nf = 0; nf < 8; nf++) {
                p[nf][0] = __expf(p[nf][0] - mx0); s0 += p[nf][0];
                p[nf][1] = __expf(p[nf][1] - mx0); s0 += p[nf][1];
                p[nf][2] = __expf(p[nf][2] - mx1); s1 += p[nf][2];
                p[nf][3] = __expf(p[nf][3] - mx1); s1 += p[nf][3];
            }
            s0 += __shfl_xor_sync(0xffffffffu, s0, 1);
            s0 += __shfl_xor_sync(0xffffffffu, s0, 2);
            s1 += __shfl_xor_sync(0xffffffffu, s1, 1);
            s1 += __shfl_xor_sync(0xffffffffu, s1, 2);
            l0 = l0 * c0 + s0;
            l1 = l1 * c1 + s1;
            #pragma unroll
            for (int nf = 0; nf < 8; nf++) {
                o[nf][0] *= c0; o[nf][1] *= c0;
                o[nf][2] *= c1; o[nf][3] *= c1;
            }

            // O += P V : P single fp16, V single fp16
            #pragma unroll
            for (int j = 0; j < 4; j++) {
                uint32_t pah[4];
                #pragma unroll
                for (int half = 0; half < 2; half++) {
                    const float* pf = p[2 * j + half];
                    pah[2 * half]     = pack_h2(__float2half_rn(pf[0]), __float2half_rn(pf[1]));
                    pah[2 * half + 1] = pack_h2(__float2half_rn(pf[2]), __float2half_rn(pf[3]));
                }
                #pragma unroll
                for (int nfp = 0; nfp < 4; nfp++) {
                    uint32_t voff = (uint32_t)(16 * j + (lane & 7) + (lane & 8)) * 128
                                    + (uint32_t)nfp * 32 + (lane & 16);
                    uint32_t swv = voff ^ ((voff >> 3) & 0x70);
                    uint32_t vf[4];
                    ldsm_x4t(vf, kb + 8192 + swv);
                    mma_f16(o[2 * nfp],     pah, &vf[0]);
                    mma_f16(o[2 * nfp + 1], pah, &vf[2]);
                }
            }
        }
        __syncthreads();
        if (tid == 0 && jt + 2 < jmax) issue(jt + 2);
    }

    // epilogue: O /= l; write AO as single-fp16 swizzled tile (rt = b*4+qt, kc = h)
    const float i0 = 1.f / l0, i1 = 1.f / l1;
    const size_t tb = (((size_t)(b * 4 + qt) * 16) + h) * 16384;   // bytes
    char* dh = (char*)g_xh + tb;
    #pragma unroll
    for (int nf = 0; nf < 8; nf++) {
        #pragma unroll
        for (int rh = 0; rh < 2; rh++) {
            float y0 = o[nf][2 * rh]     * (rh ? i1 : i0);
            float y1 = o[nf][2 * rh + 1] * (rh ? i1 : i0);
            uint32_t off = (uint32_t)((w * 16 + g + 8 * rh) * 128 + (8 * nf + 2 * tig) * 2);
            uint32_t sw = off ^ ((off >> 3) & 0x70);
            *(uint32_t*)(dh + sw) = pack_h2(__float2half_rn(y0), __float2half_rn(y1));
        }
    }
}

// ---------------- launch ----------------
extern "C" void kernel_launch(void* const* d_in, const int* in_sizes, int n_in,
                              void* d_out, int out_size) {
    const float* x  = (const float*)d_in[0];
    const float* qw = (const float*)d_in[1];
    const float* kw = (const float*)d_in[2];
    const float* vw = (const float*)d_in[3];
    const float* ow = (const float*)d_in[4];
    const float* rw = (const float*)d_in[5];
    const float* rb = (const float*)d_in[6];
    float* out = (float*)d_out;

    const int GEMM_SMEM = 1024 + 3 * 32768;           // 99328 (x2 CTAs = 198656)
    cudaFuncSetAttribute(hmma_gemm_kernel, cudaFuncAttributeMaxDynamicSharedMemorySize, GEMM_SMEM);
    const int ATTN_SMEM = 1024 + 16384 + 2 * 16384;   // 50176
    cudaFuncSetAttribute(attn_kernel, cudaFuncAttributeMaxDynamicSharedMemorySize, ATTN_SMEM);

    rope_init_kernel<<<64, 256>>>();                                          // 0

    int write_probs = (out_size >= BB * LL * DD + BB * EE) ? 1 : 0;
    router_kernel<<<BB, 256>>>(x, rw, rb, out + (size_t)BB * LL * DD, write_probs); // 1

    convert_kernel<<<6144, 256>>>(x, qw, kw, vw, ow);                         // 2

    // fused Q/K/V projection (profiled: launch index 3)
    hmma_gemm_kernel<<<dim3(24, 4, BB), 256, GEMM_SMEM>>>(nullptr, 0);        // 3

    attn_kernel<<<dim3(4, BB * HH), 256, ATTN_SMEM>>>();                      // 4

    // out projection (AO tiles written directly by attention epilogue)
    hmma_gemm_kernel<<<dim3(8, 4, BB), 256, GEMM_SMEM>>>(out, 3);             // 5
}

// round 13
// speedup vs baseline: 5.5971x; 1.0142x over previous
#include <cuda_runtime.h>
#include <cuda_bf16.h>
#include <cuda_fp16.h>
#include <cstdint>
#include <math.h>

#define BB 32
#define LL 512
#define DD 1024
#define HH 16
#define HDIM 64
#define EE 8

// ---------------- scratch (device globals; no allocation allowed) ----------------
__device__ float g_cos[LL * 32];
__device__ float g_sin[LL * 32];
__device__ int   g_routes[BB];

// X/AO tiles (single fp16): [rt(128)][kc(16)] each 128 rows x 64 cols (16KB), SW128
__device__ __half g_xh[(size_t)16384 * 1024];
// W^T tiles (single fp16): [mode(4)][e(8)][nt(8)][kc(16)] each 128(n) x 64(k), SW128
__device__ __half g_wt[(size_t)4 * 8 * 1024 * 1024];
// q/k/v single fp16: [B*H][512][64], SW128-swizzled 128B rows
__device__ __half g_qh[(size_t)BB * HH * LL * HDIM];
__device__ __half g_kh[(size_t)BB * HH * LL * HDIM];
__device__ __half g_vh[(size_t)BB * HH * LL * HDIM];

// ---------------- PTX helpers ----------------
__device__ __forceinline__ uint32_t smem_u32(const void* p) {
    uint32_t a;
    asm("{ .reg .u64 t; cvta.to.shared.u64 t, %1; cvt.u32.u64 %0, t; }" : "=r"(a) : "l"(p));
    return a;
}

#define MBAR_INIT(a, n) \
    asm volatile("mbarrier.init.shared.b64 [%0], %1;" :: "r"(a), "r"((uint32_t)(n)) : "memory")
#define MBAR_EXPECT_TX(a, b) \
    asm volatile("mbarrier.arrive.expect_tx.shared.b64 _, [%0], %1;" :: "r"(a), "r"((uint32_t)(b)) : "memory")
#define MBAR_ARRIVE(a) \
    asm volatile("mbarrier.arrive.shared.b64 _, [%0];" :: "r"(a) : "memory")

__device__ __forceinline__ void mbar_wait(uint32_t mbar, uint32_t parity) {
    asm volatile(
        "{\n\t.reg .pred P;\n\t"
        "WL_%=:\n\t"
        "mbarrier.try_wait.parity.acquire.cta.shared::cta.b64 P, [%0], %1, 0x989680;\n\t"
        "@P bra.uni WD_%=;\n\t"
        "bra.uni WL_%=;\n\t"
        "WD_%=:\n\t}"
        :: "r"(mbar), "r"(parity) : "memory");
}

__device__ __forceinline__ void bulk_g2s(uint32_t dst, const void* src, uint32_t bytes, uint32_t mbar) {
    asm volatile(
        "cp.async.bulk.shared::cluster.global.mbarrier::complete_tx::bytes [%0], [%1], %2, [%3];"
        :: "r"(dst), "l"(src), "r"(bytes), "r"(mbar) : "memory");
}

__device__ __forceinline__ void ldsm_x4(uint32_t* r, uint32_t a) {
    asm volatile("ldmatrix.sync.aligned.m8n8.x4.shared.b16 {%0,%1,%2,%3}, [%4];"
                 : "=r"(r[0]), "=r"(r[1]), "=r"(r[2]), "=r"(r[3]) : "r"(a));
}
__device__ __forceinline__ void ldsm_x4t(uint32_t* r, uint32_t a) {
    asm volatile("ldmatrix.sync.aligned.m8n8.x4.trans.shared.b16 {%0,%1,%2,%3}, [%4];"
                 : "=r"(r[0]), "=r"(r[1]), "=r"(r[2]), "=r"(r[3]) : "r"(a));
}
__device__ __forceinline__ void mma_f16(float* d, const uint32_t* a, const uint32_t* b) {
    asm volatile(
        "mma.sync.aligned.m16n8k16.row.col.f32.f16.f16.f32 "
        "{%0,%1,%2,%3}, {%4,%5,%6,%7}, {%8,%9}, {%0,%1,%2,%3};"
        : "+f"(d[0]), "+f"(d[1]), "+f"(d[2]), "+f"(d[3])
        : "r"(a[0]), "r"(a[1]), "r"(a[2]), "r"(a[3]), "r"(b[0]), "r"(b[1]));
}

__device__ __forceinline__ uint32_t pack_h2(__half a, __half b) {
    return (uint32_t)__half_as_ushort(a) | ((uint32_t)__half_as_ushort(b) << 16);
}

// ---------------- RoPE tables ----------------
__global__ void rope_init_kernel() {
    int idx = blockIdx.x * blockDim.x + threadIdx.x;
    if (idx >= LL * 32) return;
    int l = idx >> 5;
    int jp = idx & 31;
    float inv = 1.0f / powf(10000.0f, (float)(2 * jp) / 64.0f);
    float ang = (float)l * inv;
    g_cos[idx] = cosf(ang);
    g_sin[idx] = sinf(ang);
}

// ---------------- router ----------------
__global__ void router_kernel(const float* __restrict__ x,
                              const float* __restrict__ rw,
                              const float* __restrict__ rb,
                              float* __restrict__ probs_out,
                              int write_probs) {
    int b = blockIdx.x;
    __shared__ float mean[DD];
    __shared__ float logits[EE];

    for (int d = threadIdx.x; d < DD; d += blockDim.x) {
        const float* xp = x + (size_t)b * LL * DD + d;
        float s = 0.f;
        #pragma unroll 8
        for (int l = 0; l < LL; l++) s += xp[(size_t)l * DD];
        mean[d] = s * (1.0f / (float)LL);
    }
    __syncthreads();

    int w = threadIdx.x >> 5;
    int lane = threadIdx.x & 31;
    if (w < EE) {
        float s = 0.f;
        for (int d = lane; d < DD; d += 32) s += mean[d] * rw[d * EE + w];
        #pragma unroll
        for (int o = 16; o > 0; o >>= 1) s += __shfl_down_sync(0xffffffffu, s, o);
        if (lane == 0) logits[w] = s + rb[w];
    }
    __syncthreads();

    if (threadIdx.x == 0) {
        float m = logits[0]; int arg = 0;
        #pragma unroll
        for (int e = 1; e < EE; e++) if (logits[e] > m) { m = logits[e]; arg = e; }
        float p[EE], sum = 0.f;
        #pragma unroll
        for (int e = 0; e < EE; e++) { p[e] = expf(logits[e] - m); sum += p[e]; }
        if (write_probs) {
            float inv = 1.0f / sum;
            #pragma unroll
            for (int e = 0; e < EE; e++) probs_out[b * EE + e] = p[e] * inv;
        }
        g_routes[b] = arg;
    }
}

// ---------------- merged convert: X tiles + W^T tiles (single fp16) ------------------
__global__ void convert_kernel(const float* __restrict__ x,
                               const float* __restrict__ qw, const float* __restrict__ kw,
                               const float* __restrict__ vw, const float* __restrict__ ow) {
    __shared__ float sm[64][129];
    const int bid = blockIdx.x;
    const int tid = threadIdx.x;

    if (bid < 2048) {
        const int rt = bid >> 4, kc = bid & 15;
        const size_t tb = ((size_t)rt * 16 + kc) * 8192;
        char* dh = (char*)(g_xh + tb);
        #pragma unroll
        for (int i = 0; i < 4; i++) {
            int u = tid + i * 256;
            int r = u >> 3, k8 = u & 7;
            const float* p = x + ((size_t)(rt * 128 + r)) * DD + kc * 64 + k8 * 8;
            float4 a = *(const float4*)p;
            float4 b4 = *(const float4*)(p + 4);
            uint32_t off = (uint32_t)(u * 16);
            off ^= (off >> 3) & 0x70;
            *(uint4*)(dh + off) = make_uint4(
                pack_h2(__float2half_rn(a.x),  __float2half_rn(a.y)),
                pack_h2(__float2half_rn(a.z),  __float2half_rn(a.w)),
                pack_h2(__float2half_rn(b4.x), __float2half_rn(b4.y)),
                pack_h2(__float2half_rn(b4.z), __float2half_rn(b4.w)));
        }
    } else {
        const int idx = bid - 2048;
        const int kc = idx & 15, nt = (idx >> 4) & 7;
        const int e = (idx >> 7) & 7, mode = idx >> 10;
        const float* W = (mode == 0) ? qw : (mode == 1) ? kw : (mode == 2) ? vw : ow;
        const float* src = W + ((size_t)e * DD + kc * 64) * DD + nt * 128;

        #pragma unroll
        for (int i = 0; i < 8; i++) {
            int idx2 = tid + i * 256;
            int kr = idx2 >> 5, nc = (idx2 & 31) << 2;
            float4 v = *(const float4*)(src + (size_t)kr * DD + nc);
            sm[kr][nc] = v.x; sm[kr][nc + 1] = v.y; sm[kr][nc + 2] = v.z; sm[kr][nc + 3] = v.w;
        }
        __syncthreads();

        const size_t tb = (((size_t)(mode * 8 + e) * 8 + nt) * 16 + kc) * 8192;
        char* dw = (char*)(g_wt + tb);
        #pragma unroll
        for (int i = 0; i < 4; i++) {
            int u = tid + i * 256;
            int n = u >> 3, k8 = u & 7;
            __half h[8];
            #pragma unroll
            for (int j = 0; j < 8; j++) h[j] = __float2half_rn(sm[k8 * 8 + j][n]);
            uint32_t off = (uint32_t)(u * 16);
            off ^= (off >> 3) & 0x70;
            *(uint4*)(dw + off) = make_uint4(pack_h2(h[0], h[1]), pack_h2(h[2], h[3]),
                                             pack_h2(h[4], h[5]), pack_h2(h[6], h[7]));
        }
    }
}

// ---------------- HMMA GEMM: CTA 128x128, warp 64x32, 2 CTAs/SM, 3-stage -------------
__global__ void __launch_bounds__(256, 2) hmma_gemm_kernel(float* __restrict__ out, int mode0) {
    extern __shared__ __align__(1024) char smem[];
    const uint32_t sb = smem_u32(smem);
    const int tid = threadIdx.x;
    const int lane = tid & 31, wid = tid >> 5;
    const int wm = wid >> 2, wn = wid & 3;            // 2(m) x 4(n)
    const int nt = blockIdx.x & 7;
    const int mode = mode0 + (blockIdx.x >> 3);
    const int mt = blockIdx.y, b = blockIdx.z;
    const int e = g_routes[b];

    const uint32_t FULLB = sb;                        // 3 full mbarriers
    const uint32_t EMPTB = sb + 24;                   // 3 empty mbarriers (count 8)
    const uint32_t TILES = sb + 1024;                 // 3 stages x 32KB: A | B

    if (tid == 0) {
        #pragma unroll
        for (int s = 0; s < 3; s++) { MBAR_INIT(FULLB + s * 8, 1); MBAR_INIT(EMPTB + s * 8, 8); }
    }
    __syncthreads();

    const __half* Ah = g_xh + ((size_t)(b * 4 + mt) * 16) * 8192;
    const __half* B0 = g_wt + (((size_t)(mode * 8 + e) * 8 + nt) * 16) * 8192;

    auto issue = [&](int c) {
        int s = c % 3;
        uint32_t fb = FULLB + s * 8;
        uint32_t st = TILES + s * 32768;
        MBAR_EXPECT_TX(fb, 32768);
        bulk_g2s(st,         Ah + (size_t)c * 8192, 16384, fb);
        bulk_g2s(st + 16384, B0 + (size_t)c * 8192, 16384, fb);
    };
    if (tid == 0) { issue(0); issue(1); issue(2); }

    float acc[4][4][4];
    #pragma unroll
    for (int mf = 0; mf < 4; mf++)
        #pragma unroll
        for (int nf = 0; nf < 4; nf++)
            #pragma unroll
            for (int r = 0; r < 4; r++) acc[mf][nf][r] = 0.f;

    const uint32_t a_row  = (uint32_t)(wm * 64 + (lane & 15)) * 128;
    const uint32_t a_koff = (uint32_t)(lane >> 4) * 16;
    const uint32_t b_row  = (uint32_t)(wn * 32 + (lane & 7) + ((lane >> 4) << 3)) * 128;
    const uint32_t b_koff = (uint32_t)((lane >> 3) & 1) * 16;

    for (int c = 0; c < 16; c++) {
        const int s = c % 3;
        const uint32_t phase = (uint32_t)((c / 3) & 1);
        mbar_wait(FULLB + s * 8, phase);
        const uint32_t base = TILES + s * 32768;

        #pragma unroll
        for (int ks = 0; ks < 4; ks++) {
            const uint32_t k0b = (uint32_t)ks * 32;
            uint32_t ah[4][4];
            #pragma unroll
            for (int mf = 0; mf < 4; mf++) {
                uint32_t byt = a_row + (uint32_t)mf * 2048 + a_koff + k0b;
                uint32_t sw = byt ^ ((byt >> 3) & 0x70);
                ldsm_x4(ah[mf], base + sw);
            }
            uint32_t bf[2][4];
            #pragma unroll
            for (int p = 0; p < 2; p++) {
                uint32_t byt = b_row + (uint32_t)p * 2048 + b_koff + k0b;
                uint32_t sw = byt ^ ((byt >> 3) & 0x70);
                ldsm_x4(bf[p], base + 16384 + sw);
            }
            if (ks == 3 && lane == 0) MBAR_ARRIVE(EMPTB + s * 8);

            #pragma unroll
            for (int p = 0; p < 2; p++)
                #pragma unroll
                for (int mf = 0; mf < 4; mf++) {
                    mma_f16(acc[mf][2 * p],     ah[mf], &bf[p][0]);
                    mma_f16(acc[mf][2 * p + 1], ah[mf], &bf[p][2]);
                }
        }
        if (tid == 0 && c + 3 < 16) {
            mbar_wait(EMPTB + s * 8, phase);
            issue(c + 3);
        }
    }

    // ---------------- epilogue ----------------
    const int l_base = mt * 128 + wm * 64 + (lane >> 2);
    const int tig = lane & 3;
    const int colbase = nt * 128 + wn * 32;
    const int hglob = colbase >> 6;
    const int d0 = colbase & 63;

    #pragma unroll
    for (int mf = 0; mf < 4; mf++) {
        #pragma unroll
        for (int rh = 0; rh < 2; rh++) {
            const int l = l_base + mf * 16 + 8 * rh;
            #pragma unroll
            for (int nf = 0; nf < 4; nf++) {
                const int d = d0 + 8 * nf + 2 * tig;
                float x0 = acc[mf][nf][2 * rh];
                float x1 = acc[mf][nf][2 * rh + 1];
                if (mode == 3) {
                    float2* dst = (float2*)(out + ((size_t)b * LL + l) * DD + hglob * 64 + d);
                    *dst = make_float2(x0, x1);
                } else {
                    float y0, y1;
                    if (mode == 2) { y0 = x0; y1 = x1; }
                    else {
                        const int p = d >> 1;
                        float cs = g_cos[l * 32 + p];
                        float sn = g_sin[l * 32 + p];
                        y0 = x0 * cs - x1 * sn;
                        y1 = x1 * cs + x0 * sn;
                    }
                    uint32_t off = (uint32_t)((((b * HH + hglob) * LL) + l) * 128 + d * 2);
                    uint32_t sw = off ^ ((off >> 3) & 0x70);
                    char* dst = (mode == 0) ? (char*)g_qh : (mode == 1) ? (char*)g_kh : (char*)g_vh;
                    *(uint32_t*)(dst + sw) = pack_h2(__float2half_rn(y0), __float2half_rn(y1));
                }
            }
        }
    }
}

// ---------------- flash attention: paired q-tiles, balanced CTAs ---------------------
// grid (2, B*H). CTA bx handles q-tiles {3-bx, bx} sequentially (10 KV units each).
__global__ void __launch_bounds__(256, 2) attn_kernel() {
    extern __shared__ __align__(1024) char smem[];
    const uint32_t sb = smem_u32(smem);
    const int tid = threadIdx.x, lane = tid & 31, w = tid >> 5;
    const int bx = blockIdx.x;           // 0 or 1
    const int qtA = 3 - bx, qtB = bx;
    const int bh = blockIdx.y;
    const int b = bh >> 4, h = bh & 15;
    const int g = lane >> 2, tig = lane & 3;

    const uint32_t QB = sb;
    const uint32_t FB = sb + 8;
    const uint32_t QT = sb + 1024;                 // 2 Q tiles x 16KB
    const uint32_t KV = sb + 1024 + 32768;         // 2 stages x (Kh 8KB | Vh 8KB)

    if (tid == 0) { MBAR_INIT(QB, 1); MBAR_INIT(FB, 1); MBAR_INIT(FB + 8, 1); }
    __syncthreads();

    const size_t bh_off = (size_t)bh * LL * HDIM;
    const __half* kh = g_kh + bh_off;
    const __half* vh = g_vh + bh_off;

    const int n1 = 2 * qtA + 2, n2 = 2 * qtB + 2;
    const int ntot = n1 + n2;            // always 10

    auto issue = [&](int i) {
        int jt = (i < n1) ? i : (i - n1);
        int s = i & 1;
        uint32_t fb = FB + s * 8;
        uint32_t st = KV + s * 16384;
        MBAR_EXPECT_TX(fb, 16384);
        bulk_g2s(st,        kh + (size_t)jt * 4096, 8192, fb);
        bulk_g2s(st + 8192, vh + (size_t)jt * 4096, 8192, fb);
    };
    if (tid == 0) {
        MBAR_EXPECT_TX(QB, 32768);
        bulk_g2s(QT,         g_qh + bh_off + (size_t)qtA * 8192, 16384, QB);
        bulk_g2s(QT + 16384, g_qh + bh_off + (size_t)qtB * 8192, 16384, QB);
        issue(0);
        issue(1);
    }

    float o[8][4];
    #pragma unroll
    for (int nf = 0; nf < 8; nf++)
        #pragma unroll
        for (int r = 0; r < 4; r++) o[nf][r] = 0.f;
    float m0 = -1e30f, m1 = -1e30f, l0 = 0.f, l1 = 0.f;

    mbar_wait(QB, 0);

    for (int i = 0; i < ntot; i++) {
        const int pass = (i >= n1);
        const int jt = pass ? (i - n1) : i;
        const int qt = pass ? qtB : qtA;
        const uint32_t qtile = QT + (pass ? 16384u : 0u);
        const int rowmin = qt * 128 + w * 16;

        const int s = i & 1;
        mbar_wait(FB + s * 8, (uint32_t)((i >> 1) & 1));
        const uint32_t kb = KV + s * 16384;

        if (jt * 64 <= rowmin + 15) {
            float p[8][4];
            #pragma unroll
            for (int nf = 0; nf < 8; nf++)
                #pragma unroll
                for (int r = 0; r < 4; r++) p[nf][r] = 0.f;

            // S = Q K^T
            #pragma unroll
            for (int ks = 0; ks < 4; ks++) {
                uint32_t qoff = (uint32_t)(w * 16 + (lane & 15)) * 128
                                + (uint32_t)(lane >> 4) * 16 + (uint32_t)ks * 32;
                uint32_t swq = qoff ^ ((qoff >> 3) & 0x70);
                uint32_t ah[4];
                ldsm_x4(ah, qtile + swq);
                #pragma unroll
                for (int nfp = 0; nfp < 4; nfp++) {
                    uint32_t koff = (uint32_t)(nfp * 16 + (lane & 7) + ((lane & 16) >> 1)) * 128
                                    + (uint32_t)ks * 32 + ((lane & 8) << 1);
                    uint32_t swk = koff ^ ((koff >> 3) & 0x70);
                    uint32_t kf[4];
                    ldsm_x4(kf, kb + swk);
                    mma_f16(p[2 * nfp],     ah, &kf[0]);
                    mma_f16(p[2 * nfp + 1], ah, &kf[2]);
                }
            }

            const bool need_mask = (jt * 64 + 63) > rowmin;
            #pragma unroll
            for (int nf = 0; nf < 8; nf++)
                #pragma unroll
                for (int r = 0; r < 4; r++) {
                    float v = p[nf][r] * 0.125f;
                    if (need_mask) {
                        int qr = rowmin + g + ((r & 2) << 2);
                        int kc = jt * 64 + 8 * nf + 2 * tig + (r & 1);
                        if (kc > qr) v = -1e30f;
                    }
                    p[nf][r] = v;
                }

            float mx0 = m0, mx1 = m1;
            #pragma unroll
            for (int nf = 0; nf < 8; nf++) {
                mx0 = fmaxf(mx0, fmaxf(p[nf][0], p[nf][1]));
                mx1 = fmaxf(mx1, fmaxf(p[nf][2], p[nf][3]));
            }
            mx0 = fmaxf(mx0, __shfl_xor_sync(0xffffffffu, mx0, 1));
            mx0 = fmaxf(mx0, __shfl_xor_sync(0xffffffffu, mx0, 2));
            mx1 = fmaxf(mx1, __shfl_xor_sync(0xffffffffu, mx1, 1));
            mx1 = fmaxf(mx1, __shfl_xor_sync(0xffffffffu, mx1, 2));
            float c0 = __expf(m0 - mx0), c1 = __expf(m1 - mx1);
            m0 = mx0; m1 = mx1;
            float s0 = 0.f, s1 = 0.f;
            #pragma unroll
            for (int nf = 0; nf < 8; nf++) {
                p[nf][0] = __expf(p[nf][0] - mx0); s0 += p[nf][0];
                p[nf][1] = __expf(p[nf][1] - mx0); s0 += p[nf][1];
                p[nf][2] = __expf(p[nf][2] - mx1); s1 += p[nf][2];
                p[nf][3] = __expf(p[nf][3] - mx1); s1 += p[nf][3];
            }
            s0 += __shfl_xor_sync(0xffffffffu, s0, 1);
            s0 += __shfl_xor_sync(0xffffffffu, s0, 2);
            s1 += __shfl_xor_sync(0xffffffffu, s1, 1);
            s1 += __shfl_xor_sync(0xffffffffu, s1, 2);
            l0 = l0 * c0 + s0;
            l1 = l1 * c1 + s1;
            #pragma unroll
            for (int nf = 0; nf < 8; nf++) {
                o[nf][0] *= c0; o[nf][1] *= c0;
                o[nf][2] *= c1; o[nf][3] *= c1;
            }

            // O += P V
            #pragma unroll
            for (int j = 0; j < 4; j++) {
                uint32_t pah[4];
                #pragma unroll
                for (int half = 0; half < 2; half++) {
                    const float* pf = p[2 * j + half];
                    pah[2 * half]     = pack_h2(__float2half_rn(pf[0]), __float2half_rn(pf[1]));
                    pah[2 * half + 1] = pack_h2(__float2half_rn(pf[2]), __float2half_rn(pf[3]));
                }
                #pragma unroll
                for (int nfp = 0; nfp < 4; nfp++) {
                    uint32_t voff = (uint32_t)(16 * j + (lane & 7) + (lane & 8)) * 128
                                    + (uint32_t)nfp * 32 + (lane & 16);
                    uint32_t swv = voff ^ ((voff >> 3) & 0x70);
                    uint32_t vf[4];
                    ldsm_x4t(vf, kb + 8192 + swv);
                    mma_f16(o[2 * nfp],     pah, &vf[0]);
                    mma_f16(o[2 * nfp + 1], pah, &vf[2]);
                }
            }
        }
        __syncthreads();
        if (tid == 0 && i + 2 < ntot) issue(i + 2);

        // pass boundary or end: epilogue for this q-tile, then reset state
        if (i == n1 - 1 || i == ntot - 1) {
            const float i0 = 1.f / l0, i1 = 1.f / l1;
            const size_t tb = (((size_t)(b * 4 + qt) * 16) + h) * 16384;   // bytes
            char* dh = (char*)g_xh + tb;
            #pragma unroll
            for (int nf = 0; nf < 8; nf++) {
                #pragma unroll
                for (int rh = 0; rh < 2; rh++) {
                    float y0 = o[nf][2 * rh]     * (rh ? i1 : i0);
                    float y1 = o[nf][2 * rh + 1] * (rh ? i1 : i0);
                    uint32_t off = (uint32_t)((w * 16 + g + 8 * rh) * 128 + (8 * nf + 2 * tig) * 2);
                    uint32_t sw = off ^ ((off >> 3) & 0x70);
                    *(uint32_t*)(dh + sw) = pack_h2(__float2half_rn(y0), __float2half_rn(y1));
                }
            }
            if (i == n1 - 1) {
                #pragma unroll
                for (int nf = 0; nf < 8; nf++)
                    #pragma unroll
                    for (int r = 0; r < 4; r++) o[nf][r] = 0.f;
                m0 = -1e30f; m1 = -1e30f; l0 = 0.f; l1 = 0.f;
            }
        }
    }
}

// ---------------- launch ----------------
extern "C" void kernel_launch(void* const* d_in, const int* in_sizes, int n_in,
                              void* d_out, int out_size) {
    const float* x  = (const float*)d_in[0];
    const float* qw = (const float*)d_in[1];
    const float* kw = (const float*)d_in[2];
    const float* vw = (const float*)d_in[3];
    const float* ow = (const float*)d_in[4];
    const float* rw = (const float*)d_in[5];
    const float* rb = (const float*)d_in[6];
    float* out = (float*)d_out;

    const int GEMM_SMEM = 1024 + 3 * 32768;           // 99328 (x2 CTAs = 198656)
    cudaFuncSetAttribute(hmma_gemm_kernel, cudaFuncAttributeMaxDynamicSharedMemorySize, GEMM_SMEM);
    const int ATTN_SMEM = 1024 + 32768 + 2 * 16384;   // 66560 (x2 CTAs = 133120)
    cudaFuncSetAttribute(attn_kernel, cudaFuncAttributeMaxDynamicSharedMemorySize, ATTN_SMEM);

    rope_init_kernel<<<64, 256>>>();                                          // 0

    int write_probs = (out_size >= BB * LL * DD + BB * EE) ? 1 : 0;
    router_kernel<<<BB, 256>>>(x, rw, rb, out + (size_t)BB * LL * DD, write_probs); // 1

    convert_kernel<<<6144, 256>>>(x, qw, kw, vw, ow);                         // 2

    // fused Q/K/V projection (profiled: launch index 3)
    hmma_gemm_kernel<<<dim3(24, 4, BB), 256, GEMM_SMEM>>>(nullptr, 0);        // 3

    attn_kernel<<<dim3(2, BB * HH), 256, ATTN_SMEM>>>();                      // 4

    // out projection (AO tiles written directly by attention epilogue)
    hmma_gemm_kernel<<<dim3(8, 4, BB), 256, GEMM_SMEM>>>(out, 3);             // 5
}

// round 14
// speedup vs baseline: 5.6503x; 1.0095x over previous
#include <cuda_runtime.h>
#include <cuda_bf16.h>
#include <cuda_fp16.h>
#include <cstdint>
#include <math.h>

#define BB 32
#define LL 512
#define DD 1024
#define HH 16
#define HDIM 64
#define EE 8

// ---------------- scratch (device globals; no allocation allowed) ----------------
__device__ float g_cos[LL * 32];
__device__ float g_sin[LL * 32];
__device__ int   g_routes[BB];

// X/AO tiles (single fp16): [rt(128)][kc(16)] each 128 rows x 64 cols (16KB), SW128
__device__ __half g_xh[(size_t)16384 * 1024];
// W^T tiles (single fp16): [mode(4)][e(8)][nt(8)][kc(16)] each 128(n) x 64(k), SW128
__device__ __half g_wt[(size_t)4 * 8 * 1024 * 1024];
// q/k/v single fp16: [B*H][512][64], SW128-swizzled 128B rows
__device__ __half g_qh[(size_t)BB * HH * LL * HDIM];
__device__ __half g_kh[(size_t)BB * HH * LL * HDIM];
__device__ __half g_vh[(size_t)BB * HH * LL * HDIM];

// ---------------- PTX helpers ----------------
__device__ __forceinline__ uint32_t smem_u32(const void* p) {
    uint32_t a;
    asm("{ .reg .u64 t; cvta.to.shared.u64 t, %1; cvt.u32.u64 %0, t; }" : "=r"(a) : "l"(p));
    return a;
}

#define MBAR_INIT(a, n) \
    asm volatile("mbarrier.init.shared.b64 [%0], %1;" :: "r"(a), "r"((uint32_t)(n)) : "memory")
#define MBAR_EXPECT_TX(a, b) \
    asm volatile("mbarrier.arrive.expect_tx.shared.b64 _, [%0], %1;" :: "r"(a), "r"((uint32_t)(b)) : "memory")
#define MBAR_ARRIVE(a) \
    asm volatile("mbarrier.arrive.shared.b64 _, [%0];" :: "r"(a) : "memory")

__device__ __forceinline__ void mbar_wait(uint32_t mbar, uint32_t parity) {
    asm volatile(
        "{\n\t.reg .pred P;\n\t"
        "WL_%=:\n\t"
        "mbarrier.try_wait.parity.acquire.cta.shared::cta.b64 P, [%0], %1, 0x989680;\n\t"
        "@P bra.uni WD_%=;\n\t"
        "bra.uni WL_%=;\n\t"
        "WD_%=:\n\t}"
        :: "r"(mbar), "r"(parity) : "memory");
}

__device__ __forceinline__ void bulk_g2s(uint32_t dst, const void* src, uint32_t bytes, uint32_t mbar) {
    asm volatile(
        "cp.async.bulk.shared::cluster.global.mbarrier::complete_tx::bytes [%0], [%1], %2, [%3];"
        :: "r"(dst), "l"(src), "r"(bytes), "r"(mbar) : "memory");
}

__device__ __forceinline__ void ldsm_x4(uint32_t* r, uint32_t a) {
    asm volatile("ldmatrix.sync.aligned.m8n8.x4.shared.b16 {%0,%1,%2,%3}, [%4];"
                 : "=r"(r[0]), "=r"(r[1]), "=r"(r[2]), "=r"(r[3]) : "r"(a));
}
__device__ __forceinline__ void ldsm_x4t(uint32_t* r, uint32_t a) {
    asm volatile("ldmatrix.sync.aligned.m8n8.x4.trans.shared.b16 {%0,%1,%2,%3}, [%4];"
                 : "=r"(r[0]), "=r"(r[1]), "=r"(r[2]), "=r"(r[3]) : "r"(a));
}
__device__ __forceinline__ void mma_f16(float* d, const uint32_t* a, const uint32_t* b) {
    asm volatile(
        "mma.sync.aligned.m16n8k16.row.col.f32.f16.f16.f32 "
        "{%0,%1,%2,%3}, {%4,%5,%6,%7}, {%8,%9}, {%0,%1,%2,%3};"
        : "+f"(d[0]), "+f"(d[1]), "+f"(d[2]), "+f"(d[3])
        : "r"(a[0]), "r"(a[1]), "r"(a[2]), "r"(a[3]), "r"(b[0]), "r"(b[1]));
}
__device__ __forceinline__ float ex2(float x) {
    float r;
    asm("ex2.approx.f32 %0, %1;" : "=f"(r) : "f"(x));
    return r;
}

__device__ __forceinline__ uint32_t pack_h2(__half a, __half b) {
    return (uint32_t)__half_as_ushort(a) | ((uint32_t)__half_as_ushort(b) << 16);
}

// ---------------- router ----------------
__global__ void router_kernel(const float* __restrict__ x,
                              const float* __restrict__ rw,
                              const float* __restrict__ rb,
                              float* __restrict__ probs_out,
                              int write_probs) {
    int b = blockIdx.x;
    __shared__ float mean[DD];
    __shared__ float logits[EE];

    for (int d = threadIdx.x; d < DD; d += blockDim.x) {
        const float* xp = x + (size_t)b * LL * DD + d;
        float s = 0.f;
        #pragma unroll 8
        for (int l = 0; l < LL; l++) s += xp[(size_t)l * DD];
        mean[d] = s * (1.0f / (float)LL);
    }
    __syncthreads();

    int w = threadIdx.x >> 5;
    int lane = threadIdx.x & 31;
    if (w < EE) {
        float s = 0.f;
        for (int d = lane; d < DD; d += 32) s += mean[d] * rw[d * EE + w];
        #pragma unroll
        for (int o = 16; o > 0; o >>= 1) s += __shfl_down_sync(0xffffffffu, s, o);
        if (lane == 0) logits[w] = s + rb[w];
    }
    __syncthreads();

    if (threadIdx.x == 0) {
        float m = logits[0]; int arg = 0;
        #pragma unroll
        for (int e = 1; e < EE; e++) if (logits[e] > m) { m = logits[e]; arg = e; }
        float p[EE], sum = 0.f;
        #pragma unroll
        for (int e = 0; e < EE; e++) { p[e] = expf(logits[e] - m); sum += p[e]; }
        if (write_probs) {
            float inv = 1.0f / sum;
            #pragma unroll
            for (int e = 0; e < EE; e++) probs_out[b * EE + e] = p[e] * inv;
        }
        g_routes[b] = arg;
    }
}

// ---------------- merged convert: X tiles + W^T tiles + rope tables ------------------
__global__ void convert_kernel(const float* __restrict__ x,
                               const float* __restrict__ qw, const float* __restrict__ kw,
                               const float* __restrict__ vw, const float* __restrict__ ow) {
    __shared__ float sm[64][129];
    const int bid = blockIdx.x;
    const int tid = threadIdx.x;

    if (bid >= 6144) {
        // rope tables: 8 blocks x 256 threads x 8 entries = 16384
        int base = (bid - 6144) * 2048 + tid * 8;
        #pragma unroll
        for (int j = 0; j < 8; j++) {
            int idx = base + j;
            int l = idx >> 5;
            int jp = idx & 31;
            float inv = 1.0f / powf(10000.0f, (float)(2 * jp) / 64.0f);
            float ang = (float)l * inv;
            g_cos[idx] = cosf(ang);
            g_sin[idx] = sinf(ang);
        }
        return;
    }

    if (bid < 2048) {
        const int rt = bid >> 4, kc = bid & 15;
        const size_t tb = ((size_t)rt * 16 + kc) * 8192;
        char* dh = (char*)(g_xh + tb);
        #pragma unroll
        for (int i = 0; i < 4; i++) {
            int u = tid + i * 256;
            int r = u >> 3, k8 = u & 7;
            const float* p = x + ((size_t)(rt * 128 + r)) * DD + kc * 64 + k8 * 8;
            float4 a = *(const float4*)p;
            float4 b4 = *(const float4*)(p + 4);
            uint32_t off = (uint32_t)(u * 16);
            off ^= (off >> 3) & 0x70;
            *(uint4*)(dh + off) = make_uint4(
                pack_h2(__float2half_rn(a.x),  __float2half_rn(a.y)),
                pack_h2(__float2half_rn(a.z),  __float2half_rn(a.w)),
                pack_h2(__float2half_rn(b4.x), __float2half_rn(b4.y)),
                pack_h2(__float2half_rn(b4.z), __float2half_rn(b4.w)));
        }
    } else {
        const int idx = bid - 2048;
        const int kc = idx & 15, nt = (idx >> 4) & 7;
        const int e = (idx >> 7) & 7, mode = idx >> 10;
        const float* W = (mode == 0) ? qw : (mode == 1) ? kw : (mode == 2) ? vw : ow;
        const float* src = W + ((size_t)e * DD + kc * 64) * DD + nt * 128;

        #pragma unroll
        for (int i = 0; i < 8; i++) {
            int idx2 = tid + i * 256;
            int kr = idx2 >> 5, nc = (idx2 & 31) << 2;
            float4 v = *(const float4*)(src + (size_t)kr * DD + nc);
            sm[kr][nc] = v.x; sm[kr][nc + 1] = v.y; sm[kr][nc + 2] = v.z; sm[kr][nc + 3] = v.w;
        }
        __syncthreads();

        const size_t tb = (((size_t)(mode * 8 + e) * 8 + nt) * 16 + kc) * 8192;
        char* dw = (char*)(g_wt + tb);
        #pragma unroll
        for (int i = 0; i < 4; i++) {
            int u = tid + i * 256;
            int n = u >> 3, k8 = u & 7;
            __half h[8];
            #pragma unroll
            for (int j = 0; j < 8; j++) h[j] = __float2half_rn(sm[k8 * 8 + j][n]);
            uint32_t off = (uint32_t)(u * 16);
            off ^= (off >> 3) & 0x70;
            *(uint4*)(dw + off) = make_uint4(pack_h2(h[0], h[1]), pack_h2(h[2], h[3]),
                                             pack_h2(h[4], h[5]), pack_h2(h[6], h[7]));
        }
    }
}

// ---------------- HMMA GEMM: CTA 128x128, warp 64x32, 2 CTAs/SM, 3-stage -------------
__global__ void __launch_bounds__(256, 2) hmma_gemm_kernel(float* __restrict__ out, int mode0) {
    extern __shared__ __align__(1024) char smem[];
    const uint32_t sb = smem_u32(smem);
    const int tid = threadIdx.x;
    const int lane = tid & 31, wid = tid >> 5;
    const int wm = wid >> 2, wn = wid & 3;            // 2(m) x 4(n)
    const int nt = blockIdx.x & 7;
    const int mode = mode0 + (blockIdx.x >> 3);
    const int mt = blockIdx.y, b = blockIdx.z;
    const int e = g_routes[b];

    const uint32_t FULLB = sb;                        // 3 full mbarriers
    const uint32_t EMPTB = sb + 24;                   // 3 empty mbarriers (count 8)
    const uint32_t TILES = sb + 1024;                 // 3 stages x 32KB: A | B

    if (tid == 0) {
        #pragma unroll
        for (int s = 0; s < 3; s++) { MBAR_INIT(FULLB + s * 8, 1); MBAR_INIT(EMPTB + s * 8, 8); }
    }
    __syncthreads();

    const __half* Ah = g_xh + ((size_t)(b * 4 + mt) * 16) * 8192;
    const __half* B0 = g_wt + (((size_t)(mode * 8 + e) * 8 + nt) * 16) * 8192;

    auto issue = [&](int c) {
        int s = c % 3;
        uint32_t fb = FULLB + s * 8;
        uint32_t st = TILES + s * 32768;
        MBAR_EXPECT_TX(fb, 32768);
        bulk_g2s(st,         Ah + (size_t)c * 8192, 16384, fb);
        bulk_g2s(st + 16384, B0 + (size_t)c * 8192, 16384, fb);
    };
    if (tid == 0) { issue(0); issue(1); issue(2); }

    float acc[4][4][4];
    #pragma unroll
    for (int mf = 0; mf < 4; mf++)
        #pragma unroll
        for (int nf = 0; nf < 4; nf++)
            #pragma unroll
            for (int r = 0; r < 4; r++) acc[mf][nf][r] = 0.f;

    const uint32_t a_row  = (uint32_t)(wm * 64 + (lane & 15)) * 128;
    const uint32_t a_koff = (uint32_t)(lane >> 4) * 16;
    const uint32_t b_row  = (uint32_t)(wn * 32 + (lane & 7) + ((lane >> 4) << 3)) * 128;
    const uint32_t b_koff = (uint32_t)((lane >> 3) & 1) * 16;

    for (int c = 0; c < 16; c++) {
        const int s = c % 3;
        const uint32_t phase = (uint32_t)((c / 3) & 1);
        mbar_wait(FULLB + s * 8, phase);
        const uint32_t base = TILES + s * 32768;

        #pragma unroll
        for (int ks = 0; ks < 4; ks++) {
            const uint32_t k0b = (uint32_t)ks * 32;
            uint32_t ah[4][4];
            #pragma unroll
            for (int mf = 0; mf < 4; mf++) {
                uint32_t byt = a_row + (uint32_t)mf * 2048 + a_koff + k0b;
                uint32_t sw = byt ^ ((byt >> 3) & 0x70);
                ldsm_x4(ah[mf], base + sw);
            }
            uint32_t bf[2][4];
            #pragma unroll
            for (int p = 0; p < 2; p++) {
                uint32_t byt = b_row + (uint32_t)p * 2048 + b_koff + k0b;
                uint32_t sw = byt ^ ((byt >> 3) & 0x70);
                ldsm_x4(bf[p], base + 16384 + sw);
            }
            if (ks == 3 && lane == 0) MBAR_ARRIVE(EMPTB + s * 8);

            #pragma unroll
            for (int p = 0; p < 2; p++)
                #pragma unroll
                for (int mf = 0; mf < 4; mf++) {
                    mma_f16(acc[mf][2 * p],     ah[mf], &bf[p][0]);
                    mma_f16(acc[mf][2 * p + 1], ah[mf], &bf[p][2]);
                }
        }
        if (tid == 0 && c + 3 < 16) {
            mbar_wait(EMPTB + s * 8, phase);
            issue(c + 3);
        }
    }

    // ---------------- epilogue ----------------
    const int l_base = mt * 128 + wm * 64 + (lane >> 2);
    const int tig = lane & 3;
    const int colbase = nt * 128 + wn * 32;
    const int hglob = colbase >> 6;
    const int d0 = colbase & 63;

    #pragma unroll
    for (int mf = 0; mf < 4; mf++) {
        #pragma unroll
        for (int rh = 0; rh < 2; rh++) {
            const int l = l_base + mf * 16 + 8 * rh;
            #pragma unroll
            for (int nf = 0; nf < 4; nf++) {
                const int d = d0 + 8 * nf + 2 * tig;
                float x0 = acc[mf][nf][2 * rh];
                float x1 = acc[mf][nf][2 * rh + 1];
                if (mode == 3) {
                    float2* dst = (float2*)(out + ((size_t)b * LL + l) * DD + hglob * 64 + d);
                    *dst = make_float2(x0, x1);
                } else {
                    float y0, y1;
                    if (mode == 2) { y0 = x0; y1 = x1; }
                    else {
                        const int p = d >> 1;
                        float cs = g_cos[l * 32 + p];
                        float sn = g_sin[l * 32 + p];
                        y0 = x0 * cs - x1 * sn;
                        y1 = x1 * cs + x0 * sn;
                    }
                    uint32_t off = (uint32_t)((((b * HH + hglob) * LL) + l) * 128 + d * 2);
                    uint32_t sw = off ^ ((off >> 3) & 0x70);
                    char* dst = (mode == 0) ? (char*)g_qh : (mode == 1) ? (char*)g_kh : (char*)g_vh;
                    *(uint32_t*)(dst + sw) = pack_h2(__float2half_rn(y0), __float2half_rn(y1));
                }
            }
        }
    }
}

// ---------------- flash attention: paired q-tiles, mbarrier-only sync ----------------
// grid (2, B*H). CTA bx handles q-tiles {3-bx, bx} sequentially (10 KV units each).
// Scores pre-scaled by 0.125*log2(e); softmax via raw ex2.
__global__ void __launch_bounds__(256, 2) attn_kernel() {
    extern __shared__ __align__(1024) char smem[];
    const uint32_t sb = smem_u32(smem);
    const int tid = threadIdx.x, lane = tid & 31, w = tid >> 5;
    const int bx = blockIdx.x;           // 0 or 1
    const int qtA = 3 - bx, qtB = bx;
    const int bh = blockIdx.y;
    const int b = bh >> 4, h = bh & 15;
    const int g = lane >> 2, tig = lane & 3;
    const float S2 = 0.125f * 1.44269504088896341f;

    const uint32_t QB = sb;
    const uint32_t FB = sb + 8;                    // 2 full mbarriers
    const uint32_t EB = sb + 24;                   // 2 empty mbarriers (count 8)
    const uint32_t QT = sb + 1024;                 // 2 Q tiles x 16KB
    const uint32_t KV = sb + 1024 + 32768;         // 2 stages x (Kh 8KB | Vh 8KB)

    if (tid == 0) {
        MBAR_INIT(QB, 1);
        MBAR_INIT(FB, 1); MBAR_INIT(FB + 8, 1);
        MBAR_INIT(EB, 8); MBAR_INIT(EB + 8, 8);
    }
    __syncthreads();

    const size_t bh_off = (size_t)bh * LL * HDIM;
    const __half* kh = g_kh + bh_off;
    const __half* vh = g_vh + bh_off;

    const int n1 = 2 * qtA + 2, n2 = 2 * qtB + 2;
    const int ntot = n1 + n2;            // always 10

    auto issue = [&](int i) {
        int jt = (i < n1) ? i : (i - n1);
        int s = i & 1;
        uint32_t fb = FB + s * 8;
        uint32_t st = KV + s * 16384;
        MBAR_EXPECT_TX(fb, 16384);
        bulk_g2s(st,        kh + (size_t)jt * 4096, 8192, fb);
        bulk_g2s(st + 8192, vh + (size_t)jt * 4096, 8192, fb);
    };
    if (tid == 0) {
        MBAR_EXPECT_TX(QB, 32768);
        bulk_g2s(QT,         g_qh + bh_off + (size_t)qtA * 8192, 16384, QB);
        bulk_g2s(QT + 16384, g_qh + bh_off + (size_t)qtB * 8192, 16384, QB);
        issue(0);
        issue(1);
    }

    float o[8][4];
    #pragma unroll
    for (int nf = 0; nf < 8; nf++)
        #pragma unroll
        for (int r = 0; r < 4; r++) o[nf][r] = 0.f;
    float m0 = -1e30f, m1 = -1e30f, l0 = 0.f, l1 = 0.f;

    mbar_wait(QB, 0);

    for (int i = 0; i < ntot; i++) {
        const int pass = (i >= n1);
        const int jt = pass ? (i - n1) : i;
        const int qt = pass ? qtB : qtA;
        const uint32_t qtile = QT + (pass ? 16384u : 0u);
        const int rowmin = qt * 128 + w * 16;

        const int s = i & 1;
        mbar_wait(FB + s * 8, (uint32_t)((i >> 1) & 1));
        const uint32_t kb = KV + s * 16384;

        if (jt * 64 <= rowmin + 15) {
            float p[8][4];
            #pragma unroll
            for (int nf = 0; nf < 8; nf++)
                #pragma unroll
                for (int r = 0; r < 4; r++) p[nf][r] = 0.f;

            // S = Q K^T
            #pragma unroll
            for (int ks = 0; ks < 4; ks++) {
                uint32_t qoff = (uint32_t)(w * 16 + (lane & 15)) * 128
                                + (uint32_t)(lane >> 4) * 16 + (uint32_t)ks * 32;
                uint32_t swq = qoff ^ ((qoff >> 3) & 0x70);
                uint32_t ah[4];
                ldsm_x4(ah, qtile + swq);
                #pragma unroll
                for (int nfp = 0; nfp < 4; nfp++) {
                    uint32_t koff = (uint32_t)(nfp * 16 + (lane & 7) + ((lane & 16) >> 1)) * 128
                                    + (uint32_t)ks * 32 + ((lane & 8) << 1);
                    uint32_t swk = koff ^ ((koff >> 3) & 0x70);
                    uint32_t kf[4];
                    ldsm_x4(kf, kb + swk);
                    mma_f16(p[2 * nfp],     ah, &kf[0]);
                    mma_f16(p[2 * nfp + 1], ah, &kf[2]);
                }
            }

            // scale into log2 domain + causal mask
            const bool need_mask = (jt * 64 + 63) > rowmin;
            #pragma unroll
            for (int nf = 0; nf < 8; nf++)
                #pragma unroll
                for (int r = 0; r < 4; r++) {
                    float v = p[nf][r] * S2;
                    if (need_mask) {
                        int qr = rowmin + g + ((r & 2) << 2);
                        int kc = jt * 64 + 8 * nf + 2 * tig + (r & 1);
                        if (kc > qr) v = -1e30f;
                    }
                    p[nf][r] = v;
                }

            float mx0 = m0, mx1 = m1;
            #pragma unroll
            for (int nf = 0; nf < 8; nf++) {
                mx0 = fmaxf(mx0, fmaxf(p[nf][0], p[nf][1]));
                mx1 = fmaxf(mx1, fmaxf(p[nf][2], p[nf][3]));
            }
            mx0 = fmaxf(mx0, __shfl_xor_sync(0xffffffffu, mx0, 1));
            mx0 = fmaxf(mx0, __shfl_xor_sync(0xffffffffu, mx0, 2));
            mx1 = fmaxf(mx1, __shfl_xor_sync(0xffffffffu, mx1, 1));
            mx1 = fmaxf(mx1, __shfl_xor_sync(0xffffffffu, mx1, 2));
            float c0 = ex2(m0 - mx0), c1 = ex2(m1 - mx1);
            m0 = mx0; m1 = mx1;
            float s0 = 0.f, s1 = 0.f;
            #pragma unroll
            for (int nf = 0; nf < 8; nf++) {
                p[nf][0] = ex2(p[nf][0] - mx0); s0 += p[nf][0];
                p[nf][1] = ex2(p[nf][1] - mx0); s0 += p[nf][1];
                p[nf][2] = ex2(p[nf][2] - mx1); s1 += p[nf][2];
                p[nf][3] = ex2(p[nf][3] - mx1); s1 += p[nf][3];
            }
            s0 += __shfl_xor_sync(0xffffffffu, s0, 1);
            s0 += __shfl_xor_sync(0xffffffffu, s0, 2);
            s1 += __shfl_xor_sync(0xffffffffu, s1, 1);
            s1 += __shfl_xor_sync(0xffffffffu, s1, 2);
            l0 = l0 * c0 + s0;
            l1 = l1 * c1 + s1;
            #pragma unroll
            for (int nf = 0; nf < 8; nf++) {
                o[nf][0] *= c0; o[nf][1] *= c0;
                o[nf][2] *= c1; o[nf][3] *= c1;
            }

            // O += P V
            #pragma unroll
            for (int j = 0; j < 4; j++) {
                uint32_t pah[4];
                #pragma unroll
                for (int half = 0; half < 2; half++) {
                    const float* pf = p[2 * j + half];
                    pah[2 * half]     = pack_h2(__float2half_rn(pf[0]), __float2half_rn(pf[1]));
                    pah[2 * half + 1] = pack_h2(__float2half_rn(pf[2]), __float2half_rn(pf[3]));
                }
                #pragma unroll
                for (int nfp = 0; nfp < 4; nfp++) {
                    uint32_t voff = (uint32_t)(16 * j + (lane & 7) + (lane & 8)) * 128
                                    + (uint32_t)nfp * 32 + (lane & 16);
                    uint32_t swv = voff ^ ((voff >> 3) & 0x70);
                    uint32_t vf[4];
                    ldsm_x4t(vf, kb + 8192 + swv);
                    mma_f16(o[2 * nfp],     pah, &vf[0]);
                    mma_f16(o[2 * nfp + 1], pah, &vf[2]);
                }
            }
        }
        // release this stage (all warps, even masked-skip ones)
        if (lane == 0) MBAR_ARRIVE(EB + s * 8);
        if (tid == 0 && i + 2 < ntot) {
            mbar_wait(EB + s * 8, (uint32_t)((i >> 1) & 1));
            issue(i + 2);
        }

        // pass boundary or end: epilogue for this q-tile, then reset state
        if (i == n1 - 1 || i == ntot - 1) {
            const float i0 = 1.f / l0, i1 = 1.f / l1;
            const size_t tb = (((size_t)(b * 4 + qt) * 16) + h) * 16384;   // bytes
            char* dh = (char*)g_xh + tb;
            #pragma unroll
            for (int nf = 0; nf < 8; nf++) {
                #pragma unroll
                for (int rh = 0; rh < 2; rh++) {
                    float y0 = o[nf][2 * rh]     * (rh ? i1 : i0);
                    float y1 = o[nf][2 * rh + 1] * (rh ? i1 : i0);
                    uint32_t off = (uint32_t)((w * 16 + g + 8 * rh) * 128 + (8 * nf + 2 * tig) * 2);
                    uint32_t sw = off ^ ((off >> 3) & 0x70);
                    *(uint32_t*)(dh + sw) = pack_h2(__float2half_rn(y0), __float2half_rn(y1));
                }
            }
            if (i == n1 - 1) {
                #pragma unroll
                for (int nf = 0; nf < 8; nf++)
                    #pragma unroll
                    for (int r = 0; r < 4; r++) o[nf][r] = 0.f;
                m0 = -1e30f; m1 = -1e30f; l0 = 0.f; l1 = 0.f;
            }
        }
    }
}

// ---------------- launch ----------------
extern "C" void kernel_launch(void* const* d_in, const int* in_sizes, int n_in,
                              void* d_out, int out_size) {
    const float* x  = (const float*)d_in[0];
    const float* qw = (const float*)d_in[1];
    const float* kw = (const float*)d_in[2];
    const float* vw = (const float*)d_in[3];
    const float* ow = (const float*)d_in[4];
    const float* rw = (const float*)d_in[5];
    const float* rb = (const float*)d_in[6];
    float* out = (float*)d_out;

    const int GEMM_SMEM = 1024 + 3 * 32768;           // 99328 (x2 CTAs = 198656)
    cudaFuncSetAttribute(hmma_gemm_kernel, cudaFuncAttributeMaxDynamicSharedMemorySize, GEMM_SMEM);
    const int ATTN_SMEM = 1024 + 32768 + 2 * 16384;   // 66560 (x2 CTAs = 133120)
    cudaFuncSetAttribute(attn_kernel, cudaFuncAttributeMaxDynamicSharedMemorySize, ATTN_SMEM);

    int write_probs = (out_size >= BB * LL * DD + BB * EE) ? 1 : 0;
    router_kernel<<<BB, 256>>>(x, rw, rb, out + (size_t)BB * LL * DD, write_probs); // 0

    convert_kernel<<<6152, 256>>>(x, qw, kw, vw, ow);                         // 1 (incl rope)

    hmma_gemm_kernel<<<dim3(24, 4, BB), 256, GEMM_SMEM>>>(nullptr, 0);        // 2

    attn_kernel<<<dim3(2, BB * HH), 256, ATTN_SMEM>>>();                      // 3 <- profiled

    hmma_gemm_kernel<<<dim3(8, 4, BB), 256, GEMM_SMEM>>>(out, 3);             // 4
}